// round 1
// baseline (speedup 1.0000x reference)
#include <cuda_runtime.h>
#include <math.h>

#define B_SZ 12288
#define D_SZ 1024
#define H_SZ 512
#define T_SZ 12
#define K_SZ 3
#define G_SZ 1024   // B_SZ / T_SZ

// ---------------- scratch (device globals; no runtime allocation) ----------------
__device__ float g_xp[(size_t)B_SZ * H_SZ];                      // [B,H] input projection
__device__ float g_h1[(size_t)T_SZ * K_SZ * G_SZ * H_SZ];        // [T,K,g,H]
__device__ float g_h2[(size_t)T_SZ * K_SZ * G_SZ * H_SZ];        // [T,K,g,H]
__device__ float g_rh[(size_t)B_SZ * H_SZ];                      // [B,H] (scattered rows b=g*T+t)
__device__ float g_w[T_SZ * K_SZ];
__device__ float g_conf[T_SZ];
__device__ float g_ent[T_SZ];
__device__ float g_pe[B_SZ];
__device__ float g_nov[B_SZ];
__device__ float g_sp[B_SZ];
__device__ float g_pl[B_SZ];
__device__ float g_extra[T_SZ * H_SZ];                           // per-t routing extra bias

// ---------------- generic NT SGEMM: C = A @ B^T (+bias)(+extra)(relu) ----------------
// A row-major [M, lda] (k contiguous), B row-major [N, ldb] (k contiguous).
// a_scatter/c_scatter: logical row r maps to global row r*scatter + tcur, tcur = z / t_div.
#define BM 128
#define BN 128
#define BK 16

__global__ __launch_bounds__(256)
void sgemm_nt(const float* __restrict__ A, int lda, long a_bstride, int a_scatter, int t_div,
              const float* __restrict__ Bm, int ldb, long b_bstride,
              const float* __restrict__ bias, long bias_bstride,
              const float* __restrict__ extra,
              float* __restrict__ C, int ldc, long c_bstride, int c_scatter,
              int N, int Kdim, int do_relu)
{
    __shared__ float As[BK][BM + 4];
    __shared__ float Bs[BK][BN + 4];

    const int z    = blockIdx.z;
    const int tcur = z / t_div;
    const float* Ab = A  + (long)z * a_bstride;
    const float* Bb = Bm + (long)z * b_bstride;
    float*       Cb = C  + (long)z * c_bstride;

    const int tid  = threadIdx.x;
    const int brow = blockIdx.y * BM;
    const int bcol = blockIdx.x * BN;

    // each thread loads 2 float4 of A-tile and 2 float4 of B-tile per k-step
    const int id0 = tid * 2, id1 = tid * 2 + 1;
    const int r0 = id0 >> 2, c0 = (id0 & 3) * 4;
    const int r1 = id1 >> 2, c1 = (id1 & 3) * 4;

    long arow0 = brow + r0, arow1 = brow + r1;
    if (a_scatter) { arow0 = arow0 * a_scatter + tcur; arow1 = arow1 * a_scatter + tcur; }
    const float* Ap0 = Ab + arow0 * (long)lda;
    const float* Ap1 = Ab + arow1 * (long)lda;
    const float* Bp0 = Bb + (long)(bcol + r0) * ldb;
    const float* Bp1 = Bb + (long)(bcol + r1) * ldb;
    const bool bvec = ((ldb & 3) == 0);

    const int tx = tid & 15, ty = tid >> 4;
    float acc[8][8];
#pragma unroll
    for (int i = 0; i < 8; i++)
#pragma unroll
        for (int j = 0; j < 8; j++) acc[i][j] = 0.f;

    for (int kb = 0; kb < Kdim; kb += BK) {
        float4 av0 = *(const float4*)(Ap0 + kb + c0);
        float4 av1 = *(const float4*)(Ap1 + kb + c1);
        float4 bv0, bv1;
        if (bvec) {
            bv0 = *(const float4*)(Bp0 + kb + c0);
            bv1 = *(const float4*)(Bp1 + kb + c1);
        } else { // rW1 has ldb = H+7 (odd) -> scalar path
            bv0.x = Bp0[kb+c0]; bv0.y = Bp0[kb+c0+1]; bv0.z = Bp0[kb+c0+2]; bv0.w = Bp0[kb+c0+3];
            bv1.x = Bp1[kb+c1]; bv1.y = Bp1[kb+c1+1]; bv1.z = Bp1[kb+c1+2]; bv1.w = Bp1[kb+c1+3];
        }
        As[c0+0][r0] = av0.x; As[c0+1][r0] = av0.y; As[c0+2][r0] = av0.z; As[c0+3][r0] = av0.w;
        As[c1+0][r1] = av1.x; As[c1+1][r1] = av1.y; As[c1+2][r1] = av1.z; As[c1+3][r1] = av1.w;
        Bs[c0+0][r0] = bv0.x; Bs[c0+1][r0] = bv0.y; Bs[c0+2][r0] = bv0.z; Bs[c0+3][r0] = bv0.w;
        Bs[c1+0][r1] = bv1.x; Bs[c1+1][r1] = bv1.y; Bs[c1+2][r1] = bv1.z; Bs[c1+3][r1] = bv1.w;
        __syncthreads();
#pragma unroll
        for (int k = 0; k < BK; k++) {
            float ra[8], rb[8];
#pragma unroll
            for (int i = 0; i < 8; i++) ra[i] = As[k][ty*8 + i];
#pragma unroll
            for (int j = 0; j < 8; j++) rb[j] = Bs[k][tx*8 + j];
#pragma unroll
            for (int i = 0; i < 8; i++)
#pragma unroll
                for (int j = 0; j < 8; j++) acc[i][j] += ra[i] * rb[j];
        }
        __syncthreads();
    }

    const float* biasb = bias ? bias + (long)z * bias_bstride : nullptr;
#pragma unroll
    for (int i = 0; i < 8; i++) {
        long crow = brow + ty*8 + i;
        if (c_scatter) crow = crow * c_scatter + tcur;
        float* cp = Cb + crow * (long)ldc + bcol + tx*8;
#pragma unroll
        for (int j = 0; j < 8; j++) {
            int n = bcol + tx*8 + j;
            float v = acc[i][j];
            if (biasb) v += biasb[n];
            if (extra) v += extra[tcur * N + n];
            if (do_relu) v = fmaxf(v, 0.f);
            cp[j] = v;
        }
    }
}

// ---------------- softmax over op_logits + conflict/entropy ----------------
__global__ void softmax_stats(const float* __restrict__ op_logits)
{
    int t = threadIdx.x;
    if (t < T_SZ) {
        float l0 = op_logits[t*K_SZ+0], l1 = op_logits[t*K_SZ+1], l2 = op_logits[t*K_SZ+2];
        float m = fmaxf(l0, fmaxf(l1, l2));
        float e0 = expf(l0 - m), e1 = expf(l1 - m), e2 = expf(l2 - m);
        float s = e0 + e1 + e2;
        float w0 = e0 / s, w1 = e1 / s, w2 = e2 / s;
        g_w[t*K_SZ+0] = w0; g_w[t*K_SZ+1] = w1; g_w[t*K_SZ+2] = w2;
        float mean = (w0 + w1 + w2) * (1.f / 3.f);
        float d0 = w0 - mean, d1 = w1 - mean, d2 = w2 - mean;
        g_conf[t] = sqrtf((d0*d0 + d1*d1 + d2*d2) * 0.5f);     // ddof=1 -> /(K-1)=2
        float sum = w0 + w1 + w2;
        float inv = 1.f / (sum + 1e-6f);
        float u0 = w0*inv, u1 = w1*inv, u2 = w2*inv;
        float ent = -(u0*logf(fmaxf(u0,1e-6f)) + u1*logf(fmaxf(u1,1e-6f)) + u2*logf(fmaxf(u2,1e-6f)));
        g_ent[t] = ent;
    }
}

// ---------------- weighted op mixture: out_full[g*T+t] = sum_k w[t,k]*h2[t,k,g] ----------------
__global__ void wsum_kernel(float* __restrict__ out_full)
{
    long idx = (long)blockIdx.x * blockDim.x + threadIdx.x;  // over T*G*H
    int i = (int)(idx % H_SZ);
    long r = idx / H_SZ;
    int g = (int)(r % G_SZ);
    int t = (int)(r / G_SZ);
    float s = 0.f;
#pragma unroll
    for (int k = 0; k < K_SZ; k++)
        s += g_w[t*K_SZ + k] * g_h2[(((long)(t*K_SZ + k))*G_SZ + g)*H_SZ + i];
    out_full[((long)(g*T_SZ + t))*H_SZ + i] = s;
}

// ---------------- per-row stats (one warp per row b) ----------------
__device__ __forceinline__ float warp_sum(float v) {
#pragma unroll
    for (int o = 16; o > 0; o >>= 1) v += __shfl_down_sync(0xffffffffu, v, o);
    return v;
}

__global__ void row_stats(const float* __restrict__ out_full, const float* __restrict__ noise)
{
    int warp = (int)((blockIdx.x * (long)blockDim.x + threadIdx.x) >> 5);
    int lane = threadIdx.x & 31;
    if (warp >= B_SZ) return;
    const float* o  = out_full + (long)warp * H_SZ;
    const float* xr = g_xp     + (long)warp * H_SZ;
    const float* nr = noise    + (long)warp * H_SZ;
    float pe = 0.f, nov = 0.f, sp = 0.f, pl = 0.f;
    for (int i = lane; i < H_SZ; i += 32) {
        float ov = o[i], xv = xr[i], nv = nr[i] * 0.01f;
        float d = ov - xv;
        pe += d * d; nov += xv * xv; sp += fabsf(ov); pl += nv * nv;
    }
    pe = warp_sum(pe); nov = warp_sum(nov); sp = warp_sum(sp); pl = warp_sum(pl);
    if (lane == 0) {
        const float inv = 1.f / (float)H_SZ;
        g_pe[warp] = pe * inv; g_nov[warp] = nov * inv;
        g_sp[warp] = sp * inv; g_pl[warp]  = pl * inv;
    }
}

// ---------------- finalize: signals, decision, routing extra bias (one block per t) ----------------
__device__ __forceinline__ float block_sum(float v, float* red, int tid) {
    red[tid] = v; __syncthreads();
    for (int s = 128; s > 0; s >>= 1) { if (tid < s) red[tid] += red[tid + s]; __syncthreads(); }
    float r = red[0]; __syncthreads();
    return r;
}

__global__ void finalize_kernel(const float* __restrict__ id_emb, const float* __restrict__ rW1,
                                const float* __restrict__ gW1, const float* __restrict__ gb1,
                                const float* __restrict__ gW2, const float* __restrict__ gb2,
                                float* __restrict__ decision)
{
    __shared__ float red[256];
    __shared__ float sig[7];
    __shared__ float gch[H_SZ];
    const int t = blockIdx.x, tid = threadIdx.x;

    float pe = 0.f, pe2 = 0.f, nov = 0.f, sp = 0.f, pl = 0.f;
    for (int g = tid; g < G_SZ; g += 256) {
        int b = g * T_SZ + t;
        float p = g_pe[b];
        pe += p; pe2 += p * p; nov += g_nov[b]; sp += g_sp[b]; pl += g_pl[b];
    }
    float S_pe  = block_sum(pe,  red, tid);
    float S_pe2 = block_sum(pe2, red, tid);
    float S_nov = block_sum(nov, red, tid);
    float S_sp  = block_sum(sp,  red, tid);
    float S_pl  = block_sum(pl,  red, tid);

    if (tid == 0) {
        const float invg = 1.f / (float)G_SZ;
        float pe_m = S_pe * invg, pe2_m = S_pe2 * invg;
        float c = 0.01f * pe_m;
        sig[0] = S_pl * invg;                      // plasticity
        sig[1] = S_nov * invg;                     // novelty
        sig[2] = pe_m;                             // pred_err
        sig[3] = g_ent[t];                         // entropy
        sig[4] = S_sp * invg;                      // sparsity
        sig[5] = -pe_m;                            // reward_delta
        sig[6] = pe2_m - 2.f * c * pe_m + c * c;   // reward_var
    }
    __syncthreads();

    // growth controller MLP: 7 -> H (relu)
    for (int i = tid; i < H_SZ; i += 256) {
        float a = gb1[t * H_SZ + i];
#pragma unroll
        for (int j = 0; j < 7; j++) a += gW1[((long)(t * H_SZ + i)) * 7 + j] * sig[j];
        gch[i] = fmaxf(a, 0.f);
    }
    __syncthreads();

    // H -> 2
    for (int o = 0; o < 2; o++) {
        float d = 0.f;
        for (int i = tid; i < H_SZ; i += 256) d += gW2[((long)(t * 2 + o)) * H_SZ + i] * gch[i];
        float S = block_sum(d, red, tid);
        if (tid == 0) decision[t * 2 + o] = S + gb2[t * 2 + o];
    }

    // routing extra bias c_extra[t, i] = sum_j ext[j] * rW1[i, H + j]
    __shared__ float ext[7];
    if (tid == 0) {
        ext[0] = id_emb[t*4+0]; ext[1] = id_emb[t*4+1];
        ext[2] = id_emb[t*4+2]; ext[3] = id_emb[t*4+3];
        ext[4] = sig[1];        // novelty mean
        ext[5] = g_conf[t];     // conflict
        ext[6] = sig[2];        // last plasticity == pred_err mean
    }
    __syncthreads();
    for (int i = tid; i < H_SZ; i += 256) {
        float a = 0.f;
#pragma unroll
        for (int j = 0; j < 7; j++) a += ext[j] * rW1[(long)i * (H_SZ + 7) + H_SZ + j];
        g_extra[t * H_SZ + i] = a;
    }
}

// ---------------- logits: rh[b] @ rW2^T + rb2 (one block per row, warp per output) ----------------
__global__ void logits_kernel(const float* __restrict__ rW2, const float* __restrict__ rb2,
                              float* __restrict__ logits)
{
    const int b = blockIdx.x;
    const int o = threadIdx.x >> 5, lane = threadIdx.x & 31;
    const float* r = g_rh + (long)b * H_SZ;
    const float* wrow = rW2 + (long)o * H_SZ;
    float acc = 0.f;
    for (int i = lane; i < H_SZ; i += 32) acc += r[i] * wrow[i];
    acc = warp_sum(acc);
    if (lane == 0) logits[(long)b * (T_SZ + 1) + o] = acc + rb2[o];
}

// ---------------- launch ----------------
extern "C" void kernel_launch(void* const* d_in, const int* in_sizes, int n_in,
                              void* d_out, int out_size)
{
    const float* x         = (const float*)d_in[0];
    const float* Wp        = (const float*)d_in[1];
    const float* bp        = (const float*)d_in[2];
    const float* opW1      = (const float*)d_in[3];
    const float* opb1      = (const float*)d_in[4];
    const float* opW2      = (const float*)d_in[5];
    const float* opb2      = (const float*)d_in[6];
    const float* op_logits = (const float*)d_in[7];
    const float* id_emb    = (const float*)d_in[8];
    const float* rW1       = (const float*)d_in[9];
    const float* rb1       = (const float*)d_in[10];
    const float* rW2       = (const float*)d_in[11];
    const float* rb2       = (const float*)d_in[12];
    const float* gW1       = (const float*)d_in[13];
    const float* gb1       = (const float*)d_in[14];
    const float* gW2       = (const float*)d_in[15];
    const float* gb2       = (const float*)d_in[16];
    const float* phW       = (const float*)d_in[17];
    const float* phb       = (const float*)d_in[18];
    const float* noise     = (const float*)d_in[19];

    float* out_full = (float*)d_out;
    float* logits   = out_full + (size_t)B_SZ * H_SZ;
    float* pred     = logits   + (size_t)B_SZ * (T_SZ + 1);
    float* decision = pred     + (size_t)B_SZ * D_SZ;

    float *xp, *h1, *h2, *rh, *extra;
    cudaGetSymbolAddress((void**)&xp,    g_xp);
    cudaGetSymbolAddress((void**)&h1,    g_h1);
    cudaGetSymbolAddress((void**)&h2,    g_h2);
    cudaGetSymbolAddress((void**)&rh,    g_rh);
    cudaGetSymbolAddress((void**)&extra, g_extra);

    // 1) xp = x @ Wp^T + bp                        [12288,512]
    sgemm_nt<<<dim3(H_SZ/BN, B_SZ/BM, 1), 256>>>(
        x, D_SZ, 0, 0, 1,  Wp, D_SZ, 0,  bp, 0,  nullptr,
        xp, H_SZ, 0, 0,  H_SZ, D_SZ, 0);

    // 2) softmax / conflict / entropy
    softmax_stats<<<1, 32>>>(op_logits);

    // 3) h1[t,k] = relu(xg[t] @ opW1[t,k]^T + opb1[t,k])   (A rows scattered g*T+t)
    sgemm_nt<<<dim3(H_SZ/BN, G_SZ/BM, T_SZ*K_SZ), 256>>>(
        xp, H_SZ, 0, T_SZ, K_SZ,
        opW1, H_SZ, (long)H_SZ*H_SZ,  opb1, H_SZ,  nullptr,
        h1, H_SZ, (long)G_SZ*H_SZ, 0,  H_SZ, H_SZ, 1);

    // 4) h2[t,k] = relu(h1[t,k] @ opW2[t,k]^T + opb2[t,k])
    sgemm_nt<<<dim3(H_SZ/BN, G_SZ/BM, T_SZ*K_SZ), 256>>>(
        h1, H_SZ, (long)G_SZ*H_SZ, 0, 1,
        opW2, H_SZ, (long)H_SZ*H_SZ,  opb2, H_SZ,  nullptr,
        h2, H_SZ, (long)G_SZ*H_SZ, 0,  H_SZ, H_SZ, 1);

    // 5) out_full (scattered) = sum_k w[t,k] * h2[t,k]
    wsum_kernel<<<(T_SZ*G_SZ*H_SZ)/256, 256>>>(out_full);

    // 6) per-row stats
    row_stats<<<(B_SZ*32)/256, 256>>>(out_full, noise);

    // 7) signals, decision, routing extra bias
    finalize_kernel<<<T_SZ, 256>>>(id_emb, rW1, gW1, gb1, gW2, gb2, decision);

    // 8) rh = relu(out @ rW1[:, :H]^T + c_extra[t] + rb1)   (A & C rows scattered)
    sgemm_nt<<<dim3(H_SZ/BN, G_SZ/BM, T_SZ), 256>>>(
        out_full, H_SZ, 0, T_SZ, 1,
        rW1, H_SZ + 7, 0,  rb1, 0,  extra,
        rh, H_SZ, 0, T_SZ,  H_SZ, H_SZ, 1);

    // 9) logits = rh @ rW2^T + rb2
    logits_kernel<<<B_SZ, (T_SZ + 1) * 32>>>(rW2, rb2, logits);

    // 10) pred = out_full @ phW^T + phb            [12288,1024]
    sgemm_nt<<<dim3(D_SZ/BN, B_SZ/BM, 1), 256>>>(
        out_full, H_SZ, 0, 0, 1,  phW, H_SZ, 0,  phb, 0,  nullptr,
        pred, D_SZ, 0, 0,  D_SZ, H_SZ, 0);
}

// round 7
// speedup vs baseline: 1.0948x; 1.0948x over previous
#include <cuda_runtime.h>
#include <math.h>

#define B_SZ 12288
#define D_SZ 1024
#define H_SZ 512
#define T_SZ 12
#define K_SZ 3
#define G_SZ 1024   // B_SZ / T_SZ

// ---------------- scratch (device globals; no runtime allocation) ----------------
__device__ float g_xp[(size_t)B_SZ * H_SZ];                      // [B,H] input projection
__device__ float g_h1[(size_t)T_SZ * K_SZ * G_SZ * H_SZ];        // [T,K,g,H]
__device__ float g_h2[(size_t)T_SZ * K_SZ * G_SZ * H_SZ];        // [T,K,g,H]
__device__ float g_rh[(size_t)B_SZ * H_SZ];                      // [B,H] (scattered rows b=g*T+t)
__device__ float g_w[T_SZ * K_SZ];
__device__ float g_conf[T_SZ];
__device__ float g_ent[T_SZ];
__device__ float g_pe[B_SZ];
__device__ float g_nov[B_SZ];
__device__ float g_sp[B_SZ];
__device__ float g_pl[B_SZ];
__device__ float g_extra[T_SZ * H_SZ];                           // per-t routing extra bias

// ---------------- generic NT SGEMM: C = A @ B^T (+bias)(+extra)(relu) ----------------
// A row-major [M, lda] (k contiguous), B row-major [N, ldb] (k contiguous).
// a_scatter/c_scatter: logical row r maps to global row r*scatter + tcur, tcur = z / t_div.
// Double-buffered smem pipeline: prefetch next K-tile into regs while computing current.
#define BM 128
#define BN 128
#define BK 16

// NOTE: macro parameters deliberately use trailing-underscore names (BUF_, KB_)
// so they can never token-collide with struct members like float4::w.
#define LOAD_TILE(KB_)                                                        \
    av0 = *(const float4*)(Ap0 + (KB_) + c0);                                 \
    av1 = *(const float4*)(Ap1 + (KB_) + c1);                                 \
    if (bvec) {                                                               \
        bv0 = *(const float4*)(Bp0 + (KB_) + c0);                             \
        bv1 = *(const float4*)(Bp1 + (KB_) + c1);                             \
    } else {                                                                  \
        bv0.x = Bp0[(KB_)+c0]; bv0.y = Bp0[(KB_)+c0+1];                       \
        bv0.z = Bp0[(KB_)+c0+2]; bv0.w = Bp0[(KB_)+c0+3];                     \
        bv1.x = Bp1[(KB_)+c1]; bv1.y = Bp1[(KB_)+c1+1];                       \
        bv1.z = Bp1[(KB_)+c1+2]; bv1.w = Bp1[(KB_)+c1+3];                     \
    }

#define STORE_TILE(BUF_)                                                      \
    As[BUF_][c0+0][r0]=av0.x; As[BUF_][c0+1][r0]=av0.y;                       \
    As[BUF_][c0+2][r0]=av0.z; As[BUF_][c0+3][r0]=av0.w;                       \
    As[BUF_][c1+0][r1]=av1.x; As[BUF_][c1+1][r1]=av1.y;                       \
    As[BUF_][c1+2][r1]=av1.z; As[BUF_][c1+3][r1]=av1.w;                       \
    Bs[BUF_][c0+0][r0]=bv0.x; Bs[BUF_][c0+1][r0]=bv0.y;                       \
    Bs[BUF_][c0+2][r0]=bv0.z; Bs[BUF_][c0+3][r0]=bv0.w;                       \
    Bs[BUF_][c1+0][r1]=bv1.x; Bs[BUF_][c1+1][r1]=bv1.y;                       \
    Bs[BUF_][c1+2][r1]=bv1.z; Bs[BUF_][c1+3][r1]=bv1.w;

#define COMPUTE_TILE(BUF_)                                                    \
    _Pragma("unroll")                                                         \
    for (int k = 0; k < BK; k++) {                                            \
        float4 a0 = *(const float4*)&As[BUF_][k][ty*8];                       \
        float4 a1 = *(const float4*)&As[BUF_][k][ty*8+4];                     \
        float4 b0 = *(const float4*)&Bs[BUF_][k][tx*8];                       \
        float4 b1 = *(const float4*)&Bs[BUF_][k][tx*8+4];                     \
        float ra[8] = {a0.x,a0.y,a0.z,a0.w,a1.x,a1.y,a1.z,a1.w};              \
        float rb[8] = {b0.x,b0.y,b0.z,b0.w,b1.x,b1.y,b1.z,b1.w};              \
        _Pragma("unroll")                                                     \
        for (int i = 0; i < 8; i++)                                           \
            _Pragma("unroll")                                                 \
            for (int j = 0; j < 8; j++) acc[i][j] += ra[i] * rb[j];           \
    }

__global__ __launch_bounds__(256, 2)
void sgemm_nt(const float* __restrict__ A, int lda, long a_bstride, int a_scatter, int t_div,
              const float* __restrict__ Bm, int ldb, long b_bstride,
              const float* __restrict__ bias, long bias_bstride,
              const float* __restrict__ extra,
              float* __restrict__ C, int ldc, long c_bstride, int c_scatter,
              int N, int Kdim, int do_relu)
{
    __shared__ float As[2][BK][BM + 4];
    __shared__ float Bs[2][BK][BN + 4];

    const int z    = blockIdx.z;
    const int tcur = z / t_div;
    const float* Ab = A  + (long)z * a_bstride;
    const float* Bb = Bm + (long)z * b_bstride;
    float*       Cb = C  + (long)z * c_bstride;

    const int tid  = threadIdx.x;
    const int brow = blockIdx.y * BM;
    const int bcol = blockIdx.x * BN;

    // each thread loads 2 float4 of A-tile and 2 float4 of B-tile per k-step
    const int id0 = tid * 2, id1 = tid * 2 + 1;
    const int r0 = id0 >> 2, c0 = (id0 & 3) * 4;
    const int r1 = id1 >> 2, c1 = (id1 & 3) * 4;

    long arow0 = brow + r0, arow1 = brow + r1;
    if (a_scatter) { arow0 = arow0 * a_scatter + tcur; arow1 = arow1 * a_scatter + tcur; }
    const float* Ap0 = Ab + arow0 * (long)lda;
    const float* Ap1 = Ab + arow1 * (long)lda;
    const float* Bp0 = Bb + (long)(bcol + r0) * ldb;
    const float* Bp1 = Bb + (long)(bcol + r1) * ldb;
    const bool bvec = ((ldb & 3) == 0);

    const int tx = tid & 15, ty = tid >> 4;
    float acc[8][8];
#pragma unroll
    for (int i = 0; i < 8; i++)
#pragma unroll
        for (int j = 0; j < 8; j++) acc[i][j] = 0.f;

    float4 av0, av1, bv0, bv1;

    // prologue: tile 0 into buffer 0
    LOAD_TILE(0);
    STORE_TILE(0);
    __syncthreads();

    int buf = 0;
    for (int kb = BK; kb < Kdim; kb += BK) {
        LOAD_TILE(kb);            // global prefetch (latency hides under compute)
        COMPUTE_TILE(buf);        // consume current buffer
        STORE_TILE(buf ^ 1);      // stage next buffer
        __syncthreads();
        buf ^= 1;
    }
    COMPUTE_TILE(buf);            // epilogue tile

    const float* biasb = bias ? bias + (long)z * bias_bstride : nullptr;
#pragma unroll
    for (int i = 0; i < 8; i++) {
        long crow = brow + ty*8 + i;
        if (c_scatter) crow = crow * c_scatter + tcur;
        float* cp = Cb + crow * (long)ldc + bcol + tx*8;
#pragma unroll
        for (int j = 0; j < 8; j++) {
            int n = bcol + tx*8 + j;
            float v = acc[i][j];
            if (biasb) v += biasb[n];
            if (extra) v += extra[tcur * N + n];
            if (do_relu) v = fmaxf(v, 0.f);
            cp[j] = v;
        }
    }
}

// ---------------- softmax over op_logits + conflict/entropy ----------------
__global__ void softmax_stats(const float* __restrict__ op_logits)
{
    int t = threadIdx.x;
    if (t < T_SZ) {
        float l0 = op_logits[t*K_SZ+0], l1 = op_logits[t*K_SZ+1], l2 = op_logits[t*K_SZ+2];
        float m = fmaxf(l0, fmaxf(l1, l2));
        float e0 = expf(l0 - m), e1 = expf(l1 - m), e2 = expf(l2 - m);
        float s = e0 + e1 + e2;
        float w0 = e0 / s, w1 = e1 / s, w2 = e2 / s;
        g_w[t*K_SZ+0] = w0; g_w[t*K_SZ+1] = w1; g_w[t*K_SZ+2] = w2;
        float mean = (w0 + w1 + w2) * (1.f / 3.f);
        float d0 = w0 - mean, d1 = w1 - mean, d2 = w2 - mean;
        g_conf[t] = sqrtf((d0*d0 + d1*d1 + d2*d2) * 0.5f);     // ddof=1 -> /(K-1)=2
        float sum = w0 + w1 + w2;
        float inv = 1.f / (sum + 1e-6f);
        float u0 = w0*inv, u1 = w1*inv, u2 = w2*inv;
        float ent = -(u0*logf(fmaxf(u0,1e-6f)) + u1*logf(fmaxf(u1,1e-6f)) + u2*logf(fmaxf(u2,1e-6f)));
        g_ent[t] = ent;
    }
}

// ---------------- weighted op mixture: out_full[g*T+t] = sum_k w[t,k]*h2[t,k,g] ----------------
__global__ void wsum_kernel(float* __restrict__ out_full)
{
    long idx4 = (long)blockIdx.x * blockDim.x + threadIdx.x;  // over T*G*H/4
    int i4 = (int)(idx4 % (H_SZ / 4));
    long r = idx4 / (H_SZ / 4);
    int g = (int)(r % G_SZ);
    int t = (int)(r / G_SZ);
    float w0 = g_w[t*K_SZ+0], w1 = g_w[t*K_SZ+1], w2 = g_w[t*K_SZ+2];
    const float4* p0 = (const float4*)&g_h2[(((long)(t*K_SZ+0))*G_SZ + g)*H_SZ];
    const float4* p1 = (const float4*)&g_h2[(((long)(t*K_SZ+1))*G_SZ + g)*H_SZ];
    const float4* p2 = (const float4*)&g_h2[(((long)(t*K_SZ+2))*G_SZ + g)*H_SZ];
    float4 v0 = p0[i4], v1 = p1[i4], v2 = p2[i4];
    float4 o;
    o.x = w0*v0.x + w1*v1.x + w2*v2.x;
    o.y = w0*v0.y + w1*v1.y + w2*v2.y;
    o.z = w0*v0.z + w1*v1.z + w2*v2.z;
    o.w = w0*v0.w + w1*v1.w + w2*v2.w;
    ((float4*)&out_full[((long)(g*T_SZ + t))*H_SZ])[i4] = o;
}

// ---------------- per-row stats (one warp per row b) ----------------
__device__ __forceinline__ float warp_sum(float v) {
#pragma unroll
    for (int o = 16; o > 0; o >>= 1) v += __shfl_down_sync(0xffffffffu, v, o);
    return v;
}

__global__ void row_stats(const float* __restrict__ out_full, const float* __restrict__ noise)
{
    int warp = (int)((blockIdx.x * (long)blockDim.x + threadIdx.x) >> 5);
    int lane = threadIdx.x & 31;
    if (warp >= B_SZ) return;
    const float4* o  = (const float4*)(out_full + (long)warp * H_SZ);
    const float4* xr = (const float4*)(g_xp     + (long)warp * H_SZ);
    const float4* nr = (const float4*)(noise    + (long)warp * H_SZ);
    float pe = 0.f, nov = 0.f, sp = 0.f, pl = 0.f;
#pragma unroll
    for (int i = lane; i < H_SZ/4; i += 32) {
        float4 ov = o[i], xv = xr[i], nvr = nr[i];
        float d;
        d = ov.x - xv.x; pe += d*d; nov += xv.x*xv.x; sp += fabsf(ov.x);
        d = ov.y - xv.y; pe += d*d; nov += xv.y*xv.y; sp += fabsf(ov.y);
        d = ov.z - xv.z; pe += d*d; nov += xv.z*xv.z; sp += fabsf(ov.z);
        d = ov.w - xv.w; pe += d*d; nov += xv.w*xv.w; sp += fabsf(ov.w);
        float nx = nvr.x*0.01f, ny = nvr.y*0.01f, nz = nvr.z*0.01f, nw = nvr.w*0.01f;
        pl += nx*nx + ny*ny + nz*nz + nw*nw;
    }
    pe = warp_sum(pe); nov = warp_sum(nov); sp = warp_sum(sp); pl = warp_sum(pl);
    if (lane == 0) {
        const float inv = 1.f / (float)H_SZ;
        g_pe[warp] = pe * inv; g_nov[warp] = nov * inv;
        g_sp[warp] = sp * inv; g_pl[warp]  = pl * inv;
    }
}

// ---------------- finalize: signals, decision, routing extra bias (one block per t) ----------------
__device__ __forceinline__ float block_sum(float v, float* red, int tid) {
    red[tid] = v; __syncthreads();
    for (int s = 128; s > 0; s >>= 1) { if (tid < s) red[tid] += red[tid + s]; __syncthreads(); }
    float r = red[0]; __syncthreads();
    return r;
}

__global__ void finalize_kernel(const float* __restrict__ id_emb, const float* __restrict__ rW1,
                                const float* __restrict__ gW1, const float* __restrict__ gb1,
                                const float* __restrict__ gW2, const float* __restrict__ gb2,
                                float* __restrict__ decision)
{
    __shared__ float red[256];
    __shared__ float sig[7];
    __shared__ float gch[H_SZ];
    const int t = blockIdx.x, tid = threadIdx.x;

    float pe = 0.f, pe2 = 0.f, nov = 0.f, sp = 0.f, pl = 0.f;
    for (int g = tid; g < G_SZ; g += 256) {
        int b = g * T_SZ + t;
        float p = g_pe[b];
        pe += p; pe2 += p * p; nov += g_nov[b]; sp += g_sp[b]; pl += g_pl[b];
    }
    float S_pe  = block_sum(pe,  red, tid);
    float S_pe2 = block_sum(pe2, red, tid);
    float S_nov = block_sum(nov, red, tid);
    float S_sp  = block_sum(sp,  red, tid);
    float S_pl  = block_sum(pl,  red, tid);

    if (tid == 0) {
        const float invg = 1.f / (float)G_SZ;
        float pe_m = S_pe * invg, pe2_m = S_pe2 * invg;
        float c = 0.01f * pe_m;
        sig[0] = S_pl * invg;                      // plasticity
        sig[1] = S_nov * invg;                     // novelty
        sig[2] = pe_m;                             // pred_err
        sig[3] = g_ent[t];                         // entropy
        sig[4] = S_sp * invg;                      // sparsity
        sig[5] = -pe_m;                            // reward_delta
        sig[6] = pe2_m - 2.f * c * pe_m + c * c;   // reward_var
    }
    __syncthreads();

    // growth controller MLP: 7 -> H (relu)
    for (int i = tid; i < H_SZ; i += 256) {
        float a = gb1[t * H_SZ + i];
#pragma unroll
        for (int j = 0; j < 7; j++) a += gW1[((long)(t * H_SZ + i)) * 7 + j] * sig[j];
        gch[i] = fmaxf(a, 0.f);
    }
    __syncthreads();

    // H -> 2
    for (int o = 0; o < 2; o++) {
        float d = 0.f;
        for (int i = tid; i < H_SZ; i += 256) d += gW2[((long)(t * 2 + o)) * H_SZ + i] * gch[i];
        float S = block_sum(d, red, tid);
        if (tid == 0) decision[t * 2 + o] = S + gb2[t * 2 + o];
    }

    // routing extra bias c_extra[t, i] = sum_j ext[j] * rW1[i, H + j]
    __shared__ float ext[7];
    if (tid == 0) {
        ext[0] = id_emb[t*4+0]; ext[1] = id_emb[t*4+1];
        ext[2] = id_emb[t*4+2]; ext[3] = id_emb[t*4+3];
        ext[4] = sig[1];        // novelty mean
        ext[5] = g_conf[t];     // conflict
        ext[6] = sig[2];        // last plasticity == pred_err mean
    }
    __syncthreads();
    for (int i = tid; i < H_SZ; i += 256) {
        float a = 0.f;
#pragma unroll
        for (int j = 0; j < 7; j++) a += ext[j] * rW1[(long)i * (H_SZ + 7) + H_SZ + j];
        g_extra[t * H_SZ + i] = a;
    }
}

// ---------------- logits: rh[b] @ rW2^T + rb2 (one block per row, warp per output) ----------------
__global__ void logits_kernel(const float* __restrict__ rW2, const float* __restrict__ rb2,
                              float* __restrict__ logits)
{
    const int b = blockIdx.x;
    const int o = threadIdx.x >> 5, lane = threadIdx.x & 31;
    const float4* r = (const float4*)(g_rh + (long)b * H_SZ);
    const float4* wrow = (const float4*)(rW2 + (long)o * H_SZ);
    float acc = 0.f;
    for (int i = lane; i < H_SZ/4; i += 32) {
        float4 rv = r[i], wv = wrow[i];
        acc += rv.x*wv.x + rv.y*wv.y + rv.z*wv.z + rv.w*wv.w;
    }
    acc = warp_sum(acc);
    if (lane == 0) logits[(long)b * (T_SZ + 1) + o] = acc + rb2[o];
}

// ---------------- launch ----------------
extern "C" void kernel_launch(void* const* d_in, const int* in_sizes, int n_in,
                              void* d_out, int out_size)
{
    const float* x         = (const float*)d_in[0];
    const float* Wp        = (const float*)d_in[1];
    const float* bp        = (const float*)d_in[2];
    const float* opW1      = (const float*)d_in[3];
    const float* opb1      = (const float*)d_in[4];
    const float* opW2      = (const float*)d_in[5];
    const float* opb2      = (const float*)d_in[6];
    const float* op_logits = (const float*)d_in[7];
    const float* id_emb    = (const float*)d_in[8];
    const float* rW1       = (const float*)d_in[9];
    const float* rb1       = (const float*)d_in[10];
    const float* rW2       = (const float*)d_in[11];
    const float* rb2       = (const float*)d_in[12];
    const float* gW1       = (const float*)d_in[13];
    const float* gb1       = (const float*)d_in[14];
    const float* gW2       = (const float*)d_in[15];
    const float* gb2       = (const float*)d_in[16];
    const float* phW       = (const float*)d_in[17];
    const float* phb       = (const float*)d_in[18];
    const float* noise     = (const float*)d_in[19];

    float* out_full = (float*)d_out;
    float* logits   = out_full + (size_t)B_SZ * H_SZ;
    float* pred     = logits   + (size_t)B_SZ * (T_SZ + 1);
    float* decision = pred     + (size_t)B_SZ * D_SZ;

    float *xp, *h1, *h2, *rh, *extra;
    cudaGetSymbolAddress((void**)&xp,    g_xp);
    cudaGetSymbolAddress((void**)&h1,    g_h1);
    cudaGetSymbolAddress((void**)&h2,    g_h2);
    cudaGetSymbolAddress((void**)&rh,    g_rh);
    cudaGetSymbolAddress((void**)&extra, g_extra);

    // 1) xp = x @ Wp^T + bp                        [12288,512]
    sgemm_nt<<<dim3(H_SZ/BN, B_SZ/BM, 1), 256>>>(
        x, D_SZ, 0, 0, 1,  Wp, D_SZ, 0,  bp, 0,  nullptr,
        xp, H_SZ, 0, 0,  H_SZ, D_SZ, 0);

    // 2) softmax / conflict / entropy
    softmax_stats<<<1, 32>>>(op_logits);

    // 3) h1[t,k] = relu(xg[t] @ opW1[t,k]^T + opb1[t,k])   (A rows scattered g*T+t)
    sgemm_nt<<<dim3(H_SZ/BN, G_SZ/BM, T_SZ*K_SZ), 256>>>(
        xp, H_SZ, 0, T_SZ, K_SZ,
        opW1, H_SZ, (long)H_SZ*H_SZ,  opb1, H_SZ,  nullptr,
        h1, H_SZ, (long)G_SZ*H_SZ, 0,  H_SZ, H_SZ, 1);

    // 4) h2[t,k] = relu(h1[t,k] @ opW2[t,k]^T + opb2[t,k])
    sgemm_nt<<<dim3(H_SZ/BN, G_SZ/BM, T_SZ*K_SZ), 256>>>(
        h1, H_SZ, (long)G_SZ*H_SZ, 0, 1,
        opW2, H_SZ, (long)H_SZ*H_SZ,  opb2, H_SZ,  nullptr,
        h2, H_SZ, (long)G_SZ*H_SZ, 0,  H_SZ, H_SZ, 1);

    // 5) out_full (scattered) = sum_k w[t,k] * h2[t,k]
    wsum_kernel<<<(T_SZ*G_SZ*H_SZ/4)/256, 256>>>(out_full);

    // 6) per-row stats
    row_stats<<<(B_SZ*32)/256, 256>>>(out_full, noise);

    // 7) signals, decision, routing extra bias
    finalize_kernel<<<T_SZ, 256>>>(id_emb, rW1, gW1, gb1, gW2, gb2, decision);

    // 8) rh = relu(out @ rW1[:, :H]^T + c_extra[t] + rb1)   (A & C rows scattered)
    sgemm_nt<<<dim3(H_SZ/BN, G_SZ/BM, T_SZ), 256>>>(
        out_full, H_SZ, 0, T_SZ, 1,
        rW1, H_SZ + 7, 0,  rb1, 0,  extra,
        rh, H_SZ, 0, T_SZ,  H_SZ, H_SZ, 1);

    // 9) logits = rh @ rW2^T + rb2
    logits_kernel<<<B_SZ, (T_SZ + 1) * 32>>>(rW2, rb2, logits);

    // 10) pred = out_full @ phW^T + phb            [12288,1024]
    sgemm_nt<<<dim3(D_SZ/BN, B_SZ/BM, 1), 256>>>(
        out_full, H_SZ, 0, 0, 1,  phW, H_SZ, 0,  phb, 0,  nullptr,
        pred, D_SZ, 0, 0,  D_SZ, H_SZ, 0);
}

// round 9
// speedup vs baseline: 2.4310x; 2.2204x over previous
#include <cuda_runtime.h>
#include <cuda_bf16.h>
#include <stdint.h>
#include <math.h>

typedef __nv_bfloat16 bf16;

#define B_SZ 12288
#define D_SZ 1024
#define H_SZ 512
#define T_SZ 12
#define K_SZ 3
#define G_SZ 1024   // B_SZ / T_SZ

// ---------------- fp32 scratch ----------------
__device__ float g_xp[(size_t)B_SZ * H_SZ];                      // [B,H] input projection (fp32, for stats)
__device__ float g_h2[(size_t)T_SZ * K_SZ * G_SZ * H_SZ];        // [T,K,g,H]
__device__ float g_rh[(size_t)B_SZ * H_SZ];                      // [B,H] (scattered rows b=g*T+t)
__device__ float g_w[T_SZ * K_SZ];
__device__ float g_conf[T_SZ];
__device__ float g_ent[T_SZ];
__device__ float g_pe[B_SZ];
__device__ float g_nov[B_SZ];
__device__ float g_sp[B_SZ];
__device__ float g_pl[B_SZ];
__device__ float g_extra[T_SZ * H_SZ];                           // per-t routing extra bias

// ---------------- bf16 hi/lo scratch (split operands) ----------------
__device__ __align__(16) bf16 g_x_hi[(size_t)B_SZ * D_SZ];
__device__ __align__(16) bf16 g_x_lo[(size_t)B_SZ * D_SZ];
__device__ __align__(16) bf16 g_Wp_hi[(size_t)H_SZ * D_SZ];
__device__ __align__(16) bf16 g_Wp_lo[(size_t)H_SZ * D_SZ];
__device__ __align__(16) bf16 g_xp_hi[(size_t)B_SZ * H_SZ];
__device__ __align__(16) bf16 g_xp_lo[(size_t)B_SZ * H_SZ];
__device__ __align__(16) bf16 g_oW1_hi[(size_t)T_SZ * K_SZ * H_SZ * H_SZ];
__device__ __align__(16) bf16 g_oW1_lo[(size_t)T_SZ * K_SZ * H_SZ * H_SZ];
__device__ __align__(16) bf16 g_oW2_hi[(size_t)T_SZ * K_SZ * H_SZ * H_SZ];
__device__ __align__(16) bf16 g_oW2_lo[(size_t)T_SZ * K_SZ * H_SZ * H_SZ];
__device__ __align__(16) bf16 g_h1_hi[(size_t)T_SZ * K_SZ * G_SZ * H_SZ];
__device__ __align__(16) bf16 g_h1_lo[(size_t)T_SZ * K_SZ * G_SZ * H_SZ];
__device__ __align__(16) bf16 g_out_hi[(size_t)B_SZ * H_SZ];
__device__ __align__(16) bf16 g_out_lo[(size_t)B_SZ * H_SZ];
__device__ __align__(16) bf16 g_rW1c_hi[(size_t)H_SZ * H_SZ];
__device__ __align__(16) bf16 g_rW1c_lo[(size_t)H_SZ * H_SZ];
__device__ __align__(16) bf16 g_phW_hi[(size_t)D_SZ * H_SZ];
__device__ __align__(16) bf16 g_phW_lo[(size_t)D_SZ * H_SZ];

// ---------------- helpers ----------------
__device__ __forceinline__ void split2(float v, bf16& h, bf16& l) {
    h = __float2bfloat16(v);
    l = __float2bfloat16(v - __bfloat162float(h));
}

__device__ __forceinline__ void mma16816(float* c, const unsigned* a, const unsigned* b) {
    asm volatile(
        "mma.sync.aligned.m16n8k16.row.col.f32.bf16.bf16.f32 "
        "{%0,%1,%2,%3},{%4,%5,%6,%7},{%8,%9},{%0,%1,%2,%3};"
        : "+f"(c[0]), "+f"(c[1]), "+f"(c[2]), "+f"(c[3])
        : "r"(a[0]), "r"(a[1]), "r"(a[2]), "r"(a[3]), "r"(b[0]), "r"(b[1]));
}

#define LDMX4(R_, ADDR_)                                                      \
    asm volatile("ldmatrix.sync.aligned.m8n8.x4.shared.b16 {%0,%1,%2,%3},[%4];" \
                 : "=r"((R_)[0]), "=r"((R_)[1]), "=r"((R_)[2]), "=r"((R_)[3]) \
                 : "r"(ADDR_))

#define LDMX2(R_, ADDR_)                                                      \
    asm volatile("ldmatrix.sync.aligned.m8n8.x2.shared.b16 {%0,%1},[%2];"     \
                 : "=r"((R_)[0]), "=r"((R_)[1]) : "r"(ADDR_))

#define CPA(DST_, SRC_)                                                       \
    asm volatile("cp.async.cg.shared.global [%0],[%1],16;" :: "r"(DST_), "l"(SRC_))

#define CP_COMMIT asm volatile("cp.async.commit_group;")
#define CP_WAIT1  asm volatile("cp.async.wait_group 1;")
#define CP_WAIT0  asm volatile("cp.async.wait_group 0;")

// ---------------- bf16x3 tensor-core GEMM: C = A @ B^T (+bias)(+extra)(relu) ----------------
// A_hi/lo [M, lda] bf16 row-major (k contig), B_hi/lo [N, ldb] bf16 row-major (k contig).
// a_scatter/c_scatter: logical row r -> global row r*scatter + tcur, tcur = z / t_div.
// BM=BN=128, BK=32, 256 threads (8 warps in 2x4, warp tile 64x32).
// smem per stage (bytes): Ahi[128][40]=10240, Alo, Bhi, Blo -> 40960; 2 stages = 81920.
#define GBM 128
#define GBN 128
#define GBK 32
#define SROW 40           // padded row length in bf16 elements (80 bytes, conflict-free)
#define STAGE_BYTES 40960u

#define LOAD_STAGE(S_, KB_) do {                                              \
    uint32_t base_ = smem_u32 + (uint32_t)(S_) * STAGE_BYTES;                 \
    CPA(base_ +      0u + sOff0, pAh0 + (KB_));                               \
    CPA(base_ +      0u + sOff1, pAh1 + (KB_));                               \
    CPA(base_ + 10240u + sOff0, pAl0 + (KB_));                                \
    CPA(base_ + 10240u + sOff1, pAl1 + (KB_));                                \
    CPA(base_ + 20480u + sOff0, pBh0 + (KB_));                                \
    CPA(base_ + 20480u + sOff1, pBh1 + (KB_));                                \
    CPA(base_ + 30720u + sOff0, pBl0 + (KB_));                                \
    CPA(base_ + 30720u + sOff1, pBl1 + (KB_));                                \
} while (0)

__global__ __launch_bounds__(256, 2)
void gemm3(const bf16* __restrict__ Ah, const bf16* __restrict__ Al,
           int lda, long a_bstride, int a_scatter, int t_div,
           const bf16* __restrict__ Bh, const bf16* __restrict__ Bl,
           int ldb, long b_bstride,
           const float* __restrict__ bias, long bias_bstride,
           const float* __restrict__ extra,
           float* __restrict__ C, bf16* __restrict__ Chi, bf16* __restrict__ Clo,
           int ldc, long c_bstride, int c_scatter,
           int N, int Kdim, int do_relu)
{
    extern __shared__ __align__(16) char smem_raw[];
    uint32_t smem_u32 = (uint32_t)__cvta_generic_to_shared(smem_raw);

    const int tid  = threadIdx.x;
    const int z    = blockIdx.z;
    const int tcur = z / t_div;
    const int brow = blockIdx.y * GBM;
    const int bcol = blockIdx.x * GBN;

    // ---- loader setup: 512 (row,chunk) slots, 2 per thread ----
    const int id0 = tid * 2, id1 = id0 + 1;
    const int r0 = id0 >> 2, ch0 = (id0 & 3) * 8;   // chunk col (elements), 8 bf16 = 16B
    const int r1 = id1 >> 2, ch1 = (id1 & 3) * 8;

    long arow0 = brow + r0, arow1 = brow + r1;
    if (a_scatter) { arow0 = arow0 * a_scatter + tcur; arow1 = arow1 * a_scatter + tcur; }
    const bf16* pAh0 = Ah + z * a_bstride + arow0 * (long)lda + ch0;
    const bf16* pAh1 = Ah + z * a_bstride + arow1 * (long)lda + ch1;
    const bf16* pAl0 = Al + z * a_bstride + arow0 * (long)lda + ch0;
    const bf16* pAl1 = Al + z * a_bstride + arow1 * (long)lda + ch1;
    const bf16* pBh0 = Bh + z * b_bstride + (long)(bcol + r0) * ldb + ch0;
    const bf16* pBh1 = Bh + z * b_bstride + (long)(bcol + r1) * ldb + ch1;
    const bf16* pBl0 = Bl + z * b_bstride + (long)(bcol + r0) * ldb + ch0;
    const bf16* pBl1 = Bl + z * b_bstride + (long)(bcol + r1) * ldb + ch1;
    const uint32_t sOff0 = (uint32_t)(r0 * SROW + ch0) * 2u;
    const uint32_t sOff1 = (uint32_t)(r1 * SROW + ch1) * 2u;

    // ---- fragment-load setup ----
    const int lane = tid & 31;
    const int warp = tid >> 5;
    const int wm = (warp & 1) * 64;
    const int wn = (warp >> 1) * 32;
    const int aMat = lane >> 3, aR = lane & 7;
    const uint32_t aOff = (uint32_t)((wm + (aMat & 1) * 8 + aR) * SROW + (aMat >> 1) * 8) * 2u;
    const int bL = lane & 15;
    const uint32_t bOff = (uint32_t)((wn + (bL & 7)) * SROW + ((bL >> 3) & 1) * 8) * 2u;

    float acc[4][4][4];
#pragma unroll
    for (int i = 0; i < 4; i++)
#pragma unroll
        for (int j = 0; j < 4; j++)
#pragma unroll
            for (int q = 0; q < 4; q++) acc[i][j][q] = 0.f;

    const int nIter = Kdim / GBK;
    LOAD_STAGE(0, 0);
    CP_COMMIT;

    for (int it = 0; it < nIter; ++it) {
        if (it + 1 < nIter) {
            LOAD_STAGE((it + 1) & 1, (long)(it + 1) * GBK);
            CP_COMMIT;
            CP_WAIT1;
        } else {
            CP_WAIT0;
        }
        __syncthreads();

        const uint32_t baseA_hi = smem_u32 + (uint32_t)(it & 1) * STAGE_BYTES;
        const uint32_t baseA_lo = baseA_hi + 10240u;
        const uint32_t baseB_hi = baseA_hi + 20480u;
        const uint32_t baseB_lo = baseA_hi + 30720u;

#pragma unroll
        for (int kk = 0; kk < 2; kk++) {
            const uint32_t kkb = (uint32_t)kk * 32u;  // 16 cols * 2 bytes
            unsigned bh[4][2], bl[4][2];
#pragma unroll
            for (int j = 0; j < 4; j++) {
                LDMX2(bh[j], baseB_hi + bOff + (uint32_t)j * 640u + kkb);
                LDMX2(bl[j], baseB_lo + bOff + (uint32_t)j * 640u + kkb);
            }
#pragma unroll
            for (int i = 0; i < 4; i++) {
                unsigned ah[4], al[4];
                LDMX4(ah, baseA_hi + aOff + (uint32_t)i * 1280u + kkb);
                LDMX4(al, baseA_lo + aOff + (uint32_t)i * 1280u + kkb);
#pragma unroll
                for (int j = 0; j < 4; j++) {
                    mma16816(acc[i][j], ah, bh[j]);
                    mma16816(acc[i][j], ah, bl[j]);
                    mma16816(acc[i][j], al, bh[j]);
                }
            }
        }
        __syncthreads();
    }

    // ---- epilogue ----
    const float* biasb = bias ? bias + (long)z * bias_bstride : nullptr;
    const int g4 = lane >> 2, t4 = lane & 3;
#pragma unroll
    for (int i = 0; i < 4; i++) {
#pragma unroll
        for (int half = 0; half < 2; half++) {
            int m_local = wm + i * 16 + g4 + half * 8;
            long crow = brow + m_local;
            if (c_scatter) crow = crow * c_scatter + tcur;
            long rbase = (long)z * c_bstride + crow * (long)ldc;
#pragma unroll
            for (int j = 0; j < 4; j++) {
                int n_local = wn + j * 8 + t4 * 2;
                int n = bcol + n_local;
                float v0 = acc[i][j][half * 2 + 0];
                float v1 = acc[i][j][half * 2 + 1];
                if (biasb) { v0 += biasb[n]; v1 += biasb[n + 1]; }
                if (extra) { v0 += extra[tcur * N + n]; v1 += extra[tcur * N + n + 1]; }
                if (do_relu) { v0 = fmaxf(v0, 0.f); v1 = fmaxf(v1, 0.f); }
                if (C) {
                    float2 f2; f2.x = v0; f2.y = v1;
                    *(float2*)(C + rbase + n) = f2;
                }
                if (Chi) {
                    bf16 h0, l0, h1, l1;
                    split2(v0, h0, l0); split2(v1, h1, l1);
                    __nv_bfloat162 ph; ph.x = h0; ph.y = h1;
                    __nv_bfloat162 pl; pl.x = l0; pl.y = l1;
                    *(__nv_bfloat162*)(Chi + rbase + n) = ph;
                    *(__nv_bfloat162*)(Clo + rbase + n) = pl;
                }
            }
        }
    }
}

// ---------------- fp32 -> bf16 hi/lo split conversion ----------------
__global__ void convert_split(const float* __restrict__ in, bf16* __restrict__ hi,
                              bf16* __restrict__ lo, long n4)
{
    long i = blockIdx.x * (long)blockDim.x + threadIdx.x;
    if (i >= n4) return;
    float4 v = ((const float4*)in)[i];
    bf16 h0, h1, h2, h3, l0, l1, l2, l3;
    split2(v.x, h0, l0); split2(v.y, h1, l1); split2(v.z, h2, l2); split2(v.w, h3, l3);
    __nv_bfloat162 a, b;
    a.x = h0; a.y = h1; b.x = h2; b.y = h3;
    ((__nv_bfloat162*)hi)[i * 2] = a; ((__nv_bfloat162*)hi)[i * 2 + 1] = b;
    a.x = l0; a.y = l1; b.x = l2; b.y = l3;
    ((__nv_bfloat162*)lo)[i * 2] = a; ((__nv_bfloat162*)lo)[i * 2 + 1] = b;
}

// extract + split first H columns of rW1 [H, H+7]
__global__ void rw1_extract(const float* __restrict__ rW1, bf16* __restrict__ hi,
                            bf16* __restrict__ lo)
{
    int idx = blockIdx.x * 256 + threadIdx.x;   // H*H
    int i = idx >> 9, j = idx & 511;
    float f = rW1[(long)i * (H_SZ + 7) + j];
    bf16 h, l; split2(f, h, l);
    hi[idx] = h; lo[idx] = l;
}

// ---------------- softmax over op_logits + conflict/entropy ----------------
__global__ void softmax_stats(const float* __restrict__ op_logits)
{
    int t = threadIdx.x;
    if (t < T_SZ) {
        float l0 = op_logits[t*K_SZ+0], l1 = op_logits[t*K_SZ+1], l2 = op_logits[t*K_SZ+2];
        float m = fmaxf(l0, fmaxf(l1, l2));
        float e0 = expf(l0 - m), e1 = expf(l1 - m), e2 = expf(l2 - m);
        float s = e0 + e1 + e2;
        float w0 = e0 / s, w1 = e1 / s, w2 = e2 / s;
        g_w[t*K_SZ+0] = w0; g_w[t*K_SZ+1] = w1; g_w[t*K_SZ+2] = w2;
        float mean = (w0 + w1 + w2) * (1.f / 3.f);
        float d0 = w0 - mean, d1 = w1 - mean, d2 = w2 - mean;
        g_conf[t] = sqrtf((d0*d0 + d1*d1 + d2*d2) * 0.5f);     // ddof=1 -> /(K-1)=2
        float sum = w0 + w1 + w2;
        float inv = 1.f / (sum + 1e-6f);
        float u0 = w0*inv, u1 = w1*inv, u2 = w2*inv;
        float ent = -(u0*logf(fmaxf(u0,1e-6f)) + u1*logf(fmaxf(u1,1e-6f)) + u2*logf(fmaxf(u2,1e-6f)));
        g_ent[t] = ent;
    }
}

// ---------------- weighted op mixture + hi/lo emit ----------------
__global__ void wsum_kernel(float* __restrict__ out_full)
{
    long idx4 = (long)blockIdx.x * blockDim.x + threadIdx.x;  // over T*G*H/4
    int i4 = (int)(idx4 % (H_SZ / 4));
    long r = idx4 / (H_SZ / 4);
    int g = (int)(r % G_SZ);
    int t = (int)(r / G_SZ);
    float w0 = g_w[t*K_SZ+0], w1 = g_w[t*K_SZ+1], w2 = g_w[t*K_SZ+2];
    const float4* p0 = (const float4*)&g_h2[(((long)(t*K_SZ+0))*G_SZ + g)*H_SZ];
    const float4* p1 = (const float4*)&g_h2[(((long)(t*K_SZ+1))*G_SZ + g)*H_SZ];
    const float4* p2 = (const float4*)&g_h2[(((long)(t*K_SZ+2))*G_SZ + g)*H_SZ];
    float4 v0 = p0[i4], v1 = p1[i4], v2 = p2[i4];
    float4 o;
    o.x = w0*v0.x + w1*v1.x + w2*v2.x;
    o.y = w0*v0.y + w1*v1.y + w2*v2.y;
    o.z = w0*v0.z + w1*v1.z + w2*v2.z;
    o.w = w0*v0.w + w1*v1.w + w2*v2.w;
    long rowbase = ((long)(g*T_SZ + t))*H_SZ;
    ((float4*)&out_full[rowbase])[i4] = o;
    bf16 h0,h1,h2v,h3,l0,l1,l2v,l3;
    split2(o.x,h0,l0); split2(o.y,h1,l1); split2(o.z,h2v,l2v); split2(o.w,h3,l3);
    __nv_bfloat162 a,b;
    a.x=h0; a.y=h1; b.x=h2v; b.y=h3;
    ((__nv_bfloat162*)&g_out_hi[rowbase])[i4*2] = a;
    ((__nv_bfloat162*)&g_out_hi[rowbase])[i4*2+1] = b;
    a.x=l0; a.y=l1; b.x=l2v; b.y=l3;
    ((__nv_bfloat162*)&g_out_lo[rowbase])[i4*2] = a;
    ((__nv_bfloat162*)&g_out_lo[rowbase])[i4*2+1] = b;
}

// ---------------- per-row stats (one warp per row b) ----------------
__device__ __forceinline__ float warp_sum(float v) {
#pragma unroll
    for (int o = 16; o > 0; o >>= 1) v += __shfl_down_sync(0xffffffffu, v, o);
    return v;
}

__global__ void row_stats(const float* __restrict__ out_full, const float* __restrict__ noise)
{
    int warp = (int)((blockIdx.x * (long)blockDim.x + threadIdx.x) >> 5);
    int lane = threadIdx.x & 31;
    if (warp >= B_SZ) return;
    const float4* o  = (const float4*)(out_full + (long)warp * H_SZ);
    const float4* xr = (const float4*)(g_xp     + (long)warp * H_SZ);
    const float4* nr = (const float4*)(noise    + (long)warp * H_SZ);
    float pe = 0.f, nov = 0.f, sp = 0.f, pl = 0.f;
#pragma unroll
    for (int i = lane; i < H_SZ/4; i += 32) {
        float4 ov = o[i], xv = xr[i], nvr = nr[i];
        float d;
        d = ov.x - xv.x; pe += d*d; nov += xv.x*xv.x; sp += fabsf(ov.x);
        d = ov.y - xv.y; pe += d*d; nov += xv.y*xv.y; sp += fabsf(ov.y);
        d = ov.z - xv.z; pe += d*d; nov += xv.z*xv.z; sp += fabsf(ov.z);
        d = ov.w - xv.w; pe += d*d; nov += xv.w*xv.w; sp += fabsf(ov.w);
        float nx = nvr.x*0.01f, ny = nvr.y*0.01f, nz = nvr.z*0.01f, nw = nvr.w*0.01f;
        pl += nx*nx + ny*ny + nz*nz + nw*nw;
    }
    pe = warp_sum(pe); nov = warp_sum(nov); sp = warp_sum(sp); pl = warp_sum(pl);
    if (lane == 0) {
        const float inv = 1.f / (float)H_SZ;
        g_pe[warp] = pe * inv; g_nov[warp] = nov * inv;
        g_sp[warp] = sp * inv; g_pl[warp]  = pl * inv;
    }
}

// ---------------- finalize: signals, decision, routing extra bias (one block per t) ----------------
__device__ __forceinline__ float block_sum(float v, float* red, int tid) {
    red[tid] = v; __syncthreads();
    for (int s = 128; s > 0; s >>= 1) { if (tid < s) red[tid] += red[tid + s]; __syncthreads(); }
    float r = red[0]; __syncthreads();
    return r;
}

__global__ void finalize_kernel(const float* __restrict__ id_emb, const float* __restrict__ rW1,
                                const float* __restrict__ gW1, const float* __restrict__ gb1,
                                const float* __restrict__ gW2, const float* __restrict__ gb2,
                                float* __restrict__ decision)
{
    __shared__ float red[256];
    __shared__ float sig[7];
    __shared__ float gch[H_SZ];
    const int t = blockIdx.x, tid = threadIdx.x;

    float pe = 0.f, pe2 = 0.f, nov = 0.f, sp = 0.f, pl = 0.f;
    for (int g = tid; g < G_SZ; g += 256) {
        int b = g * T_SZ + t;
        float p = g_pe[b];
        pe += p; pe2 += p * p; nov += g_nov[b]; sp += g_sp[b]; pl += g_pl[b];
    }
    float S_pe  = block_sum(pe,  red, tid);
    float S_pe2 = block_sum(pe2, red, tid);
    float S_nov = block_sum(nov, red, tid);
    float S_sp  = block_sum(sp,  red, tid);
    float S_pl  = block_sum(pl,  red, tid);

    if (tid == 0) {
        const float invg = 1.f / (float)G_SZ;
        float pe_m = S_pe * invg, pe2_m = S_pe2 * invg;
        float c = 0.01f * pe_m;
        sig[0] = S_pl * invg;                      // plasticity
        sig[1] = S_nov * invg;                     // novelty
        sig[2] = pe_m;                             // pred_err
        sig[3] = g_ent[t];                         // entropy
        sig[4] = S_sp * invg;                      // sparsity
        sig[5] = -pe_m;                            // reward_delta
        sig[6] = pe2_m - 2.f * c * pe_m + c * c;   // reward_var
    }
    __syncthreads();

    // growth controller MLP: 7 -> H (relu)
    for (int i = tid; i < H_SZ; i += 256) {
        float a = gb1[t * H_SZ + i];
#pragma unroll
        for (int j = 0; j < 7; j++) a += gW1[((long)(t * H_SZ + i)) * 7 + j] * sig[j];
        gch[i] = fmaxf(a, 0.f);
    }
    __syncthreads();

    // H -> 2
    for (int o = 0; o < 2; o++) {
        float d = 0.f;
        for (int i = tid; i < H_SZ; i += 256) d += gW2[((long)(t * 2 + o)) * H_SZ + i] * gch[i];
        float S = block_sum(d, red, tid);
        if (tid == 0) decision[t * 2 + o] = S + gb2[t * 2 + o];
    }

    // routing extra bias c_extra[t, i] = sum_j ext[j] * rW1[i, H + j]
    __shared__ float ext[7];
    if (tid == 0) {
        ext[0] = id_emb[t*4+0]; ext[1] = id_emb[t*4+1];
        ext[2] = id_emb[t*4+2]; ext[3] = id_emb[t*4+3];
        ext[4] = sig[1];        // novelty mean
        ext[5] = g_conf[t];     // conflict
        ext[6] = sig[2];        // last plasticity == pred_err mean
    }
    __syncthreads();
    for (int i = tid; i < H_SZ; i += 256) {
        float a = 0.f;
#pragma unroll
        for (int j = 0; j < 7; j++) a += ext[j] * rW1[(long)i * (H_SZ + 7) + H_SZ + j];
        g_extra[t * H_SZ + i] = a;
    }
}

// ---------------- logits: rh[b] @ rW2^T + rb2 (one block per row, warp per output) ----------------
__global__ void logits_kernel(const float* __restrict__ rW2, const float* __restrict__ rb2,
                              float* __restrict__ logits)
{
    const int b = blockIdx.x;
    const int o = threadIdx.x >> 5, lane = threadIdx.x & 31;
    const float4* r = (const float4*)(g_rh + (long)b * H_SZ);
    const float4* wrow = (const float4*)(rW2 + (long)o * H_SZ);
    float acc = 0.f;
    for (int i = lane; i < H_SZ/4; i += 32) {
        float4 rv = r[i], wv = wrow[i];
        acc += rv.x*wv.x + rv.y*wv.y + rv.z*wv.z + rv.w*wv.w;
    }
    acc = warp_sum(acc);
    if (lane == 0) logits[(long)b * (T_SZ + 1) + o] = acc + rb2[o];
}

// ---------------- launch ----------------
extern "C" void kernel_launch(void* const* d_in, const int* in_sizes, int n_in,
                              void* d_out, int out_size)
{
    const float* x         = (const float*)d_in[0];
    const float* Wp        = (const float*)d_in[1];
    const float* bp        = (const float*)d_in[2];
    const float* opW1      = (const float*)d_in[3];
    const float* opb1      = (const float*)d_in[4];
    const float* opW2      = (const float*)d_in[5];
    const float* opb2      = (const float*)d_in[6];
    const float* op_logits = (const float*)d_in[7];
    const float* id_emb    = (const float*)d_in[8];
    const float* rW1       = (const float*)d_in[9];
    const float* rb1       = (const float*)d_in[10];
    const float* rW2       = (const float*)d_in[11];
    const float* rb2       = (const float*)d_in[12];
    const float* gW1       = (const float*)d_in[13];
    const float* gb1       = (const float*)d_in[14];
    const float* gW2       = (const float*)d_in[15];
    const float* gb2       = (const float*)d_in[16];
    const float* phW       = (const float*)d_in[17];
    const float* phb       = (const float*)d_in[18];
    const float* noise     = (const float*)d_in[19];

    float* out_full = (float*)d_out;
    float* logits   = out_full + (size_t)B_SZ * H_SZ;
    float* pred     = logits   + (size_t)B_SZ * (T_SZ + 1);
    float* decision = pred     + (size_t)B_SZ * D_SZ;

    float *xp, *h2, *extra;
    bf16 *x_hi, *x_lo, *Wp_hi, *Wp_lo, *xp_hi, *xp_lo, *oW1_hi, *oW1_lo, *oW2_hi, *oW2_lo;
    bf16 *h1_hi, *h1_lo, *out_hi, *out_lo, *rW1c_hi, *rW1c_lo, *phW_hi, *phW_lo;
    cudaGetSymbolAddress((void**)&xp,      g_xp);
    cudaGetSymbolAddress((void**)&h2,      g_h2);
    cudaGetSymbolAddress((void**)&extra,   g_extra);
    cudaGetSymbolAddress((void**)&x_hi,    g_x_hi);    cudaGetSymbolAddress((void**)&x_lo,    g_x_lo);
    cudaGetSymbolAddress((void**)&Wp_hi,   g_Wp_hi);   cudaGetSymbolAddress((void**)&Wp_lo,   g_Wp_lo);
    cudaGetSymbolAddress((void**)&xp_hi,   g_xp_hi);   cudaGetSymbolAddress((void**)&xp_lo,   g_xp_lo);
    cudaGetSymbolAddress((void**)&oW1_hi,  g_oW1_hi);  cudaGetSymbolAddress((void**)&oW1_lo,  g_oW1_lo);
    cudaGetSymbolAddress((void**)&oW2_hi,  g_oW2_hi);  cudaGetSymbolAddress((void**)&oW2_lo,  g_oW2_lo);
    cudaGetSymbolAddress((void**)&h1_hi,   g_h1_hi);   cudaGetSymbolAddress((void**)&h1_lo,   g_h1_lo);
    cudaGetSymbolAddress((void**)&out_hi,  g_out_hi);  cudaGetSymbolAddress((void**)&out_lo,  g_out_lo);
    cudaGetSymbolAddress((void**)&rW1c_hi, g_rW1c_hi); cudaGetSymbolAddress((void**)&rW1c_lo, g_rW1c_lo);
    cudaGetSymbolAddress((void**)&phW_hi,  g_phW_hi);  cudaGetSymbolAddress((void**)&phW_lo,  g_phW_lo);

    cudaFuncSetAttribute(gemm3, cudaFuncAttributeMaxDynamicSharedMemorySize, 2 * (int)STAGE_BYTES);
    const int SM = 2 * (int)STAGE_BYTES;
    float* rh; cudaGetSymbolAddress((void**)&rh, g_rh);

    // 0) split conversions of inputs/weights
    {
        long n4;
        n4 = (long)B_SZ * D_SZ / 4;           convert_split<<<(int)((n4 + 255) / 256), 256>>>(x,    x_hi,  x_lo,  n4);
        n4 = (long)H_SZ * D_SZ / 4;           convert_split<<<(int)((n4 + 255) / 256), 256>>>(Wp,   Wp_hi, Wp_lo, n4);
        n4 = (long)T_SZ*K_SZ*H_SZ*H_SZ / 4;   convert_split<<<(int)((n4 + 255) / 256), 256>>>(opW1, oW1_hi, oW1_lo, n4);
        n4 = (long)T_SZ*K_SZ*H_SZ*H_SZ / 4;   convert_split<<<(int)((n4 + 255) / 256), 256>>>(opW2, oW2_hi, oW2_lo, n4);
        n4 = (long)D_SZ * H_SZ / 4;           convert_split<<<(int)((n4 + 255) / 256), 256>>>(phW,  phW_hi, phW_lo, n4);
        rw1_extract<<<(H_SZ * H_SZ) / 256, 256>>>(rW1, rW1c_hi, rW1c_lo);
    }

    // 1) xp = x @ Wp^T + bp          (fp32 + hi/lo out)
    gemm3<<<dim3(H_SZ/GBN, B_SZ/GBM, 1), 256, SM>>>(
        x_hi, x_lo, D_SZ, 0, 0, 1,
        Wp_hi, Wp_lo, D_SZ, 0,
        bp, 0, nullptr,
        xp, xp_hi, xp_lo, H_SZ, 0, 0, H_SZ, D_SZ, 0);

    // 2) softmax / conflict / entropy
    softmax_stats<<<1, 32>>>(op_logits);

    // 3) h1[t,k] = relu(xg[t] @ opW1[t,k]^T + opb1)   (A scattered; hi/lo out only)
    gemm3<<<dim3(H_SZ/GBN, G_SZ/GBM, T_SZ*K_SZ), 256, SM>>>(
        xp_hi, xp_lo, H_SZ, 0, T_SZ, K_SZ,
        oW1_hi, oW1_lo, H_SZ, (long)H_SZ*H_SZ,
        opb1, H_SZ, nullptr,
        nullptr, h1_hi, h1_lo, H_SZ, (long)G_SZ*H_SZ, 0, H_SZ, H_SZ, 1);

    // 4) h2[t,k] = relu(h1[t,k] @ opW2[t,k]^T + opb2)   (fp32 out only)
    gemm3<<<dim3(H_SZ/GBN, G_SZ/GBM, T_SZ*K_SZ), 256, SM>>>(
        h1_hi, h1_lo, H_SZ, (long)G_SZ*H_SZ, 0, 1,
        oW2_hi, oW2_lo, H_SZ, (long)H_SZ*H_SZ,
        opb2, H_SZ, nullptr,
        h2, nullptr, nullptr, H_SZ, (long)G_SZ*H_SZ, 0, H_SZ, H_SZ, 1);

    // 5) out_full (scattered) = sum_k w[t,k] * h2[t,k]   (+ hi/lo emit)
    wsum_kernel<<<(T_SZ*G_SZ*H_SZ/4)/256, 256>>>(out_full);

    // 6) per-row stats
    row_stats<<<(B_SZ*32)/256, 256>>>(out_full, noise);

    // 7) signals, decision, routing extra bias
    finalize_kernel<<<T_SZ, 256>>>(id_emb, rW1, gW1, gb1, gW2, gb2, decision);

    // 8) rh = relu(out @ rW1[:, :H]^T + c_extra[t] + rb1)   (A & C rows scattered)
    gemm3<<<dim3(H_SZ/GBN, G_SZ/GBM, T_SZ), 256, SM>>>(
        out_hi, out_lo, H_SZ, 0, T_SZ, 1,
        rW1c_hi, rW1c_lo, H_SZ, 0,
        rb1, 0, extra,
        rh, nullptr, nullptr, H_SZ, 0, T_SZ, H_SZ, H_SZ, 1);

    // 9) logits = rh @ rW2^T + rb2
    logits_kernel<<<B_SZ, (T_SZ + 1) * 32>>>(rW2, rb2, logits);

    // 10) pred = out_full @ phW^T + phb
    gemm3<<<dim3(D_SZ/GBN, B_SZ/GBM, 1), 256, SM>>>(
        out_hi, out_lo, H_SZ, 0, 0, 1,
        phW_hi, phW_lo, H_SZ, 0,
        phb, 0, nullptr,
        pred, nullptr, nullptr, D_SZ, 0, 0, D_SZ, H_SZ, 0);
}

// round 12
// speedup vs baseline: 3.0933x; 1.2724x over previous
#include <cuda_runtime.h>
#include <cuda_fp16.h>
#include <stdint.h>
#include <math.h>

typedef __half h16;

#define B_SZ 12288
#define D_SZ 1024
#define H_SZ 512
#define T_SZ 12
#define K_SZ 3
#define G_SZ 1024   // B_SZ / T_SZ

// ---------------- fp32 scratch ----------------
__device__ float g_xp[(size_t)B_SZ * H_SZ];
__device__ float g_h2[(size_t)T_SZ * K_SZ * G_SZ * H_SZ];
__device__ float g_rh[(size_t)B_SZ * H_SZ];
__device__ float g_w[T_SZ * K_SZ];
__device__ float g_conf[T_SZ];
__device__ float g_ent[T_SZ];
__device__ float g_pe[B_SZ];
__device__ float g_nov[B_SZ];
__device__ float g_sp[B_SZ];
__device__ float g_pl[B_SZ];
__device__ float g_extra[T_SZ * H_SZ];

// ---------------- fp16 scratch: A-side hi/lo pairs, B-side single ----------------
__device__ __align__(16) h16 g_x_hi[(size_t)B_SZ * D_SZ];
__device__ __align__(16) h16 g_x_lo[(size_t)B_SZ * D_SZ];
__device__ __align__(16) h16 g_xp_hi[(size_t)B_SZ * H_SZ];
__device__ __align__(16) h16 g_xp_lo[(size_t)B_SZ * H_SZ];
__device__ __align__(16) h16 g_h1_hi[(size_t)T_SZ * K_SZ * G_SZ * H_SZ];
__device__ __align__(16) h16 g_h1_lo[(size_t)T_SZ * K_SZ * G_SZ * H_SZ];
__device__ __align__(16) h16 g_out_hi[(size_t)B_SZ * H_SZ];
__device__ __align__(16) h16 g_out_lo[(size_t)B_SZ * H_SZ];
__device__ __align__(16) h16 g_Wp_h[(size_t)H_SZ * D_SZ];
__device__ __align__(16) h16 g_oW1_h[(size_t)T_SZ * K_SZ * H_SZ * H_SZ];
__device__ __align__(16) h16 g_oW2_h[(size_t)T_SZ * K_SZ * H_SZ * H_SZ];
__device__ __align__(16) h16 g_rW1c_h[(size_t)H_SZ * H_SZ];
__device__ __align__(16) h16 g_phW_h[(size_t)D_SZ * H_SZ];

// ---------------- helpers ----------------
__device__ __forceinline__ void split2h(float v, h16& h, h16& l) {
    h = __float2half_rn(v);
    l = __float2half_rn(v - __half2float(h));
}

__device__ __forceinline__ void mma16816(float* c, const unsigned* a, const unsigned* b) {
    asm volatile(
        "mma.sync.aligned.m16n8k16.row.col.f32.f16.f16.f32 "
        "{%0,%1,%2,%3},{%4,%5,%6,%7},{%8,%9},{%0,%1,%2,%3};"
        : "+f"(c[0]), "+f"(c[1]), "+f"(c[2]), "+f"(c[3])
        : "r"(a[0]), "r"(a[1]), "r"(a[2]), "r"(a[3]), "r"(b[0]), "r"(b[1]));
}

#define LDMX4(R_, ADDR_)                                                      \
    asm volatile("ldmatrix.sync.aligned.m8n8.x4.shared.b16 {%0,%1,%2,%3},[%4];" \
                 : "=r"((R_)[0]), "=r"((R_)[1]), "=r"((R_)[2]), "=r"((R_)[3]) \
                 : "r"(ADDR_))

#define LDMX2(R_, ADDR_)                                                      \
    asm volatile("ldmatrix.sync.aligned.m8n8.x2.shared.b16 {%0,%1},[%2];"     \
                 : "=r"((R_)[0]), "=r"((R_)[1]) : "r"(ADDR_))

#define CPA(DST_, SRC_)                                                       \
    asm volatile("cp.async.cg.shared.global [%0],[%1],16;" :: "r"(DST_), "l"(SRC_))

#define CP_COMMIT asm volatile("cp.async.commit_group;")
#define CP_WAIT1  asm volatile("cp.async.wait_group 1;")
#define CP_WAIT0  asm volatile("cp.async.wait_group 0;")

// ---------------- fp16 2-product tensor-core GEMM: C = A @ B^T (+bias)(+extra)(relu) ----
// A_hi/lo [M, lda] fp16 row-major (k contig) — exact split pair.
// B [N, ldb] single fp16 row-major (k contig).
// a_scatter/c_scatter: logical row r -> global row r*scatter + tcur, tcur = z / t_div.
// BM=BN=128, BK=32, 256 threads (8 warps 2x4, warp tile 64x32).
// smem per stage: Ahi[128][40] + Alo + B = 30720 B; 2 stages = 61440 B.
#define GBM 128
#define GBN 128
#define GBK 32
#define SROW 40
#define STAGE_BYTES 30720u

#define LOAD_STAGE(S_, KB_) do {                                              \
    uint32_t base_ = smem_u32 + (uint32_t)(S_) * STAGE_BYTES;                 \
    CPA(base_ +      0u + sOff0, pAh0 + (KB_));                               \
    CPA(base_ +      0u + sOff1, pAh1 + (KB_));                               \
    CPA(base_ + 10240u + sOff0, pAl0 + (KB_));                                \
    CPA(base_ + 10240u + sOff1, pAl1 + (KB_));                                \
    CPA(base_ + 20480u + sOff0, pB0 + (KB_));                                 \
    CPA(base_ + 20480u + sOff1, pB1 + (KB_));                                 \
} while (0)

__global__ __launch_bounds__(256, 2)
void gemm2(const h16* __restrict__ Ah, const h16* __restrict__ Al,
           int lda, long a_bstride, int a_scatter, int t_div,
           const h16* __restrict__ Bm,
           int ldb, long b_bstride,
           const float* __restrict__ bias, long bias_bstride,
           const float* __restrict__ extra,
           float* __restrict__ C, h16* __restrict__ Chi, h16* __restrict__ Clo,
           int ldc, long c_bstride, int c_scatter,
           int N, int Kdim, int do_relu)
{
    extern __shared__ __align__(16) char smem_raw[];
    uint32_t smem_u32 = (uint32_t)__cvta_generic_to_shared(smem_raw);

    const int tid  = threadIdx.x;
    const int z    = blockIdx.z;
    const int tcur = z / t_div;
    const int brow = blockIdx.y * GBM;
    const int bcol = blockIdx.x * GBN;

    // ---- loader setup: 512 (row,chunk) slots, 2 per thread ----
    const int id0 = tid * 2, id1 = id0 + 1;
    const int r0 = id0 >> 2, ch0 = (id0 & 3) * 8;
    const int r1 = id1 >> 2, ch1 = (id1 & 3) * 8;

    long arow0 = brow + r0, arow1 = brow + r1;
    if (a_scatter) { arow0 = arow0 * a_scatter + tcur; arow1 = arow1 * a_scatter + tcur; }
    const h16* pAh0 = Ah + z * a_bstride + arow0 * (long)lda + ch0;
    const h16* pAh1 = Ah + z * a_bstride + arow1 * (long)lda + ch1;
    const h16* pAl0 = Al + z * a_bstride + arow0 * (long)lda + ch0;
    const h16* pAl1 = Al + z * a_bstride + arow1 * (long)lda + ch1;
    const h16* pB0  = Bm + z * b_bstride + (long)(bcol + r0) * ldb + ch0;
    const h16* pB1  = Bm + z * b_bstride + (long)(bcol + r1) * ldb + ch1;
    const uint32_t sOff0 = (uint32_t)(r0 * SROW + ch0) * 2u;
    const uint32_t sOff1 = (uint32_t)(r1 * SROW + ch1) * 2u;

    // ---- fragment-load setup ----
    const int lane = tid & 31;
    const int warp = tid >> 5;
    const int wm = (warp & 1) * 64;
    const int wn = (warp >> 1) * 32;
    const int aMat = lane >> 3, aR = lane & 7;
    const uint32_t aOff = (uint32_t)((wm + (aMat & 1) * 8 + aR) * SROW + (aMat >> 1) * 8) * 2u;
    const int bL = lane & 15;
    const uint32_t bOff = (uint32_t)((wn + (bL & 7)) * SROW + ((bL >> 3) & 1) * 8) * 2u;

    float acc[4][4][4];
#pragma unroll
    for (int i = 0; i < 4; i++)
#pragma unroll
        for (int j = 0; j < 4; j++)
#pragma unroll
            for (int q = 0; q < 4; q++) acc[i][j][q] = 0.f;

    const int nIter = Kdim / GBK;
    LOAD_STAGE(0, 0);
    CP_COMMIT;

    for (int it = 0; it < nIter; ++it) {
        if (it + 1 < nIter) {
            LOAD_STAGE((it + 1) & 1, (long)(it + 1) * GBK);
            CP_COMMIT;
            CP_WAIT1;
        } else {
            CP_WAIT0;
        }
        __syncthreads();

        const uint32_t baseA_hi = smem_u32 + (uint32_t)(it & 1) * STAGE_BYTES;
        const uint32_t baseA_lo = baseA_hi + 10240u;
        const uint32_t baseB    = baseA_hi + 20480u;

#pragma unroll
        for (int kk = 0; kk < 2; kk++) {
            const uint32_t kkb = (uint32_t)kk * 32u;
            unsigned bh[4][2];
#pragma unroll
            for (int j = 0; j < 4; j++)
                LDMX2(bh[j], baseB + bOff + (uint32_t)j * 640u + kkb);
#pragma unroll
            for (int i = 0; i < 4; i++) {
                unsigned ah[4], al[4];
                LDMX4(ah, baseA_hi + aOff + (uint32_t)i * 1280u + kkb);
                LDMX4(al, baseA_lo + aOff + (uint32_t)i * 1280u + kkb);
#pragma unroll
                for (int j = 0; j < 4; j++) {
                    mma16816(acc[i][j], ah, bh[j]);
                    mma16816(acc[i][j], al, bh[j]);
                }
            }
        }
        __syncthreads();
    }

    // ---- epilogue ----
    const float* biasb = bias ? bias + (long)z * bias_bstride : nullptr;
    const int g4 = lane >> 2, t4 = lane & 3;
#pragma unroll
    for (int i = 0; i < 4; i++) {
#pragma unroll
        for (int half_ = 0; half_ < 2; half_++) {
            int m_local = wm + i * 16 + g4 + half_ * 8;
            long crow = brow + m_local;
            if (c_scatter) crow = crow * c_scatter + tcur;
            long rbase = (long)z * c_bstride + crow * (long)ldc;
#pragma unroll
            for (int j = 0; j < 4; j++) {
                int n_local = wn + j * 8 + t4 * 2;
                int n = bcol + n_local;
                float v0 = acc[i][j][half_ * 2 + 0];
                float v1 = acc[i][j][half_ * 2 + 1];
                if (biasb) { v0 += biasb[n]; v1 += biasb[n + 1]; }
                if (extra) { v0 += extra[tcur * N + n]; v1 += extra[tcur * N + n + 1]; }
                if (do_relu) { v0 = fmaxf(v0, 0.f); v1 = fmaxf(v1, 0.f); }
                if (C) {
                    float2 f2; f2.x = v0; f2.y = v1;
                    *(float2*)(C + rbase + n) = f2;
                }
                if (Chi) {
                    h16 h0, l0, h1, l1;
                    split2h(v0, h0, l0); split2h(v1, h1, l1);
                    __half2 ph; ph.x = h0; ph.y = h1;
                    __half2 pl; pl.x = l0; pl.y = l1;
                    *(__half2*)(Chi + rbase + n) = ph;
                    *(__half2*)(Clo + rbase + n) = pl;
                }
            }
        }
    }
}

// ---------------- fp32 -> fp16 hi/lo split (A-side) ----------------
__global__ void convert_split(const float* __restrict__ in, h16* __restrict__ hi,
                              h16* __restrict__ lo, long n4)
{
    long i = blockIdx.x * (long)blockDim.x + threadIdx.x;
    if (i >= n4) return;
    float4 v = ((const float4*)in)[i];
    h16 h0, h1, h2, h3, l0, l1, l2, l3;
    split2h(v.x, h0, l0); split2h(v.y, h1, l1); split2h(v.z, h2, l2); split2h(v.w, h3, l3);
    __half2 a, b;
    a.x = h0; a.y = h1; b.x = h2; b.y = h3;
    ((__half2*)hi)[i * 2] = a; ((__half2*)hi)[i * 2 + 1] = b;
    a.x = l0; a.y = l1; b.x = l2; b.y = l3;
    ((__half2*)lo)[i * 2] = a; ((__half2*)lo)[i * 2 + 1] = b;
}

// ---------------- fp32 -> fp16 single (B-side weights) ----------------
__global__ void convert_h(const float* __restrict__ in, h16* __restrict__ out, long n4)
{
    long i = blockIdx.x * (long)blockDim.x + threadIdx.x;
    if (i >= n4) return;
    float4 v = ((const float4*)in)[i];
    __half2 a, b;
    a.x = __float2half_rn(v.x); a.y = __float2half_rn(v.y);
    b.x = __float2half_rn(v.z); b.y = __float2half_rn(v.w);
    ((__half2*)out)[i * 2] = a; ((__half2*)out)[i * 2 + 1] = b;
}

// extract first H columns of rW1 [H, H+7] as fp16
__global__ void rw1_extract(const float* __restrict__ rW1, h16* __restrict__ out)
{
    int idx = blockIdx.x * 256 + threadIdx.x;   // H*H
    int i = idx >> 9, j = idx & 511;
    out[idx] = __float2half_rn(rW1[(long)i * (H_SZ + 7) + j]);
}

// ---------------- softmax over op_logits + conflict/entropy ----------------
__global__ void softmax_stats(const float* __restrict__ op_logits)
{
    int t = threadIdx.x;
    if (t < T_SZ) {
        float l0 = op_logits[t*K_SZ+0], l1 = op_logits[t*K_SZ+1], l2 = op_logits[t*K_SZ+2];
        float m = fmaxf(l0, fmaxf(l1, l2));
        float e0 = expf(l0 - m), e1 = expf(l1 - m), e2 = expf(l2 - m);
        float s = e0 + e1 + e2;
        float w0 = e0 / s, w1 = e1 / s, w2 = e2 / s;
        g_w[t*K_SZ+0] = w0; g_w[t*K_SZ+1] = w1; g_w[t*K_SZ+2] = w2;
        float mean = (w0 + w1 + w2) * (1.f / 3.f);
        float d0 = w0 - mean, d1 = w1 - mean, d2 = w2 - mean;
        g_conf[t] = sqrtf((d0*d0 + d1*d1 + d2*d2) * 0.5f);
        float sum = w0 + w1 + w2;
        float inv = 1.f / (sum + 1e-6f);
        float u0 = w0*inv, u1 = w1*inv, u2 = w2*inv;
        float ent = -(u0*logf(fmaxf(u0,1e-6f)) + u1*logf(fmaxf(u1,1e-6f)) + u2*logf(fmaxf(u2,1e-6f)));
        g_ent[t] = ent;
    }
}

// ---------------- weighted op mixture + hi/lo emit ----------------
__global__ void wsum_kernel(float* __restrict__ out_full)
{
    long idx4 = (long)blockIdx.x * blockDim.x + threadIdx.x;
    int i4 = (int)(idx4 % (H_SZ / 4));
    long r = idx4 / (H_SZ / 4);
    int g = (int)(r % G_SZ);
    int t = (int)(r / G_SZ);
    float w0 = g_w[t*K_SZ+0], w1 = g_w[t*K_SZ+1], w2 = g_w[t*K_SZ+2];
    const float4* p0 = (const float4*)&g_h2[(((long)(t*K_SZ+0))*G_SZ + g)*H_SZ];
    const float4* p1 = (const float4*)&g_h2[(((long)(t*K_SZ+1))*G_SZ + g)*H_SZ];
    const float4* p2 = (const float4*)&g_h2[(((long)(t*K_SZ+2))*G_SZ + g)*H_SZ];
    float4 v0 = p0[i4], v1 = p1[i4], v2 = p2[i4];
    float4 o;
    o.x = w0*v0.x + w1*v1.x + w2*v2.x;
    o.y = w0*v0.y + w1*v1.y + w2*v2.y;
    o.z = w0*v0.z + w1*v1.z + w2*v2.z;
    o.w = w0*v0.w + w1*v1.w + w2*v2.w;
    long rowbase = ((long)(g*T_SZ + t))*H_SZ;
    ((float4*)&out_full[rowbase])[i4] = o;
    h16 h0,h1,h2v,h3,l0,l1,l2v,l3;
    split2h(o.x,h0,l0); split2h(o.y,h1,l1); split2h(o.z,h2v,l2v); split2h(o.w,h3,l3);
    __half2 a,b;
    a.x=h0; a.y=h1; b.x=h2v; b.y=h3;
    ((__half2*)&g_out_hi[rowbase])[i4*2] = a;
    ((__half2*)&g_out_hi[rowbase])[i4*2+1] = b;
    a.x=l0; a.y=l1; b.x=l2v; b.y=l3;
    ((__half2*)&g_out_lo[rowbase])[i4*2] = a;
    ((__half2*)&g_out_lo[rowbase])[i4*2+1] = b;
}

// ---------------- per-row stats (one warp per row b) ----------------
__device__ __forceinline__ float warp_sum(float v) {
#pragma unroll
    for (int o = 16; o > 0; o >>= 1) v += __shfl_down_sync(0xffffffffu, v, o);
    return v;
}

__global__ void row_stats(const float* __restrict__ out_full, const float* __restrict__ noise)
{
    int warp = (int)((blockIdx.x * (long)blockDim.x + threadIdx.x) >> 5);
    int lane = threadIdx.x & 31;
    if (warp >= B_SZ) return;
    const float4* o  = (const float4*)(out_full + (long)warp * H_SZ);
    const float4* xr = (const float4*)(g_xp     + (long)warp * H_SZ);
    const float4* nr = (const float4*)(noise    + (long)warp * H_SZ);
    float pe = 0.f, nov = 0.f, sp = 0.f, pl = 0.f;
#pragma unroll
    for (int i = lane; i < H_SZ/4; i += 32) {
        float4 ov = o[i], xv = xr[i], nvr = nr[i];
        float d;
        d = ov.x - xv.x; pe += d*d; nov += xv.x*xv.x; sp += fabsf(ov.x);
        d = ov.y - xv.y; pe += d*d; nov += xv.y*xv.y; sp += fabsf(ov.y);
        d = ov.z - xv.z; pe += d*d; nov += xv.z*xv.z; sp += fabsf(ov.z);
        d = ov.w - xv.w; pe += d*d; nov += xv.w*xv.w; sp += fabsf(ov.w);
        float nx = nvr.x*0.01f, ny = nvr.y*0.01f, nz = nvr.z*0.01f, nw = nvr.w*0.01f;
        pl += nx*nx + ny*ny + nz*nz + nw*nw;
    }
    pe = warp_sum(pe); nov = warp_sum(nov); sp = warp_sum(sp); pl = warp_sum(pl);
    if (lane == 0) {
        const float inv = 1.f / (float)H_SZ;
        g_pe[warp] = pe * inv; g_nov[warp] = nov * inv;
        g_sp[warp] = sp * inv; g_pl[warp]  = pl * inv;
    }
}

// ---------------- finalize (one block per t) ----------------
__device__ __forceinline__ float block_sum(float v, float* red, int tid) {
    red[tid] = v; __syncthreads();
    for (int s = 128; s > 0; s >>= 1) { if (tid < s) red[tid] += red[tid + s]; __syncthreads(); }
    float r = red[0]; __syncthreads();
    return r;
}

__global__ void finalize_kernel(const float* __restrict__ id_emb, const float* __restrict__ rW1,
                                const float* __restrict__ gW1, const float* __restrict__ gb1,
                                const float* __restrict__ gW2, const float* __restrict__ gb2,
                                float* __restrict__ decision)
{
    __shared__ float red[256];
    __shared__ float sig[7];
    __shared__ float gch[H_SZ];
    const int t = blockIdx.x, tid = threadIdx.x;

    float pe = 0.f, pe2 = 0.f, nov = 0.f, sp = 0.f, pl = 0.f;
    for (int g = tid; g < G_SZ; g += 256) {
        int b = g * T_SZ + t;
        float p = g_pe[b];
        pe += p; pe2 += p * p; nov += g_nov[b]; sp += g_sp[b]; pl += g_pl[b];
    }
    float S_pe  = block_sum(pe,  red, tid);
    float S_pe2 = block_sum(pe2, red, tid);
    float S_nov = block_sum(nov, red, tid);
    float S_sp  = block_sum(sp,  red, tid);
    float S_pl  = block_sum(pl,  red, tid);

    if (tid == 0) {
        const float invg = 1.f / (float)G_SZ;
        float pe_m = S_pe * invg, pe2_m = S_pe2 * invg;
        float c = 0.01f * pe_m;
        sig[0] = S_pl * invg;
        sig[1] = S_nov * invg;
        sig[2] = pe_m;
        sig[3] = g_ent[t];
        sig[4] = S_sp * invg;
        sig[5] = -pe_m;
        sig[6] = pe2_m - 2.f * c * pe_m + c * c;
    }
    __syncthreads();

    for (int i = tid; i < H_SZ; i += 256) {
        float a = gb1[t * H_SZ + i];
#pragma unroll
        for (int j = 0; j < 7; j++) a += gW1[((long)(t * H_SZ + i)) * 7 + j] * sig[j];
        gch[i] = fmaxf(a, 0.f);
    }
    __syncthreads();

    for (int o = 0; o < 2; o++) {
        float d = 0.f;
        for (int i = tid; i < H_SZ; i += 256) d += gW2[((long)(t * 2 + o)) * H_SZ + i] * gch[i];
        float S = block_sum(d, red, tid);
        if (tid == 0) decision[t * 2 + o] = S + gb2[t * 2 + o];
    }

    __shared__ float ext[7];
    if (tid == 0) {
        ext[0] = id_emb[t*4+0]; ext[1] = id_emb[t*4+1];
        ext[2] = id_emb[t*4+2]; ext[3] = id_emb[t*4+3];
        ext[4] = sig[1];
        ext[5] = g_conf[t];
        ext[6] = sig[2];
    }
    __syncthreads();
    for (int i = tid; i < H_SZ; i += 256) {
        float a = 0.f;
#pragma unroll
        for (int j = 0; j < 7; j++) a += ext[j] * rW1[(long)i * (H_SZ + 7) + H_SZ + j];
        g_extra[t * H_SZ + i] = a;
    }
}

// ---------------- logits ----------------
__global__ void logits_kernel(const float* __restrict__ rW2, const float* __restrict__ rb2,
                              float* __restrict__ logits)
{
    const int b = blockIdx.x;
    const int o = threadIdx.x >> 5, lane = threadIdx.x & 31;
    const float4* r = (const float4*)(g_rh + (long)b * H_SZ);
    const float4* wrow = (const float4*)(rW2 + (long)o * H_SZ);
    float acc = 0.f;
    for (int i = lane; i < H_SZ/4; i += 32) {
        float4 rv = r[i], wv = wrow[i];
        acc += rv.x*wv.x + rv.y*wv.y + rv.z*wv.z + rv.w*wv.w;
    }
    acc = warp_sum(acc);
    if (lane == 0) logits[(long)b * (T_SZ + 1) + o] = acc + rb2[o];
}

// ---------------- launch ----------------
extern "C" void kernel_launch(void* const* d_in, const int* in_sizes, int n_in,
                              void* d_out, int out_size)
{
    const float* x         = (const float*)d_in[0];
    const float* Wp        = (const float*)d_in[1];
    const float* bp        = (const float*)d_in[2];
    const float* opW1      = (const float*)d_in[3];
    const float* opb1      = (const float*)d_in[4];
    const float* opW2      = (const float*)d_in[5];
    const float* opb2      = (const float*)d_in[6];
    const float* op_logits = (const float*)d_in[7];
    const float* id_emb    = (const float*)d_in[8];
    const float* rW1       = (const float*)d_in[9];
    const float* rb1       = (const float*)d_in[10];
    const float* rW2       = (const float*)d_in[11];
    const float* rb2       = (const float*)d_in[12];
    const float* gW1       = (const float*)d_in[13];
    const float* gb1       = (const float*)d_in[14];
    const float* gW2       = (const float*)d_in[15];
    const float* gb2       = (const float*)d_in[16];
    const float* phW       = (const float*)d_in[17];
    const float* phb       = (const float*)d_in[18];
    const float* noise     = (const float*)d_in[19];

    float* out_full = (float*)d_out;
    float* logits   = out_full + (size_t)B_SZ * H_SZ;
    float* pred     = logits   + (size_t)B_SZ * (T_SZ + 1);
    float* decision = pred     + (size_t)B_SZ * D_SZ;

    float *xp, *h2, *extra, *rh;
    h16 *x_hi, *x_lo, *xp_hi, *xp_lo, *h1_hi, *h1_lo, *out_hi, *out_lo;
    h16 *Wp_h, *oW1_h, *oW2_h, *rW1c_h, *phW_h;
    cudaGetSymbolAddress((void**)&xp,      g_xp);
    cudaGetSymbolAddress((void**)&h2,      g_h2);
    cudaGetSymbolAddress((void**)&extra,   g_extra);
    cudaGetSymbolAddress((void**)&rh,      g_rh);
    cudaGetSymbolAddress((void**)&x_hi,    g_x_hi);    cudaGetSymbolAddress((void**)&x_lo,    g_x_lo);
    cudaGetSymbolAddress((void**)&xp_hi,   g_xp_hi);   cudaGetSymbolAddress((void**)&xp_lo,   g_xp_lo);
    cudaGetSymbolAddress((void**)&h1_hi,   g_h1_hi);   cudaGetSymbolAddress((void**)&h1_lo,   g_h1_lo);
    cudaGetSymbolAddress((void**)&out_hi,  g_out_hi);  cudaGetSymbolAddress((void**)&out_lo,  g_out_lo);
    cudaGetSymbolAddress((void**)&Wp_h,    g_Wp_h);
    cudaGetSymbolAddress((void**)&oW1_h,   g_oW1_h);
    cudaGetSymbolAddress((void**)&oW2_h,   g_oW2_h);
    cudaGetSymbolAddress((void**)&rW1c_h,  g_rW1c_h);
    cudaGetSymbolAddress((void**)&phW_h,   g_phW_h);

    cudaFuncSetAttribute(gemm2, cudaFuncAttributeMaxDynamicSharedMemorySize, 2 * (int)STAGE_BYTES);
    const int SM = 2 * (int)STAGE_BYTES;

    // 0) conversions: A-side split pairs, B-side single fp16
    {
        long n4;
        n4 = (long)B_SZ * D_SZ / 4;           convert_split<<<(int)((n4 + 255) / 256), 256>>>(x,    x_hi,  x_lo,  n4);
        n4 = (long)H_SZ * D_SZ / 4;           convert_h<<<(int)((n4 + 255) / 256), 256>>>(Wp,   Wp_h,  n4);
        n4 = (long)T_SZ*K_SZ*H_SZ*H_SZ / 4;   convert_h<<<(int)((n4 + 255) / 256), 256>>>(opW1, oW1_h, n4);
        n4 = (long)T_SZ*K_SZ*H_SZ*H_SZ / 4;   convert_h<<<(int)((n4 + 255) / 256), 256>>>(opW2, oW2_h, n4);
        n4 = (long)D_SZ * H_SZ / 4;           convert_h<<<(int)((n4 + 255) / 256), 256>>>(phW,  phW_h, n4);
        rw1_extract<<<(H_SZ * H_SZ) / 256, 256>>>(rW1, rW1c_h);
    }

    // 1) xp = x @ Wp^T + bp          (fp32 + hi/lo out)
    gemm2<<<dim3(H_SZ/GBN, B_SZ/GBM, 1), 256, SM>>>(
        x_hi, x_lo, D_SZ, 0, 0, 1,
        Wp_h, D_SZ, 0,
        bp, 0, nullptr,
        xp, xp_hi, xp_lo, H_SZ, 0, 0, H_SZ, D_SZ, 0);

    // 2) softmax / conflict / entropy
    softmax_stats<<<1, 32>>>(op_logits);

    // 3) h1[t,k] = relu(xg[t] @ opW1[t,k]^T + opb1)   (A scattered; hi/lo out only)
    gemm2<<<dim3(H_SZ/GBN, G_SZ/GBM, T_SZ*K_SZ), 256, SM>>>(
        xp_hi, xp_lo, H_SZ, 0, T_SZ, K_SZ,
        oW1_h, H_SZ, (long)H_SZ*H_SZ,
        opb1, H_SZ, nullptr,
        nullptr, h1_hi, h1_lo, H_SZ, (long)G_SZ*H_SZ, 0, H_SZ, H_SZ, 1);

    // 4) h2[t,k] = relu(h1[t,k] @ opW2[t,k]^T + opb2)   (fp32 out only)
    gemm2<<<dim3(H_SZ/GBN, G_SZ/GBM, T_SZ*K_SZ), 256, SM>>>(
        h1_hi, h1_lo, H_SZ, (long)G_SZ*H_SZ, 0, 1,
        oW2_h, H_SZ, (long)H_SZ*H_SZ,
        opb2, H_SZ, nullptr,
        h2, nullptr, nullptr, H_SZ, (long)G_SZ*H_SZ, 0, H_SZ, H_SZ, 1);

    // 5) out_full (scattered) = sum_k w[t,k] * h2[t,k]   (+ hi/lo emit)
    wsum_kernel<<<(T_SZ*G_SZ*H_SZ/4)/256, 256>>>(out_full);

    // 6) per-row stats
    row_stats<<<(B_SZ*32)/256, 256>>>(out_full, noise);

    // 7) signals, decision, routing extra bias
    finalize_kernel<<<T_SZ, 256>>>(id_emb, rW1, gW1, gb1, gW2, gb2, decision);

    // 8) rh = relu(out @ rW1[:, :H]^T + c_extra[t] + rb1)   (A & C rows scattered)
    gemm2<<<dim3(H_SZ/GBN, G_SZ/GBM, T_SZ), 256, SM>>>(
        out_hi, out_lo, H_SZ, 0, T_SZ, 1,
        rW1c_h, H_SZ, 0,
        rb1, 0, extra,
        rh, nullptr, nullptr, H_SZ, 0, T_SZ, H_SZ, H_SZ, 1);

    // 9) logits = rh @ rW2^T + rb2
    logits_kernel<<<B_SZ, (T_SZ + 1) * 32>>>(rW2, rb2, logits);

    // 10) pred = out_full @ phW^T + phb
    gemm2<<<dim3(D_SZ/GBN, B_SZ/GBM, 1), 256, SM>>>(
        out_hi, out_lo, H_SZ, 0, 0, 1,
        phW_h, H_SZ, 0,
        phb, 0, nullptr,
        pred, nullptr, nullptr, D_SZ, 0, 0, D_SZ, H_SZ, 0);
}

// round 13
// speedup vs baseline: 3.4721x; 1.1225x over previous
#include <cuda_runtime.h>
#include <cuda_fp16.h>
#include <stdint.h>
#include <math.h>

typedef __half h16;

#define B_SZ 12288
#define D_SZ 1024
#define H_SZ 512
#define T_SZ 12
#define K_SZ 3
#define G_SZ 1024   // B_SZ / T_SZ

// ---------------- fp32 scratch ----------------
__device__ float g_xp[(size_t)B_SZ * H_SZ];
__device__ float g_h2[(size_t)T_SZ * K_SZ * G_SZ * H_SZ];
__device__ float g_rh[(size_t)B_SZ * H_SZ];
__device__ float g_w[T_SZ * K_SZ];
__device__ float g_conf[T_SZ];
__device__ float g_ent[T_SZ];
__device__ float g_pe[B_SZ];
__device__ float g_nov[B_SZ];
__device__ float g_sp[B_SZ];
__device__ float g_pl[B_SZ];
__device__ float g_extra[T_SZ * H_SZ];

// ---------------- fp16 scratch: A-side hi/lo pairs, B-side single ----------------
__device__ __align__(16) h16 g_x_hi[(size_t)B_SZ * D_SZ];
__device__ __align__(16) h16 g_x_lo[(size_t)B_SZ * D_SZ];
__device__ __align__(16) h16 g_xp_hi[(size_t)B_SZ * H_SZ];
__device__ __align__(16) h16 g_xp_lo[(size_t)B_SZ * H_SZ];
__device__ __align__(16) h16 g_h1_hi[(size_t)T_SZ * K_SZ * G_SZ * H_SZ];
__device__ __align__(16) h16 g_h1_lo[(size_t)T_SZ * K_SZ * G_SZ * H_SZ];
__device__ __align__(16) h16 g_out_hi[(size_t)B_SZ * H_SZ];
__device__ __align__(16) h16 g_out_lo[(size_t)B_SZ * H_SZ];
__device__ __align__(16) h16 g_Wp_h[(size_t)H_SZ * D_SZ];
__device__ __align__(16) h16 g_oW1_h[(size_t)T_SZ * K_SZ * H_SZ * H_SZ];
__device__ __align__(16) h16 g_oW2_h[(size_t)T_SZ * K_SZ * H_SZ * H_SZ];
__device__ __align__(16) h16 g_rW1c_h[(size_t)H_SZ * H_SZ];
__device__ __align__(16) h16 g_phW_h[(size_t)D_SZ * H_SZ];

// ---------------- helpers ----------------
__device__ __forceinline__ void split2h(float v, h16& h, h16& l) {
    h = __float2half_rn(v);
    l = __float2half_rn(v - __half2float(h));
}

__device__ __forceinline__ void mma16816(float* c, const unsigned* a, const unsigned* b) {
    asm volatile(
        "mma.sync.aligned.m16n8k16.row.col.f32.f16.f16.f32 "
        "{%0,%1,%2,%3},{%4,%5,%6,%7},{%8,%9},{%0,%1,%2,%3};"
        : "+f"(c[0]), "+f"(c[1]), "+f"(c[2]), "+f"(c[3])
        : "r"(a[0]), "r"(a[1]), "r"(a[2]), "r"(a[3]), "r"(b[0]), "r"(b[1]));
}

#define LDMX4(R_, ADDR_)                                                      \
    asm volatile("ldmatrix.sync.aligned.m8n8.x4.shared.b16 {%0,%1,%2,%3},[%4];" \
                 : "=r"((R_)[0]), "=r"((R_)[1]), "=r"((R_)[2]), "=r"((R_)[3]) \
                 : "r"(ADDR_))

#define LDMX2(R_, ADDR_)                                                      \
    asm volatile("ldmatrix.sync.aligned.m8n8.x2.shared.b16 {%0,%1},[%2];"     \
                 : "=r"((R_)[0]), "=r"((R_)[1]) : "r"(ADDR_))

#define CPA(DST_, SRC_)                                                       \
    asm volatile("cp.async.cg.shared.global [%0],[%1],16;" :: "r"(DST_), "l"(SRC_))

#define CP_COMMIT asm volatile("cp.async.commit_group;")
#define CP_WAIT1  asm volatile("cp.async.wait_group 1;")
#define CP_WAIT0  asm volatile("cp.async.wait_group 0;")

// ---------------- fp16 2-product tensor-core GEMM: C = A @ B^T (+bias)(+extra)(relu) ----
// A_hi/lo [M, lda] fp16 row-major (k contig) — exact split pair.
// B [N, ldb] single fp16 row-major (k contig).
// a_scatter/c_scatter: logical row r -> global row r*scatter + tcur, tcur = z / t_div.
// BM=BN=128, BK=32, 256 threads (8 warps 2x4, warp tile 64x32).
// 3-stage cp.async pipeline; smem 3*30720 = 92160 B per CTA, 2 CTAs/SM.
#define GBM 128
#define GBN 128
#define GBK 32
#define SROW 40
#define STAGE_BYTES 30720u
#define NSTAGE 3

#define LOAD_STAGE(S_, KB_) do {                                              \
    uint32_t base_ = smem_u32 + (uint32_t)(S_) * STAGE_BYTES;                 \
    CPA(base_ +      0u + sOff0, pAh0 + (KB_));                               \
    CPA(base_ +      0u + sOff1, pAh1 + (KB_));                               \
    CPA(base_ + 10240u + sOff0, pAl0 + (KB_));                                \
    CPA(base_ + 10240u + sOff1, pAl1 + (KB_));                                \
    CPA(base_ + 20480u + sOff0, pB0 + (KB_));                                 \
    CPA(base_ + 20480u + sOff1, pB1 + (KB_));                                 \
} while (0)

__global__ __launch_bounds__(256, 2)
void gemm2(const h16* __restrict__ Ah, const h16* __restrict__ Al,
           int lda, long a_bstride, int a_scatter, int t_div,
           const h16* __restrict__ Bm,
           int ldb, long b_bstride,
           const float* __restrict__ bias, long bias_bstride,
           const float* __restrict__ extra,
           float* __restrict__ C, h16* __restrict__ Chi, h16* __restrict__ Clo,
           int ldc, long c_bstride, int c_scatter,
           int N, int Kdim, int do_relu)
{
    extern __shared__ __align__(16) char smem_raw[];
    uint32_t smem_u32 = (uint32_t)__cvta_generic_to_shared(smem_raw);

    const int tid  = threadIdx.x;
    const int z    = blockIdx.z;
    const int tcur = z / t_div;
    const int brow = blockIdx.y * GBM;
    const int bcol = blockIdx.x * GBN;

    // ---- loader setup: 512 (row,chunk) slots, 2 per thread ----
    const int id0 = tid * 2, id1 = id0 + 1;
    const int r0 = id0 >> 2, ch0 = (id0 & 3) * 8;
    const int r1 = id1 >> 2, ch1 = (id1 & 3) * 8;

    long arow0 = brow + r0, arow1 = brow + r1;
    if (a_scatter) { arow0 = arow0 * a_scatter + tcur; arow1 = arow1 * a_scatter + tcur; }
    const h16* pAh0 = Ah + z * a_bstride + arow0 * (long)lda + ch0;
    const h16* pAh1 = Ah + z * a_bstride + arow1 * (long)lda + ch1;
    const h16* pAl0 = Al + z * a_bstride + arow0 * (long)lda + ch0;
    const h16* pAl1 = Al + z * a_bstride + arow1 * (long)lda + ch1;
    const h16* pB0  = Bm + z * b_bstride + (long)(bcol + r0) * ldb + ch0;
    const h16* pB1  = Bm + z * b_bstride + (long)(bcol + r1) * ldb + ch1;
    const uint32_t sOff0 = (uint32_t)(r0 * SROW + ch0) * 2u;
    const uint32_t sOff1 = (uint32_t)(r1 * SROW + ch1) * 2u;

    // ---- fragment-load setup ----
    const int lane = tid & 31;
    const int warp = tid >> 5;
    const int wm = (warp & 1) * 64;
    const int wn = (warp >> 1) * 32;
    const int aMat = lane >> 3, aR = lane & 7;
    const uint32_t aOff = (uint32_t)((wm + (aMat & 1) * 8 + aR) * SROW + (aMat >> 1) * 8) * 2u;
    const int bL = lane & 15;
    const uint32_t bOff = (uint32_t)((wn + (bL & 7)) * SROW + ((bL >> 3) & 1) * 8) * 2u;

    float acc[4][4][4];
#pragma unroll
    for (int i = 0; i < 4; i++)
#pragma unroll
        for (int j = 0; j < 4; j++)
#pragma unroll
            for (int q = 0; q < 4; q++) acc[i][j][q] = 0.f;

    const int nIter = Kdim / GBK;   // >= 16 for all our shapes
    LOAD_STAGE(0, 0);
    CP_COMMIT;
    LOAD_STAGE(1, GBK);
    CP_COMMIT;

    int sc = 0;                      // stage index = it % 3, tracked incrementally
    for (int it = 0; it < nIter; ++it) {
        if (it < nIter - 1) { CP_WAIT1; } else { CP_WAIT0; }
        __syncthreads();

        const uint32_t baseA_hi = smem_u32 + (uint32_t)sc * STAGE_BYTES;
        const uint32_t baseA_lo = baseA_hi + 10240u;
        const uint32_t baseB    = baseA_hi + 20480u;

#pragma unroll
        for (int kk = 0; kk < 2; kk++) {
            const uint32_t kkb = (uint32_t)kk * 32u;
            unsigned bh[4][2];
#pragma unroll
            for (int j = 0; j < 4; j++)
                LDMX2(bh[j], baseB + bOff + (uint32_t)j * 640u + kkb);
#pragma unroll
            for (int i = 0; i < 4; i++) {
                unsigned ah[4], al[4];
                LDMX4(ah, baseA_hi + aOff + (uint32_t)i * 1280u + kkb);
                LDMX4(al, baseA_lo + aOff + (uint32_t)i * 1280u + kkb);
#pragma unroll
                for (int j = 0; j < 4; j++) {
                    mma16816(acc[i][j], ah, bh[j]);
                    mma16816(acc[i][j], al, bh[j]);
                }
            }
        }

        if (it + 2 < nIter) {
            int sn = sc + 2; if (sn >= NSTAGE) sn -= NSTAGE;
            LOAD_STAGE(sn, (long)(it + 2) * GBK);
            CP_COMMIT;
        }
        if (++sc == NSTAGE) sc = 0;
    }

    // ---- epilogue ----
    const float* biasb = bias ? bias + (long)z * bias_bstride : nullptr;
    const int g4 = lane >> 2, t4 = lane & 3;
#pragma unroll
    for (int i = 0; i < 4; i++) {
#pragma unroll
        for (int half_ = 0; half_ < 2; half_++) {
            int m_local = wm + i * 16 + g4 + half_ * 8;
            long crow = brow + m_local;
            if (c_scatter) crow = crow * c_scatter + tcur;
            long rbase = (long)z * c_bstride + crow * (long)ldc;
#pragma unroll
            for (int j = 0; j < 4; j++) {
                int n_local = wn + j * 8 + t4 * 2;
                int n = bcol + n_local;
                float v0 = acc[i][j][half_ * 2 + 0];
                float v1 = acc[i][j][half_ * 2 + 1];
                if (biasb) { v0 += biasb[n]; v1 += biasb[n + 1]; }
                if (extra) { v0 += extra[tcur * N + n]; v1 += extra[tcur * N + n + 1]; }
                if (do_relu) { v0 = fmaxf(v0, 0.f); v1 = fmaxf(v1, 0.f); }
                if (C) {
                    float2 f2; f2.x = v0; f2.y = v1;
                    *(float2*)(C + rbase + n) = f2;
                }
                if (Chi) {
                    h16 h0, l0, h1, l1;
                    split2h(v0, h0, l0); split2h(v1, h1, l1);
                    __half2 ph; ph.x = h0; ph.y = h1;
                    __half2 pl; pl.x = l0; pl.y = l1;
                    *(__half2*)(Chi + rbase + n) = ph;
                    *(__half2*)(Clo + rbase + n) = pl;
                }
            }
        }
    }
}

// ---------------- fp32 -> fp16 hi/lo split (A-side) ----------------
__global__ void convert_split(const float* __restrict__ in, h16* __restrict__ hi,
                              h16* __restrict__ lo, long n4)
{
    long i = blockIdx.x * (long)blockDim.x + threadIdx.x;
    if (i >= n4) return;
    float4 v = ((const float4*)in)[i];
    h16 h0, h1, h2, h3, l0, l1, l2, l3;
    split2h(v.x, h0, l0); split2h(v.y, h1, l1); split2h(v.z, h2, l2); split2h(v.w, h3, l3);
    __half2 a, b;
    a.x = h0; a.y = h1; b.x = h2; b.y = h3;
    ((__half2*)hi)[i * 2] = a; ((__half2*)hi)[i * 2 + 1] = b;
    a.x = l0; a.y = l1; b.x = l2; b.y = l3;
    ((__half2*)lo)[i * 2] = a; ((__half2*)lo)[i * 2 + 1] = b;
}

// ---------------- fp32 -> fp16 single (B-side weights) ----------------
__global__ void convert_h(const float* __restrict__ in, h16* __restrict__ out, long n4)
{
    long i = blockIdx.x * (long)blockDim.x + threadIdx.x;
    if (i >= n4) return;
    float4 v = ((const float4*)in)[i];
    __half2 a, b;
    a.x = __float2half_rn(v.x); a.y = __float2half_rn(v.y);
    b.x = __float2half_rn(v.z); b.y = __float2half_rn(v.w);
    ((__half2*)out)[i * 2] = a; ((__half2*)out)[i * 2 + 1] = b;
}

// extract first H columns of rW1 [H, H+7] as fp16
__global__ void rw1_extract(const float* __restrict__ rW1, h16* __restrict__ out)
{
    int idx = blockIdx.x * 256 + threadIdx.x;   // H*H
    int i = idx >> 9, j = idx & 511;
    out[idx] = __float2half_rn(rW1[(long)i * (H_SZ + 7) + j]);
}

// ---------------- softmax over op_logits + conflict/entropy ----------------
__global__ void softmax_stats(const float* __restrict__ op_logits)
{
    int t = threadIdx.x;
    if (t < T_SZ) {
        float l0 = op_logits[t*K_SZ+0], l1 = op_logits[t*K_SZ+1], l2 = op_logits[t*K_SZ+2];
        float m = fmaxf(l0, fmaxf(l1, l2));
        float e0 = expf(l0 - m), e1 = expf(l1 - m), e2 = expf(l2 - m);
        float s = e0 + e1 + e2;
        float w0 = e0 / s, w1 = e1 / s, w2 = e2 / s;
        g_w[t*K_SZ+0] = w0; g_w[t*K_SZ+1] = w1; g_w[t*K_SZ+2] = w2;
        float mean = (w0 + w1 + w2) * (1.f / 3.f);
        float d0 = w0 - mean, d1 = w1 - mean, d2 = w2 - mean;
        g_conf[t] = sqrtf((d0*d0 + d1*d1 + d2*d2) * 0.5f);
        float sum = w0 + w1 + w2;
        float inv = 1.f / (sum + 1e-6f);
        float u0 = w0*inv, u1 = w1*inv, u2 = w2*inv;
        float ent = -(u0*logf(fmaxf(u0,1e-6f)) + u1*logf(fmaxf(u1,1e-6f)) + u2*logf(fmaxf(u2,1e-6f)));
        g_ent[t] = ent;
    }
}

// ---------------- weighted op mixture + hi/lo emit ----------------
__global__ void wsum_kernel(float* __restrict__ out_full)
{
    long idx4 = (long)blockIdx.x * blockDim.x + threadIdx.x;
    int i4 = (int)(idx4 % (H_SZ / 4));
    long r = idx4 / (H_SZ / 4);
    int g = (int)(r % G_SZ);
    int t = (int)(r / G_SZ);
    float w0 = g_w[t*K_SZ+0], w1 = g_w[t*K_SZ+1], w2 = g_w[t*K_SZ+2];
    const float4* p0 = (const float4*)&g_h2[(((long)(t*K_SZ+0))*G_SZ + g)*H_SZ];
    const float4* p1 = (const float4*)&g_h2[(((long)(t*K_SZ+1))*G_SZ + g)*H_SZ];
    const float4* p2 = (const float4*)&g_h2[(((long)(t*K_SZ+2))*G_SZ + g)*H_SZ];
    float4 v0 = p0[i4], v1 = p1[i4], v2 = p2[i4];
    float4 o;
    o.x = w0*v0.x + w1*v1.x + w2*v2.x;
    o.y = w0*v0.y + w1*v1.y + w2*v2.y;
    o.z = w0*v0.z + w1*v1.z + w2*v2.z;
    o.w = w0*v0.w + w1*v1.w + w2*v2.w;
    long rowbase = ((long)(g*T_SZ + t))*H_SZ;
    ((float4*)&out_full[rowbase])[i4] = o;
    h16 h0,h1,h2v,h3,l0,l1,l2v,l3;
    split2h(o.x,h0,l0); split2h(o.y,h1,l1); split2h(o.z,h2v,l2v); split2h(o.w,h3,l3);
    __half2 a,b;
    a.x=h0; a.y=h1; b.x=h2v; b.y=h3;
    ((__half2*)&g_out_hi[rowbase])[i4*2] = a;
    ((__half2*)&g_out_hi[rowbase])[i4*2+1] = b;
    a.x=l0; a.y=l1; b.x=l2v; b.y=l3;
    ((__half2*)&g_out_lo[rowbase])[i4*2] = a;
    ((__half2*)&g_out_lo[rowbase])[i4*2+1] = b;
}

// ---------------- per-row stats (one warp per row b) ----------------
__device__ __forceinline__ float warp_sum(float v) {
#pragma unroll
    for (int o = 16; o > 0; o >>= 1) v += __shfl_down_sync(0xffffffffu, v, o);
    return v;
}

__global__ void row_stats(const float* __restrict__ out_full, const float* __restrict__ noise)
{
    int warp = (int)((blockIdx.x * (long)blockDim.x + threadIdx.x) >> 5);
    int lane = threadIdx.x & 31;
    if (warp >= B_SZ) return;
    const float4* o  = (const float4*)(out_full + (long)warp * H_SZ);
    const float4* xr = (const float4*)(g_xp     + (long)warp * H_SZ);
    const float4* nr = (const float4*)(noise    + (long)warp * H_SZ);
    float pe = 0.f, nov = 0.f, sp = 0.f, pl = 0.f;
#pragma unroll
    for (int i = lane; i < H_SZ/4; i += 32) {
        float4 ov = o[i], xv = xr[i], nvr = nr[i];
        float d;
        d = ov.x - xv.x; pe += d*d; nov += xv.x*xv.x; sp += fabsf(ov.x);
        d = ov.y - xv.y; pe += d*d; nov += xv.y*xv.y; sp += fabsf(ov.y);
        d = ov.z - xv.z; pe += d*d; nov += xv.z*xv.z; sp += fabsf(ov.z);
        d = ov.w - xv.w; pe += d*d; nov += xv.w*xv.w; sp += fabsf(ov.w);
        float nx = nvr.x*0.01f, ny = nvr.y*0.01f, nz = nvr.z*0.01f, nw = nvr.w*0.01f;
        pl += nx*nx + ny*ny + nz*nz + nw*nw;
    }
    pe = warp_sum(pe); nov = warp_sum(nov); sp = warp_sum(sp); pl = warp_sum(pl);
    if (lane == 0) {
        const float inv = 1.f / (float)H_SZ;
        g_pe[warp] = pe * inv; g_nov[warp] = nov * inv;
        g_sp[warp] = sp * inv; g_pl[warp]  = pl * inv;
    }
}

// ---------------- finalize (one block per t) ----------------
__device__ __forceinline__ float block_sum(float v, float* red, int tid) {
    red[tid] = v; __syncthreads();
    for (int s = 128; s > 0; s >>= 1) { if (tid < s) red[tid] += red[tid + s]; __syncthreads(); }
    float r = red[0]; __syncthreads();
    return r;
}

__global__ void finalize_kernel(const float* __restrict__ id_emb, const float* __restrict__ rW1,
                                const float* __restrict__ gW1, const float* __restrict__ gb1,
                                const float* __restrict__ gW2, const float* __restrict__ gb2,
                                float* __restrict__ decision)
{
    __shared__ float red[256];
    __shared__ float sig[7];
    __shared__ float gch[H_SZ];
    const int t = blockIdx.x, tid = threadIdx.x;

    float pe = 0.f, pe2 = 0.f, nov = 0.f, sp = 0.f, pl = 0.f;
    for (int g = tid; g < G_SZ; g += 256) {
        int b = g * T_SZ + t;
        float p = g_pe[b];
        pe += p; pe2 += p * p; nov += g_nov[b]; sp += g_sp[b]; pl += g_pl[b];
    }
    float S_pe  = block_sum(pe,  red, tid);
    float S_pe2 = block_sum(pe2, red, tid);
    float S_nov = block_sum(nov, red, tid);
    float S_sp  = block_sum(sp,  red, tid);
    float S_pl  = block_sum(pl,  red, tid);

    if (tid == 0) {
        const float invg = 1.f / (float)G_SZ;
        float pe_m = S_pe * invg, pe2_m = S_pe2 * invg;
        float c = 0.01f * pe_m;
        sig[0] = S_pl * invg;
        sig[1] = S_nov * invg;
        sig[2] = pe_m;
        sig[3] = g_ent[t];
        sig[4] = S_sp * invg;
        sig[5] = -pe_m;
        sig[6] = pe2_m - 2.f * c * pe_m + c * c;
    }
    __syncthreads();

    for (int i = tid; i < H_SZ; i += 256) {
        float a = gb1[t * H_SZ + i];
#pragma unroll
        for (int j = 0; j < 7; j++) a += gW1[((long)(t * H_SZ + i)) * 7 + j] * sig[j];
        gch[i] = fmaxf(a, 0.f);
    }
    __syncthreads();

    for (int o = 0; o < 2; o++) {
        float d = 0.f;
        for (int i = tid; i < H_SZ; i += 256) d += gW2[((long)(t * 2 + o)) * H_SZ + i] * gch[i];
        float S = block_sum(d, red, tid);
        if (tid == 0) decision[t * 2 + o] = S + gb2[t * 2 + o];
    }

    __shared__ float ext[7];
    if (tid == 0) {
        ext[0] = id_emb[t*4+0]; ext[1] = id_emb[t*4+1];
        ext[2] = id_emb[t*4+2]; ext[3] = id_emb[t*4+3];
        ext[4] = sig[1];
        ext[5] = g_conf[t];
        ext[6] = sig[2];
    }
    __syncthreads();
    for (int i = tid; i < H_SZ; i += 256) {
        float a = 0.f;
#pragma unroll
        for (int j = 0; j < 7; j++) a += ext[j] * rW1[(long)i * (H_SZ + 7) + H_SZ + j];
        g_extra[t * H_SZ + i] = a;
    }
}

// ---------------- logits ----------------
__global__ void logits_kernel(const float* __restrict__ rW2, const float* __restrict__ rb2,
                              float* __restrict__ logits)
{
    const int b = blockIdx.x;
    const int o = threadIdx.x >> 5, lane = threadIdx.x & 31;
    const float4* r = (const float4*)(g_rh + (long)b * H_SZ);
    const float4* wrow = (const float4*)(rW2 + (long)o * H_SZ);
    float acc = 0.f;
    for (int i = lane; i < H_SZ/4; i += 32) {
        float4 rv = r[i], wv = wrow[i];
        acc += rv.x*wv.x + rv.y*wv.y + rv.z*wv.z + rv.w*wv.w;
    }
    acc = warp_sum(acc);
    if (lane == 0) logits[(long)b * (T_SZ + 1) + o] = acc + rb2[o];
}

// ---------------- launch ----------------
extern "C" void kernel_launch(void* const* d_in, const int* in_sizes, int n_in,
                              void* d_out, int out_size)
{
    const float* x         = (const float*)d_in[0];
    const float* Wp        = (const float*)d_in[1];
    const float* bp        = (const float*)d_in[2];
    const float* opW1      = (const float*)d_in[3];
    const float* opb1      = (const float*)d_in[4];
    const float* opW2      = (const float*)d_in[5];
    const float* opb2      = (const float*)d_in[6];
    const float* op_logits = (const float*)d_in[7];
    const float* id_emb    = (const float*)d_in[8];
    const float* rW1       = (const float*)d_in[9];
    const float* rb1       = (const float*)d_in[10];
    const float* rW2       = (const float*)d_in[11];
    const float* rb2       = (const float*)d_in[12];
    const float* gW1       = (const float*)d_in[13];
    const float* gb1       = (const float*)d_in[14];
    const float* gW2       = (const float*)d_in[15];
    const float* gb2       = (const float*)d_in[16];
    const float* phW       = (const float*)d_in[17];
    const float* phb       = (const float*)d_in[18];
    const float* noise     = (const float*)d_in[19];

    float* out_full = (float*)d_out;
    float* logits   = out_full + (size_t)B_SZ * H_SZ;
    float* pred     = logits   + (size_t)B_SZ * (T_SZ + 1);
    float* decision = pred     + (size_t)B_SZ * D_SZ;

    float *xp, *h2, *extra, *rh;
    h16 *x_hi, *x_lo, *xp_hi, *xp_lo, *h1_hi, *h1_lo, *out_hi, *out_lo;
    h16 *Wp_h, *oW1_h, *oW2_h, *rW1c_h, *phW_h;
    cudaGetSymbolAddress((void**)&xp,      g_xp);
    cudaGetSymbolAddress((void**)&h2,      g_h2);
    cudaGetSymbolAddress((void**)&extra,   g_extra);
    cudaGetSymbolAddress((void**)&rh,      g_rh);
    cudaGetSymbolAddress((void**)&x_hi,    g_x_hi);    cudaGetSymbolAddress((void**)&x_lo,    g_x_lo);
    cudaGetSymbolAddress((void**)&xp_hi,   g_xp_hi);   cudaGetSymbolAddress((void**)&xp_lo,   g_xp_lo);
    cudaGetSymbolAddress((void**)&h1_hi,   g_h1_hi);   cudaGetSymbolAddress((void**)&h1_lo,   g_h1_lo);
    cudaGetSymbolAddress((void**)&out_hi,  g_out_hi);  cudaGetSymbolAddress((void**)&out_lo,  g_out_lo);
    cudaGetSymbolAddress((void**)&Wp_h,    g_Wp_h);
    cudaGetSymbolAddress((void**)&oW1_h,   g_oW1_h);
    cudaGetSymbolAddress((void**)&oW2_h,   g_oW2_h);
    cudaGetSymbolAddress((void**)&rW1c_h,  g_rW1c_h);
    cudaGetSymbolAddress((void**)&phW_h,   g_phW_h);

    cudaFuncSetAttribute(gemm2, cudaFuncAttributeMaxDynamicSharedMemorySize,
                         NSTAGE * (int)STAGE_BYTES);
    const int SM = NSTAGE * (int)STAGE_BYTES;

    // Launch order arranged so that launches #5/#6 are gemm2 (step 1 / step 3)
    // to land inside the profiler's -s 5 -c 1 capture window.

    // (1) x -> hi/lo split
    {
        long n4 = (long)B_SZ * D_SZ / 4;
        convert_split<<<(int)((n4 + 255) / 256), 256>>>(x, x_hi, x_lo, n4);
    }
    // (2) Wp -> fp16
    {
        long n4 = (long)H_SZ * D_SZ / 4;
        convert_h<<<(int)((n4 + 255) / 256), 256>>>(Wp, Wp_h, n4);
    }
    // (3) opW1 -> fp16
    {
        long n4 = (long)T_SZ * K_SZ * H_SZ * H_SZ / 4;
        convert_h<<<(int)((n4 + 255) / 256), 256>>>(opW1, oW1_h, n4);
    }
    // (4) softmax / conflict / entropy
    softmax_stats<<<1, 32>>>(op_logits);

    // (5) xp = x @ Wp^T + bp          (fp32 + hi/lo out)
    gemm2<<<dim3(H_SZ/GBN, B_SZ/GBM, 1), 256, SM>>>(
        x_hi, x_lo, D_SZ, 0, 0, 1,
        Wp_h, D_SZ, 0,
        bp, 0, nullptr,
        xp, xp_hi, xp_lo, H_SZ, 0, 0, H_SZ, D_SZ, 0);

    // (6) h1[t,k] = relu(xg[t] @ opW1[t,k]^T + opb1)   (A scattered; hi/lo out only)
    gemm2<<<dim3(H_SZ/GBN, G_SZ/GBM, T_SZ*K_SZ), 256, SM>>>(
        xp_hi, xp_lo, H_SZ, 0, T_SZ, K_SZ,
        oW1_h, H_SZ, (long)H_SZ*H_SZ,
        opb1, H_SZ, nullptr,
        nullptr, h1_hi, h1_lo, H_SZ, (long)G_SZ*H_SZ, 0, H_SZ, H_SZ, 1);

    // (7) opW2 -> fp16
    {
        long n4 = (long)T_SZ * K_SZ * H_SZ * H_SZ / 4;
        convert_h<<<(int)((n4 + 255) / 256), 256>>>(opW2, oW2_h, n4);
    }

    // (8) h2[t,k] = relu(h1[t,k] @ opW2[t,k]^T + opb2)   (fp32 out only)
    gemm2<<<dim3(H_SZ/GBN, G_SZ/GBM, T_SZ*K_SZ), 256, SM>>>(
        h1_hi, h1_lo, H_SZ, (long)G_SZ*H_SZ, 0, 1,
        oW2_h, H_SZ, (long)H_SZ*H_SZ,
        opb2, H_SZ, nullptr,
        h2, nullptr, nullptr, H_SZ, (long)G_SZ*H_SZ, 0, H_SZ, H_SZ, 1);

    // (9) out_full (scattered) = sum_k w[t,k] * h2[t,k]   (+ hi/lo emit)
    wsum_kernel<<<(T_SZ*G_SZ*H_SZ/4)/256, 256>>>(out_full);

    // (10) per-row stats
    row_stats<<<(B_SZ*32)/256, 256>>>(out_full, noise);

    // (11) phW -> fp16
    {
        long n4 = (long)D_SZ * H_SZ / 4;
        convert_h<<<(int)((n4 + 255) / 256), 256>>>(phW, phW_h, n4);
    }
    // (12) rW1 first-H columns -> fp16
    rw1_extract<<<(H_SZ * H_SZ) / 256, 256>>>(rW1, rW1c_h);

    // (13) signals, decision, routing extra bias
    finalize_kernel<<<T_SZ, 256>>>(id_emb, rW1, gW1, gb1, gW2, gb2, decision);

    // (14) rh = relu(out @ rW1[:, :H]^T + c_extra[t] + rb1)   (A & C rows scattered)
    gemm2<<<dim3(H_SZ/GBN, G_SZ/GBM, T_SZ), 256, SM>>>(
        out_hi, out_lo, H_SZ, 0, T_SZ, 1,
        rW1c_h, H_SZ, 0,
        rb1, 0, extra,
        rh, nullptr, nullptr, H_SZ, 0, T_SZ, H_SZ, H_SZ, 1);

    // (15) logits = rh @ rW2^T + rb2
    logits_kernel<<<B_SZ, (T_SZ + 1) * 32>>>(rW2, rb2, logits);

    // (16) pred = out_full @ phW^T + phb
    gemm2<<<dim3(D_SZ/GBN, B_SZ/GBM, 1), 256, SM>>>(
        out_hi, out_lo, H_SZ, 0, 0, 1,
        phW_h, H_SZ, 0,
        phb, 0, nullptr,
        pred, nullptr, nullptr, D_SZ, 0, 0, D_SZ, H_SZ, 0);
}

// round 14
// speedup vs baseline: 3.5854x; 1.0326x over previous
#include <cuda_runtime.h>
#include <cuda_fp16.h>
#include <stdint.h>
#include <math.h>

typedef __half h16;

#define B_SZ 12288
#define D_SZ 1024
#define H_SZ 512
#define T_SZ 12
#define K_SZ 3
#define G_SZ 1024   // B_SZ / T_SZ

// ---------------- fp32 scratch ----------------
__device__ float g_xp[(size_t)B_SZ * H_SZ];
__device__ float g_h2[(size_t)T_SZ * K_SZ * G_SZ * H_SZ];
__device__ float g_rh[(size_t)B_SZ * H_SZ];
__device__ float g_w[T_SZ * K_SZ];
__device__ float g_conf[T_SZ];
__device__ float g_ent[T_SZ];
__device__ float g_pe[B_SZ];
__device__ float g_nov[B_SZ];
__device__ float g_sp[B_SZ];
__device__ float g_pl[B_SZ];
__device__ float g_extra[T_SZ * H_SZ];

// ---------------- fp16 scratch: A-side hi/lo pairs, B-side single ----------------
__device__ __align__(16) h16 g_x_hi[(size_t)B_SZ * D_SZ];
__device__ __align__(16) h16 g_x_lo[(size_t)B_SZ * D_SZ];
__device__ __align__(16) h16 g_xp_hi[(size_t)B_SZ * H_SZ];
__device__ __align__(16) h16 g_xp_lo[(size_t)B_SZ * H_SZ];
__device__ __align__(16) h16 g_h1_hi[(size_t)T_SZ * K_SZ * G_SZ * H_SZ];
__device__ __align__(16) h16 g_h1_lo[(size_t)T_SZ * K_SZ * G_SZ * H_SZ];
__device__ __align__(16) h16 g_out_hi[(size_t)B_SZ * H_SZ];
__device__ __align__(16) h16 g_out_lo[(size_t)B_SZ * H_SZ];
__device__ __align__(16) h16 g_Wp_h[(size_t)H_SZ * D_SZ];
__device__ __align__(16) h16 g_oW1_h[(size_t)T_SZ * K_SZ * H_SZ * H_SZ];
__device__ __align__(16) h16 g_oW2_h[(size_t)T_SZ * K_SZ * H_SZ * H_SZ];
__device__ __align__(16) h16 g_rW1c_h[(size_t)H_SZ * H_SZ];
__device__ __align__(16) h16 g_phW_h[(size_t)D_SZ * H_SZ];

// ---------------- helpers ----------------
__device__ __forceinline__ void split2h(float v, h16& h, h16& l) {
    h = __float2half_rn(v);
    l = __float2half_rn(v - __half2float(h));
}

__device__ __forceinline__ void mma16816(float* c, const unsigned* a, const unsigned* b) {
    asm volatile(
        "mma.sync.aligned.m16n8k16.row.col.f32.f16.f16.f32 "
        "{%0,%1,%2,%3},{%4,%5,%6,%7},{%8,%9},{%0,%1,%2,%3};"
        : "+f"(c[0]), "+f"(c[1]), "+f"(c[2]), "+f"(c[3])
        : "r"(a[0]), "r"(a[1]), "r"(a[2]), "r"(a[3]), "r"(b[0]), "r"(b[1]));
}

#define LDMX4(R_, ADDR_)                                                      \
    asm volatile("ldmatrix.sync.aligned.m8n8.x4.shared.b16 {%0,%1,%2,%3},[%4];" \
                 : "=r"((R_)[0]), "=r"((R_)[1]), "=r"((R_)[2]), "=r"((R_)[3]) \
                 : "r"(ADDR_))

#define LDMX2(R_, ADDR_)                                                      \
    asm volatile("ldmatrix.sync.aligned.m8n8.x2.shared.b16 {%0,%1},[%2];"     \
                 : "=r"((R_)[0]), "=r"((R_)[1]) : "r"(ADDR_))

#define CPA(DST_, SRC_)                                                       \
    asm volatile("cp.async.cg.shared.global [%0],[%1],16;" :: "r"(DST_), "l"(SRC_))

#define CP_COMMIT asm volatile("cp.async.commit_group;")
#define CP_WAIT1  asm volatile("cp.async.wait_group 1;")
#define CP_WAIT0  asm volatile("cp.async.wait_group 0;")

// ---------------- fp16 2-product tensor-core GEMM: C = A @ B^T (+bias)(+extra)(relu) ----
// A_hi/lo [M, lda] fp16 row-major (k contig) — exact split pair.
// B [N, ldb] single fp16 row-major (k contig).
// a_scatter/c_scatter: logical row r -> global row r*scatter + tcur, tcur = z / t_div.
// BM=BN=128, BK=32, 256 threads (8 warps 2x4, warp tile 64x32).
// 3-stage cp.async pipeline; smem 3*30720 = 92160 B per CTA, 2 CTAs/SM.
#define GBM 128
#define GBN 128
#define GBK 32
#define SROW 40
#define STAGE_BYTES 30720u
#define NSTAGE 3

#define LOAD_STAGE(S_, KB_) do {                                              \
    uint32_t base_ = smem_u32 + (uint32_t)(S_) * STAGE_BYTES;                 \
    CPA(base_ +      0u + sOff0, pAh0 + (KB_));                               \
    CPA(base_ +      0u + sOff1, pAh1 + (KB_));                               \
    CPA(base_ + 10240u + sOff0, pAl0 + (KB_));                                \
    CPA(base_ + 10240u + sOff1, pAl1 + (KB_));                                \
    CPA(base_ + 20480u + sOff0, pB0 + (KB_));                                 \
    CPA(base_ + 20480u + sOff1, pB1 + (KB_));                                 \
} while (0)

__global__ __launch_bounds__(256, 2)
void gemm2(const h16* __restrict__ Ah, const h16* __restrict__ Al,
           int lda, long a_bstride, int a_scatter, int t_div,
           const h16* __restrict__ Bm,
           int ldb, long b_bstride,
           const float* __restrict__ bias, long bias_bstride,
           const float* __restrict__ extra,
           float* __restrict__ C, h16* __restrict__ Chi, h16* __restrict__ Clo,
           int ldc, long c_bstride, int c_scatter,
           int N, int Kdim, int do_relu)
{
    extern __shared__ __align__(16) char smem_raw[];
    uint32_t smem_u32 = (uint32_t)__cvta_generic_to_shared(smem_raw);

    const int tid  = threadIdx.x;
    const int z    = blockIdx.z;
    const int tcur = z / t_div;
    const int brow = blockIdx.y * GBM;
    const int bcol = blockIdx.x * GBN;

    // ---- loader setup: 512 (row,chunk) slots, 2 per thread ----
    const int id0 = tid * 2, id1 = id0 + 1;
    const int r0 = id0 >> 2, ch0 = (id0 & 3) * 8;
    const int r1 = id1 >> 2, ch1 = (id1 & 3) * 8;

    long arow0 = brow + r0, arow1 = brow + r1;
    if (a_scatter) { arow0 = arow0 * a_scatter + tcur; arow1 = arow1 * a_scatter + tcur; }
    const h16* pAh0 = Ah + z * a_bstride + arow0 * (long)lda + ch0;
    const h16* pAh1 = Ah + z * a_bstride + arow1 * (long)lda + ch1;
    const h16* pAl0 = Al + z * a_bstride + arow0 * (long)lda + ch0;
    const h16* pAl1 = Al + z * a_bstride + arow1 * (long)lda + ch1;
    const h16* pB0  = Bm + z * b_bstride + (long)(bcol + r0) * ldb + ch0;
    const h16* pB1  = Bm + z * b_bstride + (long)(bcol + r1) * ldb + ch1;
    const uint32_t sOff0 = (uint32_t)(r0 * SROW + ch0) * 2u;
    const uint32_t sOff1 = (uint32_t)(r1 * SROW + ch1) * 2u;

    // ---- fragment-load setup ----
    const int lane = tid & 31;
    const int warp = tid >> 5;
    const int wm = (warp & 1) * 64;
    const int wn = (warp >> 1) * 32;
    const int aMat = lane >> 3, aR = lane & 7;
    const uint32_t aOff = (uint32_t)((wm + (aMat & 1) * 8 + aR) * SROW + (aMat >> 1) * 8) * 2u;
    const int bL = lane & 15;
    const uint32_t bOff = (uint32_t)((wn + (bL & 7)) * SROW + ((bL >> 3) & 1) * 8) * 2u;

    float acc[4][4][4];
#pragma unroll
    for (int i = 0; i < 4; i++)
#pragma unroll
        for (int j = 0; j < 4; j++)
#pragma unroll
            for (int q = 0; q < 4; q++) acc[i][j][q] = 0.f;

    const int nIter = Kdim / GBK;
    LOAD_STAGE(0, 0);
    CP_COMMIT;
    LOAD_STAGE(1, GBK);
    CP_COMMIT;

    int sc = 0;
    for (int it = 0; it < nIter; ++it) {
        if (it < nIter - 1) { CP_WAIT1; } else { CP_WAIT0; }
        __syncthreads();

        const uint32_t baseA_hi = smem_u32 + (uint32_t)sc * STAGE_BYTES;
        const uint32_t baseA_lo = baseA_hi + 10240u;
        const uint32_t baseB    = baseA_hi + 20480u;

#pragma unroll
        for (int kk = 0; kk < 2; kk++) {
            const uint32_t kkb = (uint32_t)kk * 32u;
            unsigned bh[4][2];
#pragma unroll
            for (int j = 0; j < 4; j++)
                LDMX2(bh[j], baseB + bOff + (uint32_t)j * 640u + kkb);
#pragma unroll
            for (int i = 0; i < 4; i++) {
                unsigned ah[4], al[4];
                LDMX4(ah, baseA_hi + aOff + (uint32_t)i * 1280u + kkb);
                LDMX4(al, baseA_lo + aOff + (uint32_t)i * 1280u + kkb);
#pragma unroll
                for (int j = 0; j < 4; j++) {
                    mma16816(acc[i][j], ah, bh[j]);
                    mma16816(acc[i][j], al, bh[j]);
                }
            }
        }

        if (it + 2 < nIter) {
            int sn = sc + 2; if (sn >= NSTAGE) sn -= NSTAGE;
            LOAD_STAGE(sn, (long)(it + 2) * GBK);
            CP_COMMIT;
        }
        if (++sc == NSTAGE) sc = 0;
    }

    // ---- epilogue ----
    const float* biasb = bias ? bias + (long)z * bias_bstride : nullptr;
    const int g4 = lane >> 2, t4 = lane & 3;
#pragma unroll
    for (int i = 0; i < 4; i++) {
#pragma unroll
        for (int half_ = 0; half_ < 2; half_++) {
            int m_local = wm + i * 16 + g4 + half_ * 8;
            long crow = brow + m_local;
            if (c_scatter) crow = crow * c_scatter + tcur;
            long rbase = (long)z * c_bstride + crow * (long)ldc;
#pragma unroll
            for (int j = 0; j < 4; j++) {
                int n_local = wn + j * 8 + t4 * 2;
                int n = bcol + n_local;
                float v0 = acc[i][j][half_ * 2 + 0];
                float v1 = acc[i][j][half_ * 2 + 1];
                if (biasb) { v0 += biasb[n]; v1 += biasb[n + 1]; }
                if (extra) { v0 += extra[tcur * N + n]; v1 += extra[tcur * N + n + 1]; }
                if (do_relu) { v0 = fmaxf(v0, 0.f); v1 = fmaxf(v1, 0.f); }
                if (C) {
                    float2 f2; f2.x = v0; f2.y = v1;
                    *(float2*)(C + rbase + n) = f2;
                }
                if (Chi) {
                    h16 h0, l0, h1, l1;
                    split2h(v0, h0, l0); split2h(v1, h1, l1);
                    __half2 ph; ph.x = h0; ph.y = h1;
                    __half2 pl; pl.x = l0; pl.y = l1;
                    *(__half2*)(Chi + rbase + n) = ph;
                    *(__half2*)(Clo + rbase + n) = pl;
                }
            }
        }
    }
}

// ---------------- prep: all conversions + rW1 extract + softmax in ONE kernel ----------
// segments (blocks of 256 thr, 2 float4/thread = 512 float4/block):
//  x      : 3145728 f4 -> 6144 blocks   [0, 6144)
//  Wp     :  131072 f4 ->  256 blocks   [6144, 6400)
//  opW1   : 2359296 f4 -> 4608 blocks   [6400, 11008)
//  opW2   : 2359296 f4 -> 4608 blocks   [11008, 15616)
//  phW    :  131072 f4 ->  256 blocks   [15616, 15872)
//  rW1    :  262144 el ->  128 blocks   [15872, 16000)  (8 scalars/thread)
//  softmax: 1 block                     [16000]
#define SEG_X   6144
#define SEG_WP  (SEG_X + 256)
#define SEG_W1  (SEG_WP + 4608)
#define SEG_W2  (SEG_W1 + 4608)
#define SEG_PH  (SEG_W2 + 256)
#define SEG_RW  (SEG_PH + 128)
#define PREP_BLOCKS (SEG_RW + 1)

__device__ __forceinline__ void conv_split_f4(const float4* in, __half2* hi, __half2* lo, long i) {
    float4 v = in[i];
    h16 h0,h1,h2,h3,l0,l1,l2,l3;
    split2h(v.x,h0,l0); split2h(v.y,h1,l1); split2h(v.z,h2,l2); split2h(v.w,h3,l3);
    __half2 a,b;
    a.x=h0; a.y=h1; b.x=h2; b.y=h3; hi[i*2]=a; hi[i*2+1]=b;
    a.x=l0; a.y=l1; b.x=l2; b.y=l3; lo[i*2]=a; lo[i*2+1]=b;
}
__device__ __forceinline__ void conv_h_f4(const float4* in, __half2* out, long i) {
    float4 v = in[i];
    __half2 a,b;
    a.x=__float2half_rn(v.x); a.y=__float2half_rn(v.y);
    b.x=__float2half_rn(v.z); b.y=__float2half_rn(v.w);
    out[i*2]=a; out[i*2+1]=b;
}

__global__ void prep_kernel(const float* __restrict__ x, const float* __restrict__ Wp,
                            const float* __restrict__ opW1, const float* __restrict__ opW2,
                            const float* __restrict__ phW, const float* __restrict__ rW1,
                            const float* __restrict__ op_logits)
{
    const int b = blockIdx.x, tid = threadIdx.x;
    if (b < SEG_X) {
        long i0 = (long)b * 512 + tid;
        conv_split_f4((const float4*)x, (__half2*)g_x_hi, (__half2*)g_x_lo, i0);
        conv_split_f4((const float4*)x, (__half2*)g_x_hi, (__half2*)g_x_lo, i0 + 256);
    } else if (b < SEG_WP) {
        long i0 = (long)(b - SEG_X) * 512 + tid;
        conv_h_f4((const float4*)Wp, (__half2*)g_Wp_h, i0);
        conv_h_f4((const float4*)Wp, (__half2*)g_Wp_h, i0 + 256);
    } else if (b < SEG_W1) {
        long i0 = (long)(b - SEG_WP) * 512 + tid;
        conv_h_f4((const float4*)opW1, (__half2*)g_oW1_h, i0);
        conv_h_f4((const float4*)opW1, (__half2*)g_oW1_h, i0 + 256);
    } else if (b < SEG_W2) {
        long i0 = (long)(b - SEG_W1) * 512 + tid;
        conv_h_f4((const float4*)opW2, (__half2*)g_oW2_h, i0);
        conv_h_f4((const float4*)opW2, (__half2*)g_oW2_h, i0 + 256);
    } else if (b < SEG_PH) {
        long i0 = (long)(b - SEG_W2) * 512 + tid;
        conv_h_f4((const float4*)phW, (__half2*)g_phW_h, i0);
        conv_h_f4((const float4*)phW, (__half2*)g_phW_h, i0 + 256);
    } else if (b < SEG_RW) {
        int base = (b - SEG_PH) * 2048 + tid * 8;   // element index into H*H
#pragma unroll
        for (int e = 0; e < 8; e++) {
            int idx = base + e;
            int i = idx >> 9, j = idx & 511;
            g_rW1c_h[idx] = __float2half_rn(rW1[(long)i * (H_SZ + 7) + j]);
        }
    } else {
        int t = tid;
        if (t < T_SZ) {
            float l0 = op_logits[t*K_SZ+0], l1 = op_logits[t*K_SZ+1], l2 = op_logits[t*K_SZ+2];
            float m = fmaxf(l0, fmaxf(l1, l2));
            float e0 = expf(l0 - m), e1 = expf(l1 - m), e2 = expf(l2 - m);
            float s = e0 + e1 + e2;
            float w0 = e0 / s, w1 = e1 / s, w2 = e2 / s;
            g_w[t*K_SZ+0] = w0; g_w[t*K_SZ+1] = w1; g_w[t*K_SZ+2] = w2;
            float mean = (w0 + w1 + w2) * (1.f / 3.f);
            float d0 = w0 - mean, d1 = w1 - mean, d2 = w2 - mean;
            g_conf[t] = sqrtf((d0*d0 + d1*d1 + d2*d2) * 0.5f);
            float sum = w0 + w1 + w2;
            float inv = 1.f / (sum + 1e-6f);
            float u0 = w0*inv, u1 = w1*inv, u2 = w2*inv;
            float ent = -(u0*logf(fmaxf(u0,1e-6f)) + u1*logf(fmaxf(u1,1e-6f)) + u2*logf(fmaxf(u2,1e-6f)));
            g_ent[t] = ent;
        }
    }
}

// ---------------- fused wsum + row stats: one block (128 thr) per row b ----------------
__device__ __forceinline__ float warp_sum(float v) {
#pragma unroll
    for (int o = 16; o > 0; o >>= 1) v += __shfl_down_sync(0xffffffffu, v, o);
    return v;
}

__global__ __launch_bounds__(128)
void wsum_stats(float* __restrict__ out_full, const float* __restrict__ noise)
{
    __shared__ float4 red[4];
    const int b = blockIdx.x;            // row in out order; b = g*T + t
    const int tid = threadIdx.x;         // 0..127, handles cols 4*tid..4*tid+3
    const int t = b % T_SZ, g = b / T_SZ;

    float w0 = g_w[t*K_SZ+0], w1 = g_w[t*K_SZ+1], w2 = g_w[t*K_SZ+2];
    const float4* p0 = (const float4*)&g_h2[(((long)(t*K_SZ+0))*G_SZ + g)*H_SZ];
    const float4* p1 = (const float4*)&g_h2[(((long)(t*K_SZ+1))*G_SZ + g)*H_SZ];
    const float4* p2 = (const float4*)&g_h2[(((long)(t*K_SZ+2))*G_SZ + g)*H_SZ];
    float4 v0 = p0[tid], v1 = p1[tid], v2 = p2[tid];
    float4 o;
    o.x = w0*v0.x + w1*v1.x + w2*v2.x;
    o.y = w0*v0.y + w1*v1.y + w2*v2.y;
    o.z = w0*v0.z + w1*v1.z + w2*v2.z;
    o.w = w0*v0.w + w1*v1.w + w2*v2.w;

    const long rowbase = (long)b * H_SZ;
    ((float4*)&out_full[rowbase])[tid] = o;

    h16 h0,h1,h2v,h3,l0,l1,l2v,l3;
    split2h(o.x,h0,l0); split2h(o.y,h1,l1); split2h(o.z,h2v,l2v); split2h(o.w,h3,l3);
    __half2 a2,b2;
    a2.x=h0; a2.y=h1; b2.x=h2v; b2.y=h3;
    ((__half2*)&g_out_hi[rowbase])[tid*2] = a2;
    ((__half2*)&g_out_hi[rowbase])[tid*2+1] = b2;
    a2.x=l0; a2.y=l1; b2.x=l2v; b2.y=l3;
    ((__half2*)&g_out_lo[rowbase])[tid*2] = a2;
    ((__half2*)&g_out_lo[rowbase])[tid*2+1] = b2;

    // stats vs xp and noise (same row index b in original order)
    float4 xv = ((const float4*)&g_xp[rowbase])[tid];
    float4 nv = ((const float4*)&noise[rowbase])[tid];
    float pe, nov, sp, pl, d;
    d = o.x - xv.x; pe  = d*d; nov  = xv.x*xv.x; sp  = fabsf(o.x);
    d = o.y - xv.y; pe += d*d; nov += xv.y*xv.y; sp += fabsf(o.y);
    d = o.z - xv.z; pe += d*d; nov += xv.z*xv.z; sp += fabsf(o.z);
    d = o.w - xv.w; pe += d*d; nov += xv.w*xv.w; sp += fabsf(o.w);
    float nx = nv.x*0.01f, ny = nv.y*0.01f, nz = nv.z*0.01f, nw = nv.w*0.01f;
    pl = nx*nx + ny*ny + nz*nz + nw*nw;

    pe = warp_sum(pe); nov = warp_sum(nov); sp = warp_sum(sp); pl = warp_sum(pl);
    const int lane = tid & 31, warp = tid >> 5;
    if (lane == 0) { float4 f; f.x=pe; f.y=nov; f.z=sp; f.w=pl; red[warp] = f; }
    __syncthreads();
    if (tid == 0) {
        float4 s = red[0];
        s.x += red[1].x + red[2].x + red[3].x;
        s.y += red[1].y + red[2].y + red[3].y;
        s.z += red[1].z + red[2].z + red[3].z;
        s.w += red[1].w + red[2].w + red[3].w;
        const float inv = 1.f / (float)H_SZ;
        g_pe[b]  = s.x * inv;
        g_nov[b] = s.y * inv;
        g_sp[b]  = s.z * inv;
        g_pl[b]  = s.w * inv;
    }
}

// ---------------- finalize (one block per t) ----------------
__device__ __forceinline__ float block_sum(float v, float* red, int tid) {
    red[tid] = v; __syncthreads();
    for (int s = 128; s > 0; s >>= 1) { if (tid < s) red[tid] += red[tid + s]; __syncthreads(); }
    float r = red[0]; __syncthreads();
    return r;
}

__global__ void finalize_kernel(const float* __restrict__ id_emb, const float* __restrict__ rW1,
                                const float* __restrict__ gW1, const float* __restrict__ gb1,
                                const float* __restrict__ gW2, const float* __restrict__ gb2,
                                float* __restrict__ decision)
{
    __shared__ float red[256];
    __shared__ float sig[7];
    __shared__ float gch[H_SZ];
    const int t = blockIdx.x, tid = threadIdx.x;

    float pe = 0.f, pe2 = 0.f, nov = 0.f, sp = 0.f, pl = 0.f;
    for (int g = tid; g < G_SZ; g += 256) {
        int b = g * T_SZ + t;
        float p = g_pe[b];
        pe += p; pe2 += p * p; nov += g_nov[b]; sp += g_sp[b]; pl += g_pl[b];
    }
    float S_pe  = block_sum(pe,  red, tid);
    float S_pe2 = block_sum(pe2, red, tid);
    float S_nov = block_sum(nov, red, tid);
    float S_sp  = block_sum(sp,  red, tid);
    float S_pl  = block_sum(pl,  red, tid);

    if (tid == 0) {
        const float invg = 1.f / (float)G_SZ;
        float pe_m = S_pe * invg, pe2_m = S_pe2 * invg;
        float c = 0.01f * pe_m;
        sig[0] = S_pl * invg;
        sig[1] = S_nov * invg;
        sig[2] = pe_m;
        sig[3] = g_ent[t];
        sig[4] = S_sp * invg;
        sig[5] = -pe_m;
        sig[6] = pe2_m - 2.f * c * pe_m + c * c;
    }
    __syncthreads();

    for (int i = tid; i < H_SZ; i += 256) {
        float a = gb1[t * H_SZ + i];
#pragma unroll
        for (int j = 0; j < 7; j++) a += gW1[((long)(t * H_SZ + i)) * 7 + j] * sig[j];
        gch[i] = fmaxf(a, 0.f);
    }
    __syncthreads();

    for (int o = 0; o < 2; o++) {
        float d = 0.f;
        for (int i = tid; i < H_SZ; i += 256) d += gW2[((long)(t * 2 + o)) * H_SZ + i] * gch[i];
        float S = block_sum(d, red, tid);
        if (tid == 0) decision[t * 2 + o] = S + gb2[t * 2 + o];
    }

    __shared__ float ext[7];
    if (tid == 0) {
        ext[0] = id_emb[t*4+0]; ext[1] = id_emb[t*4+1];
        ext[2] = id_emb[t*4+2]; ext[3] = id_emb[t*4+3];
        ext[4] = sig[1];
        ext[5] = g_conf[t];
        ext[6] = sig[2];
    }
    __syncthreads();
    for (int i = tid; i < H_SZ; i += 256) {
        float a = 0.f;
#pragma unroll
        for (int j = 0; j < 7; j++) a += ext[j] * rW1[(long)i * (H_SZ + 7) + H_SZ + j];
        g_extra[t * H_SZ + i] = a;
    }
}

// ---------------- logits ----------------
__global__ void logits_kernel(const float* __restrict__ rW2, const float* __restrict__ rb2,
                              float* __restrict__ logits)
{
    const int b = blockIdx.x;
    const int o = threadIdx.x >> 5, lane = threadIdx.x & 31;
    const float4* r = (const float4*)(g_rh + (long)b * H_SZ);
    const float4* wrow = (const float4*)(rW2 + (long)o * H_SZ);
    float acc = 0.f;
    for (int i = lane; i < H_SZ/4; i += 32) {
        float4 rv = r[i], wv = wrow[i];
        acc += rv.x*wv.x + rv.y*wv.y + rv.z*wv.z + rv.w*wv.w;
    }
    acc = warp_sum(acc);
    if (lane == 0) logits[(long)b * (T_SZ + 1) + o] = acc + rb2[o];
}

// ---------------- launch ----------------
extern "C" void kernel_launch(void* const* d_in, const int* in_sizes, int n_in,
                              void* d_out, int out_size)
{
    const float* x         = (const float*)d_in[0];
    const float* Wp        = (const float*)d_in[1];
    const float* bp        = (const float*)d_in[2];
    const float* opW1      = (const float*)d_in[3];
    const float* opb1      = (const float*)d_in[4];
    const float* opW2      = (const float*)d_in[5];
    const float* opb2      = (const float*)d_in[6];
    const float* op_logits = (const float*)d_in[7];
    const float* id_emb    = (const float*)d_in[8];
    const float* rW1       = (const float*)d_in[9];
    const float* rb1       = (const float*)d_in[10];
    const float* rW2       = (const float*)d_in[11];
    const float* rb2       = (const float*)d_in[12];
    const float* gW1       = (const float*)d_in[13];
    const float* gb1       = (const float*)d_in[14];
    const float* gW2       = (const float*)d_in[15];
    const float* gb2       = (const float*)d_in[16];
    const float* phW       = (const float*)d_in[17];
    const float* phb       = (const float*)d_in[18];
    const float* noise     = (const float*)d_in[19];

    float* out_full = (float*)d_out;
    float* logits   = out_full + (size_t)B_SZ * H_SZ;
    float* pred     = logits   + (size_t)B_SZ * (T_SZ + 1);
    float* decision = pred     + (size_t)B_SZ * D_SZ;

    float *xp, *h2, *extra, *rh;
    h16 *x_hi, *x_lo, *xp_hi, *xp_lo, *h1_hi, *h1_lo, *out_hi, *out_lo;
    h16 *Wp_h, *oW1_h, *oW2_h, *rW1c_h, *phW_h;
    cudaGetSymbolAddress((void**)&xp,      g_xp);
    cudaGetSymbolAddress((void**)&h2,      g_h2);
    cudaGetSymbolAddress((void**)&extra,   g_extra);
    cudaGetSymbolAddress((void**)&rh,      g_rh);
    cudaGetSymbolAddress((void**)&x_hi,    g_x_hi);    cudaGetSymbolAddress((void**)&x_lo,    g_x_lo);
    cudaGetSymbolAddress((void**)&xp_hi,   g_xp_hi);   cudaGetSymbolAddress((void**)&xp_lo,   g_xp_lo);
    cudaGetSymbolAddress((void**)&h1_hi,   g_h1_hi);   cudaGetSymbolAddress((void**)&h1_lo,   g_h1_lo);
    cudaGetSymbolAddress((void**)&out_hi,  g_out_hi);  cudaGetSymbolAddress((void**)&out_lo,  g_out_lo);
    cudaGetSymbolAddress((void**)&Wp_h,    g_Wp_h);
    cudaGetSymbolAddress((void**)&oW1_h,   g_oW1_h);
    cudaGetSymbolAddress((void**)&oW2_h,   g_oW2_h);
    cudaGetSymbolAddress((void**)&rW1c_h,  g_rW1c_h);
    cudaGetSymbolAddress((void**)&phW_h,   g_phW_h);

    cudaFuncSetAttribute(gemm2, cudaFuncAttributeMaxDynamicSharedMemorySize,
                         NSTAGE * (int)STAGE_BYTES);
    const int SM = NSTAGE * (int)STAGE_BYTES;

    // (1) all conversions + softmax fused
    prep_kernel<<<PREP_BLOCKS, 256>>>(x, Wp, opW1, opW2, phW, rW1, op_logits);

    // (2) xp = x @ Wp^T + bp          (fp32 + hi/lo out)
    gemm2<<<dim3(H_SZ/GBN, B_SZ/GBM, 1), 256, SM>>>(
        x_hi, x_lo, D_SZ, 0, 0, 1,
        Wp_h, D_SZ, 0,
        bp, 0, nullptr,
        xp, xp_hi, xp_lo, H_SZ, 0, 0, H_SZ, D_SZ, 0);

    // (3) h1[t,k] = relu(xg[t] @ opW1[t,k]^T + opb1)   (A scattered; hi/lo out only)
    gemm2<<<dim3(H_SZ/GBN, G_SZ/GBM, T_SZ*K_SZ), 256, SM>>>(
        xp_hi, xp_lo, H_SZ, 0, T_SZ, K_SZ,
        oW1_h, H_SZ, (long)H_SZ*H_SZ,
        opb1, H_SZ, nullptr,
        nullptr, h1_hi, h1_lo, H_SZ, (long)G_SZ*H_SZ, 0, H_SZ, H_SZ, 1);

    // (4) h2[t,k] = relu(h1[t,k] @ opW2[t,k]^T + opb2)   (fp32 out only)  [profiled]
    gemm2<<<dim3(H_SZ/GBN, G_SZ/GBM, T_SZ*K_SZ), 256, SM>>>(
        h1_hi, h1_lo, H_SZ, (long)G_SZ*H_SZ, 0, 1,
        oW2_h, H_SZ, (long)H_SZ*H_SZ,
        opb2, H_SZ, nullptr,
        h2, nullptr, nullptr, H_SZ, (long)G_SZ*H_SZ, 0, H_SZ, H_SZ, 1);

    // (5) fused weighted mixture + per-row stats
    wsum_stats<<<B_SZ, 128>>>(out_full, noise);

    // (6) signals, decision, routing extra bias
    finalize_kernel<<<T_SZ, 256>>>(id_emb, rW1, gW1, gb1, gW2, gb2, decision);

    // (7) rh = relu(out @ rW1[:, :H]^T + c_extra[t] + rb1)   (A & C rows scattered)
    gemm2<<<dim3(H_SZ/GBN, G_SZ/GBM, T_SZ), 256, SM>>>(
        out_hi, out_lo, H_SZ, 0, T_SZ, 1,
        rW1c_h, H_SZ, 0,
        rb1, 0, extra,
        rh, nullptr, nullptr, H_SZ, 0, T_SZ, H_SZ, H_SZ, 1);

    // (8) logits = rh @ rW2^T + rb2
    logits_kernel<<<B_SZ, (T_SZ + 1) * 32>>>(rW2, rb2, logits);

    // (9) pred = out_full @ phW^T + phb
    gemm2<<<dim3(D_SZ/GBN, B_SZ/GBM, 1), 256, SM>>>(
        out_hi, out_lo, H_SZ, 0, 0, 1,
        phW_h, H_SZ, 0,
        phb, 0, nullptr,
        pred, nullptr, nullptr, D_SZ, 0, 0, D_SZ, H_SZ, 0);
}

// round 15
// speedup vs baseline: 3.6660x; 1.0225x over previous
#include <cuda_runtime.h>
#include <cuda_fp16.h>
#include <stdint.h>
#include <math.h>

typedef __half h16;

#define B_SZ 12288
#define D_SZ 1024
#define H_SZ 512
#define T_SZ 12
#define K_SZ 3
#define G_SZ 1024   // B_SZ / T_SZ

// ---------------- fp32 scratch ----------------
__device__ float g_xp[(size_t)B_SZ * H_SZ];
__device__ float g_h2[(size_t)T_SZ * K_SZ * G_SZ * H_SZ];
__device__ float g_rh[(size_t)B_SZ * H_SZ];
__device__ float g_w[T_SZ * K_SZ];
__device__ float g_conf[T_SZ];
__device__ float g_ent[T_SZ];
__device__ float g_pe[B_SZ];
__device__ float g_nov[B_SZ];
__device__ float g_sp[B_SZ];
__device__ float g_pl[B_SZ];
__device__ float g_extra[T_SZ * H_SZ];

// ---------------- fp16 scratch: A-side hi/lo pairs, B-side single ----------------
__device__ __align__(16) h16 g_x_hi[(size_t)B_SZ * D_SZ];
__device__ __align__(16) h16 g_x_lo[(size_t)B_SZ * D_SZ];
__device__ __align__(16) h16 g_xp_hi[(size_t)B_SZ * H_SZ];
__device__ __align__(16) h16 g_xp_lo[(size_t)B_SZ * H_SZ];
__device__ __align__(16) h16 g_h1_hi[(size_t)T_SZ * K_SZ * G_SZ * H_SZ];
__device__ __align__(16) h16 g_h1_lo[(size_t)T_SZ * K_SZ * G_SZ * H_SZ];
__device__ __align__(16) h16 g_out_hi[(size_t)B_SZ * H_SZ];
__device__ __align__(16) h16 g_out_lo[(size_t)B_SZ * H_SZ];
__device__ __align__(16) h16 g_Wp_h[(size_t)H_SZ * D_SZ];
__device__ __align__(16) h16 g_oW1_h[(size_t)T_SZ * K_SZ * H_SZ * H_SZ];
__device__ __align__(16) h16 g_oW2_h[(size_t)T_SZ * K_SZ * H_SZ * H_SZ];
__device__ __align__(16) h16 g_rW1c_h[(size_t)H_SZ * H_SZ];
__device__ __align__(16) h16 g_phW_h[(size_t)D_SZ * H_SZ];

// ---------------- helpers ----------------
__device__ __forceinline__ void split2h(float v, h16& h, h16& l) {
    h = __float2half_rn(v);
    l = __float2half_rn(v - __half2float(h));
}

__device__ __forceinline__ void mma16816(float* c, const unsigned* a, const unsigned* b) {
    asm volatile(
        "mma.sync.aligned.m16n8k16.row.col.f32.f16.f16.f32 "
        "{%0,%1,%2,%3},{%4,%5,%6,%7},{%8,%9},{%0,%1,%2,%3};"
        : "+f"(c[0]), "+f"(c[1]), "+f"(c[2]), "+f"(c[3])
        : "r"(a[0]), "r"(a[1]), "r"(a[2]), "r"(a[3]), "r"(b[0]), "r"(b[1]));
}

#define LDMX4(R_, ADDR_)                                                      \
    asm volatile("ldmatrix.sync.aligned.m8n8.x4.shared.b16 {%0,%1,%2,%3},[%4];" \
                 : "=r"((R_)[0]), "=r"((R_)[1]), "=r"((R_)[2]), "=r"((R_)[3]) \
                 : "r"(ADDR_))

#define LDMX2(R_, ADDR_)                                                      \
    asm volatile("ldmatrix.sync.aligned.m8n8.x2.shared.b16 {%0,%1},[%2];"     \
                 : "=r"((R_)[0]), "=r"((R_)[1]) : "r"(ADDR_))

#define CPA(DST_, SRC_)                                                       \
    asm volatile("cp.async.cg.shared.global [%0],[%1],16;" :: "r"(DST_), "l"(SRC_))

#define CP_COMMIT asm volatile("cp.async.commit_group;")
#define CP_WAIT1  asm volatile("cp.async.wait_group 1;")
#define CP_WAIT0  asm volatile("cp.async.wait_group 0;")

// ---------------- fp16 2-product tensor-core GEMM: C = A @ B^T (+bias)(+extra)(relu) ----
// A_hi/lo [M, lda] fp16 row-major (k contig) — exact split pair.
// B [N, ldb] single fp16 row-major (k contig).
// a_scatter/c_scatter: logical row r -> global row r*scatter + tcur, tcur = z / t_div.
// BM=BN=128, BK=32, 256 threads (8 warps 2x4, warp tile 64x32).
// 3-stage cp.async pipeline; register-double-buffered A-fragment loads.
#define GBM 128
#define GBN 128
#define GBK 32
#define SROW 40
#define STAGE_BYTES 30720u
#define NSTAGE 3

#define LOAD_STAGE(S_, KB_) do {                                              \
    uint32_t base_ = smem_u32 + (uint32_t)(S_) * STAGE_BYTES;                 \
    CPA(base_ +      0u + sOff0, pAh0 + (KB_));                               \
    CPA(base_ +      0u + sOff1, pAh1 + (KB_));                               \
    CPA(base_ + 10240u + sOff0, pAl0 + (KB_));                                \
    CPA(base_ + 10240u + sOff1, pAl1 + (KB_));                                \
    CPA(base_ + 20480u + sOff0, pB0 + (KB_));                                 \
    CPA(base_ + 20480u + sOff1, pB1 + (KB_));                                 \
} while (0)

__global__ __launch_bounds__(256, 2)
void gemm2(const h16* __restrict__ Ah, const h16* __restrict__ Al,
           int lda, long a_bstride, int a_scatter, int t_div,
           const h16* __restrict__ Bm,
           int ldb, long b_bstride,
           const float* __restrict__ bias, long bias_bstride,
           const float* __restrict__ extra,
           float* __restrict__ C, h16* __restrict__ Chi, h16* __restrict__ Clo,
           int ldc, long c_bstride, int c_scatter,
           int N, int Kdim, int do_relu)
{
    extern __shared__ __align__(16) char smem_raw[];
    uint32_t smem_u32 = (uint32_t)__cvta_generic_to_shared(smem_raw);

    const int tid  = threadIdx.x;
    const int z    = blockIdx.z;
    const int tcur = z / t_div;
    const int brow = blockIdx.y * GBM;
    const int bcol = blockIdx.x * GBN;

    // ---- loader setup: 512 (row,chunk) slots, 2 per thread ----
    const int id0 = tid * 2, id1 = id0 + 1;
    const int r0 = id0 >> 2, ch0 = (id0 & 3) * 8;
    const int r1 = id1 >> 2, ch1 = (id1 & 3) * 8;

    long arow0 = brow + r0, arow1 = brow + r1;
    if (a_scatter) { arow0 = arow0 * a_scatter + tcur; arow1 = arow1 * a_scatter + tcur; }
    const h16* pAh0 = Ah + z * a_bstride + arow0 * (long)lda + ch0;
    const h16* pAh1 = Ah + z * a_bstride + arow1 * (long)lda + ch1;
    const h16* pAl0 = Al + z * a_bstride + arow0 * (long)lda + ch0;
    const h16* pAl1 = Al + z * a_bstride + arow1 * (long)lda + ch1;
    const h16* pB0  = Bm + z * b_bstride + (long)(bcol + r0) * ldb + ch0;
    const h16* pB1  = Bm + z * b_bstride + (long)(bcol + r1) * ldb + ch1;
    const uint32_t sOff0 = (uint32_t)(r0 * SROW + ch0) * 2u;
    const uint32_t sOff1 = (uint32_t)(r1 * SROW + ch1) * 2u;

    // ---- fragment-load setup ----
    const int lane = tid & 31;
    const int warp = tid >> 5;
    const int wm = (warp & 1) * 64;
    const int wn = (warp >> 1) * 32;
    const int aMat = lane >> 3, aR = lane & 7;
    const uint32_t aOff = (uint32_t)((wm + (aMat & 1) * 8 + aR) * SROW + (aMat >> 1) * 8) * 2u;
    const int bL = lane & 15;
    const uint32_t bOff = (uint32_t)((wn + (bL & 7)) * SROW + ((bL >> 3) & 1) * 8) * 2u;

    float acc[4][4][4];
#pragma unroll
    for (int i = 0; i < 4; i++)
#pragma unroll
        for (int j = 0; j < 4; j++)
#pragma unroll
            for (int q = 0; q < 4; q++) acc[i][j][q] = 0.f;

    const int nIter = Kdim / GBK;
    LOAD_STAGE(0, 0);
    CP_COMMIT;
    LOAD_STAGE(1, GBK);
    CP_COMMIT;

    int sc = 0;
    for (int it = 0; it < nIter; ++it) {
        if (it < nIter - 1) { CP_WAIT1; } else { CP_WAIT0; }
        __syncthreads();

        const uint32_t baseA_hi = smem_u32 + (uint32_t)sc * STAGE_BYTES;
        const uint32_t baseA_lo = baseA_hi + 10240u;
        const uint32_t baseB    = baseA_hi + 20480u;

#pragma unroll
        for (int kk = 0; kk < 2; kk++) {
            const uint32_t kkb = (uint32_t)kk * 32u;
            unsigned bh[4][2];
#pragma unroll
            for (int j = 0; j < 4; j++)
                LDMX2(bh[j], baseB + bOff + (uint32_t)j * 640u + kkb);

            // register-double-buffered A fragments: issue ldsm for tile i+1
            // BEFORE the MMAs of tile i, so each ldsm hides under a full MMA batch.
            unsigned ah[2][4], al[2][4];
            LDMX4(ah[0], baseA_hi + aOff + kkb);
            LDMX4(al[0], baseA_lo + aOff + kkb);
#pragma unroll
            for (int i = 0; i < 4; i++) {
                const int cur = i & 1, nxt = cur ^ 1;
                if (i < 3) {
                    LDMX4(ah[nxt], baseA_hi + aOff + (uint32_t)(i + 1) * 1280u + kkb);
                    LDMX4(al[nxt], baseA_lo + aOff + (uint32_t)(i + 1) * 1280u + kkb);
                }
#pragma unroll
                for (int j = 0; j < 4; j++) {
                    mma16816(acc[i][j], ah[cur], bh[j]);
                    mma16816(acc[i][j], al[cur], bh[j]);
                }
            }
        }

        if (it + 2 < nIter) {
            int sn = sc + 2; if (sn >= NSTAGE) sn -= NSTAGE;
            LOAD_STAGE(sn, (long)(it + 2) * GBK);
            CP_COMMIT;
        }
        if (++sc == NSTAGE) sc = 0;
    }

    // ---- epilogue ----
    const float* biasb = bias ? bias + (long)z * bias_bstride : nullptr;
    const int g4 = lane >> 2, t4 = lane & 3;
#pragma unroll
    for (int i = 0; i < 4; i++) {
#pragma unroll
        for (int half_ = 0; half_ < 2; half_++) {
            int m_local = wm + i * 16 + g4 + half_ * 8;
            long crow = brow + m_local;
            if (c_scatter) crow = crow * c_scatter + tcur;
            long rbase = (long)z * c_bstride + crow * (long)ldc;
#pragma unroll
            for (int j = 0; j < 4; j++) {
                int n_local = wn + j * 8 + t4 * 2;
                int n = bcol + n_local;
                float v0 = acc[i][j][half_ * 2 + 0];
                float v1 = acc[i][j][half_ * 2 + 1];
                if (biasb) { v0 += biasb[n]; v1 += biasb[n + 1]; }
                if (extra) { v0 += extra[tcur * N + n]; v1 += extra[tcur * N + n + 1]; }
                if (do_relu) { v0 = fmaxf(v0, 0.f); v1 = fmaxf(v1, 0.f); }
                if (C) {
                    float2 f2; f2.x = v0; f2.y = v1;
                    *(float2*)(C + rbase + n) = f2;
                }
                if (Chi) {
                    h16 h0, l0, h1, l1;
                    split2h(v0, h0, l0); split2h(v1, h1, l1);
                    __half2 ph; ph.x = h0; ph.y = h1;
                    __half2 pl; pl.x = l0; pl.y = l1;
                    *(__half2*)(Chi + rbase + n) = ph;
                    *(__half2*)(Clo + rbase + n) = pl;
                }
            }
        }
    }
}

// ---------------- prep: all conversions + rW1 extract + softmax in ONE kernel ----------
#define SEG_X   6144
#define SEG_WP  (SEG_X + 256)
#define SEG_W1  (SEG_WP + 4608)
#define SEG_W2  (SEG_W1 + 4608)
#define SEG_PH  (SEG_W2 + 256)
#define SEG_RW  (SEG_PH + 128)
#define PREP_BLOCKS (SEG_RW + 1)

__device__ __forceinline__ void conv_split_f4(const float4* in, __half2* hi, __half2* lo, long i) {
    float4 v = in[i];
    h16 h0,h1,h2,h3,l0,l1,l2,l3;
    split2h(v.x,h0,l0); split2h(v.y,h1,l1); split2h(v.z,h2,l2); split2h(v.w,h3,l3);
    __half2 a,b;
    a.x=h0; a.y=h1; b.x=h2; b.y=h3; hi[i*2]=a; hi[i*2+1]=b;
    a.x=l0; a.y=l1; b.x=l2; b.y=l3; lo[i*2]=a; lo[i*2+1]=b;
}
__device__ __forceinline__ void conv_h_f4(const float4* in, __half2* out, long i) {
    float4 v = in[i];
    __half2 a,b;
    a.x=__float2half_rn(v.x); a.y=__float2half_rn(v.y);
    b.x=__float2half_rn(v.z); b.y=__float2half_rn(v.w);
    out[i*2]=a; out[i*2+1]=b;
}

__global__ void prep_kernel(const float* __restrict__ x, const float* __restrict__ Wp,
                            const float* __restrict__ opW1, const float* __restrict__ opW2,
                            const float* __restrict__ phW, const float* __restrict__ rW1,
                            const float* __restrict__ op_logits)
{
    const int b = blockIdx.x, tid = threadIdx.x;
    if (b < SEG_X) {
        long i0 = (long)b * 512 + tid;
        conv_split_f4((const float4*)x, (__half2*)g_x_hi, (__half2*)g_x_lo, i0);
        conv_split_f4((const float4*)x, (__half2*)g_x_hi, (__half2*)g_x_lo, i0 + 256);
    } else if (b < SEG_WP) {
        long i0 = (long)(b - SEG_X) * 512 + tid;
        conv_h_f4((const float4*)Wp, (__half2*)g_Wp_h, i0);
        conv_h_f4((const float4*)Wp, (__half2*)g_Wp_h, i0 + 256);
    } else if (b < SEG_W1) {
        long i0 = (long)(b - SEG_WP) * 512 + tid;
        conv_h_f4((const float4*)opW1, (__half2*)g_oW1_h, i0);
        conv_h_f4((const float4*)opW1, (__half2*)g_oW1_h, i0 + 256);
    } else if (b < SEG_W2) {
        long i0 = (long)(b - SEG_W1) * 512 + tid;
        conv_h_f4((const float4*)opW2, (__half2*)g_oW2_h, i0);
        conv_h_f4((const float4*)opW2, (__half2*)g_oW2_h, i0 + 256);
    } else if (b < SEG_PH) {
        long i0 = (long)(b - SEG_W2) * 512 + tid;
        conv_h_f4((const float4*)phW, (__half2*)g_phW_h, i0);
        conv_h_f4((const float4*)phW, (__half2*)g_phW_h, i0 + 256);
    } else if (b < SEG_RW) {
        int base = (b - SEG_PH) * 2048 + tid * 8;
#pragma unroll
        for (int e = 0; e < 8; e++) {
            int idx = base + e;
            int i = idx >> 9, j = idx & 511;
            g_rW1c_h[idx] = __float2half_rn(rW1[(long)i * (H_SZ + 7) + j]);
        }
    } else {
        int t = tid;
        if (t < T_SZ) {
            float l0 = op_logits[t*K_SZ+0], l1 = op_logits[t*K_SZ+1], l2 = op_logits[t*K_SZ+2];
            float m = fmaxf(l0, fmaxf(l1, l2));
            float e0 = expf(l0 - m), e1 = expf(l1 - m), e2 = expf(l2 - m);
            float s = e0 + e1 + e2;
            float w0 = e0 / s, w1 = e1 / s, w2 = e2 / s;
            g_w[t*K_SZ+0] = w0; g_w[t*K_SZ+1] = w1; g_w[t*K_SZ+2] = w2;
            float mean = (w0 + w1 + w2) * (1.f / 3.f);
            float d0 = w0 - mean, d1 = w1 - mean, d2 = w2 - mean;
            g_conf[t] = sqrtf((d0*d0 + d1*d1 + d2*d2) * 0.5f);
            float sum = w0 + w1 + w2;
            float inv = 1.f / (sum + 1e-6f);
            float u0 = w0*inv, u1 = w1*inv, u2 = w2*inv;
            float ent = -(u0*logf(fmaxf(u0,1e-6f)) + u1*logf(fmaxf(u1,1e-6f)) + u2*logf(fmaxf(u2,1e-6f)));
            g_ent[t] = ent;
        }
    }
}

// ---------------- fused wsum + row stats: one block (128 thr) per row b ----------------
__device__ __forceinline__ float warp_sum(float v) {
#pragma unroll
    for (int o = 16; o > 0; o >>= 1) v += __shfl_down_sync(0xffffffffu, v, o);
    return v;
}

__global__ __launch_bounds__(128)
void wsum_stats(float* __restrict__ out_full, const float* __restrict__ noise)
{
    __shared__ float4 red[4];
    const int b = blockIdx.x;
    const int tid = threadIdx.x;
    const int t = b % T_SZ, g = b / T_SZ;

    float w0 = g_w[t*K_SZ+0], w1 = g_w[t*K_SZ+1], w2 = g_w[t*K_SZ+2];
    const float4* p0 = (const float4*)&g_h2[(((long)(t*K_SZ+0))*G_SZ + g)*H_SZ];
    const float4* p1 = (const float4*)&g_h2[(((long)(t*K_SZ+1))*G_SZ + g)*H_SZ];
    const float4* p2 = (const float4*)&g_h2[(((long)(t*K_SZ+2))*G_SZ + g)*H_SZ];
    float4 v0 = p0[tid], v1 = p1[tid], v2 = p2[tid];
    float4 o;
    o.x = w0*v0.x + w1*v1.x + w2*v2.x;
    o.y = w0*v0.y + w1*v1.y + w2*v2.y;
    o.z = w0*v0.z + w1*v1.z + w2*v2.z;
    o.w = w0*v0.w + w1*v1.w + w2*v2.w;

    const long rowbase = (long)b * H_SZ;
    ((float4*)&out_full[rowbase])[tid] = o;

    h16 h0,h1,h2v,h3,l0,l1,l2v,l3;
    split2h(o.x,h0,l0); split2h(o.y,h1,l1); split2h(o.z,h2v,l2v); split2h(o.w,h3,l3);
    __half2 a2,b2;
    a2.x=h0; a2.y=h1; b2.x=h2v; b2.y=h3;
    ((__half2*)&g_out_hi[rowbase])[tid*2] = a2;
    ((__half2*)&g_out_hi[rowbase])[tid*2+1] = b2;
    a2.x=l0; a2.y=l1; b2.x=l2v; b2.y=l3;
    ((__half2*)&g_out_lo[rowbase])[tid*2] = a2;
    ((__half2*)&g_out_lo[rowbase])[tid*2+1] = b2;

    float4 xv = ((const float4*)&g_xp[rowbase])[tid];
    float4 nv = ((const float4*)&noise[rowbase])[tid];
    float pe, nov, sp, pl, d;
    d = o.x - xv.x; pe  = d*d; nov  = xv.x*xv.x; sp  = fabsf(o.x);
    d = o.y - xv.y; pe += d*d; nov += xv.y*xv.y; sp += fabsf(o.y);
    d = o.z - xv.z; pe += d*d; nov += xv.z*xv.z; sp += fabsf(o.z);
    d = o.w - xv.w; pe += d*d; nov += xv.w*xv.w; sp += fabsf(o.w);
    float nx = nv.x*0.01f, ny = nv.y*0.01f, nz = nv.z*0.01f, nw = nv.w*0.01f;
    pl = nx*nx + ny*ny + nz*nz + nw*nw;

    pe = warp_sum(pe); nov = warp_sum(nov); sp = warp_sum(sp); pl = warp_sum(pl);
    const int lane = tid & 31, warp = tid >> 5;
    if (lane == 0) { float4 f; f.x=pe; f.y=nov; f.z=sp; f.w=pl; red[warp] = f; }
    __syncthreads();
    if (tid == 0) {
        float4 s = red[0];
        s.x += red[1].x + red[2].x + red[3].x;
        s.y += red[1].y + red[2].y + red[3].y;
        s.z += red[1].z + red[2].z + red[3].z;
        s.w += red[1].w + red[2].w + red[3].w;
        const float inv = 1.f / (float)H_SZ;
        g_pe[b]  = s.x * inv;
        g_nov[b] = s.y * inv;
        g_sp[b]  = s.z * inv;
        g_pl[b]  = s.w * inv;
    }
}

// ---------------- finalize (one block per t) ----------------
__device__ __forceinline__ float block_sum(float v, float* red, int tid) {
    red[tid] = v; __syncthreads();
    for (int s = 128; s > 0; s >>= 1) { if (tid < s) red[tid] += red[tid + s]; __syncthreads(); }
    float r = red[0]; __syncthreads();
    return r;
}

__global__ void finalize_kernel(const float* __restrict__ id_emb, const float* __restrict__ rW1,
                                const float* __restrict__ gW1, const float* __restrict__ gb1,
                                const float* __restrict__ gW2, const float* __restrict__ gb2,
                                float* __restrict__ decision)
{
    __shared__ float red[256];
    __shared__ float sig[7];
    __shared__ float gch[H_SZ];
    const int t = blockIdx.x, tid = threadIdx.x;

    float pe = 0.f, pe2 = 0.f, nov = 0.f, sp = 0.f, pl = 0.f;
    for (int g = tid; g < G_SZ; g += 256) {
        int b = g * T_SZ + t;
        float p = g_pe[b];
        pe += p; pe2 += p * p; nov += g_nov[b]; sp += g_sp[b]; pl += g_pl[b];
    }
    float S_pe  = block_sum(pe,  red, tid);
    float S_pe2 = block_sum(pe2, red, tid);
    float S_nov = block_sum(nov, red, tid);
    float S_sp  = block_sum(sp,  red, tid);
    float S_pl  = block_sum(pl,  red, tid);

    if (tid == 0) {
        const float invg = 1.f / (float)G_SZ;
        float pe_m = S_pe * invg, pe2_m = S_pe2 * invg;
        float c = 0.01f * pe_m;
        sig[0] = S_pl * invg;
        sig[1] = S_nov * invg;
        sig[2] = pe_m;
        sig[3] = g_ent[t];
        sig[4] = S_sp * invg;
        sig[5] = -pe_m;
        sig[6] = pe2_m - 2.f * c * pe_m + c * c;
    }
    __syncthreads();

    for (int i = tid; i < H_SZ; i += 256) {
        float a = gb1[t * H_SZ + i];
#pragma unroll
        for (int j = 0; j < 7; j++) a += gW1[((long)(t * H_SZ + i)) * 7 + j] * sig[j];
        gch[i] = fmaxf(a, 0.f);
    }
    __syncthreads();

    for (int o = 0; o < 2; o++) {
        float d = 0.f;
        for (int i = tid; i < H_SZ; i += 256) d += gW2[((long)(t * 2 + o)) * H_SZ + i] * gch[i];
        float S = block_sum(d, red, tid);
        if (tid == 0) decision[t * 2 + o] = S + gb2[t * 2 + o];
    }

    __shared__ float ext[7];
    if (tid == 0) {
        ext[0] = id_emb[t*4+0]; ext[1] = id_emb[t*4+1];
        ext[2] = id_emb[t*4+2]; ext[3] = id_emb[t*4+3];
        ext[4] = sig[1];
        ext[5] = g_conf[t];
        ext[6] = sig[2];
    }
    __syncthreads();
    for (int i = tid; i < H_SZ; i += 256) {
        float a = 0.f;
#pragma unroll
        for (int j = 0; j < 7; j++) a += ext[j] * rW1[(long)i * (H_SZ + 7) + H_SZ + j];
        g_extra[t * H_SZ + i] = a;
    }
}

// ---------------- logits ----------------
__global__ void logits_kernel(const float* __restrict__ rW2, const float* __restrict__ rb2,
                              float* __restrict__ logits)
{
    const int b = blockIdx.x;
    const int o = threadIdx.x >> 5, lane = threadIdx.x & 31;
    const float4* r = (const float4*)(g_rh + (long)b * H_SZ);
    const float4* wrow = (const float4*)(rW2 + (long)o * H_SZ);
    float acc = 0.f;
    for (int i = lane; i < H_SZ/4; i += 32) {
        float4 rv = r[i], wv = wrow[i];
        acc += rv.x*wv.x + rv.y*wv.y + rv.z*wv.z + rv.w*wv.w;
    }
    acc = warp_sum(acc);
    if (lane == 0) logits[(long)b * (T_SZ + 1) + o] = acc + rb2[o];
}

// ---------------- launch ----------------
extern "C" void kernel_launch(void* const* d_in, const int* in_sizes, int n_in,
                              void* d_out, int out_size)
{
    const float* x         = (const float*)d_in[0];
    const float* Wp        = (const float*)d_in[1];
    const float* bp        = (const float*)d_in[2];
    const float* opW1      = (const float*)d_in[3];
    const float* opb1      = (const float*)d_in[4];
    const float* opW2      = (const float*)d_in[5];
    const float* opb2      = (const float*)d_in[6];
    const float* op_logits = (const float*)d_in[7];
    const float* id_emb    = (const float*)d_in[8];
    const float* rW1       = (const float*)d_in[9];
    const float* rb1       = (const float*)d_in[10];
    const float* rW2       = (const float*)d_in[11];
    const float* rb2       = (const float*)d_in[12];
    const float* gW1       = (const float*)d_in[13];
    const float* gb1       = (const float*)d_in[14];
    const float* gW2       = (const float*)d_in[15];
    const float* gb2       = (const float*)d_in[16];
    const float* phW       = (const float*)d_in[17];
    const float* phb       = (const float*)d_in[18];
    const float* noise     = (const float*)d_in[19];

    float* out_full = (float*)d_out;
    float* logits   = out_full + (size_t)B_SZ * H_SZ;
    float* pred     = logits   + (size_t)B_SZ * (T_SZ + 1);
    float* decision = pred     + (size_t)B_SZ * D_SZ;

    float *xp, *h2, *extra, *rh;
    h16 *x_hi, *x_lo, *xp_hi, *xp_lo, *h1_hi, *h1_lo, *out_hi, *out_lo;
    h16 *Wp_h, *oW1_h, *oW2_h, *rW1c_h, *phW_h;
    cudaGetSymbolAddress((void**)&xp,      g_xp);
    cudaGetSymbolAddress((void**)&h2,      g_h2);
    cudaGetSymbolAddress((void**)&extra,   g_extra);
    cudaGetSymbolAddress((void**)&rh,      g_rh);
    cudaGetSymbolAddress((void**)&x_hi,    g_x_hi);    cudaGetSymbolAddress((void**)&x_lo,    g_x_lo);
    cudaGetSymbolAddress((void**)&xp_hi,   g_xp_hi);   cudaGetSymbolAddress((void**)&xp_lo,   g_xp_lo);
    cudaGetSymbolAddress((void**)&h1_hi,   g_h1_hi);   cudaGetSymbolAddress((void**)&h1_lo,   g_h1_lo);
    cudaGetSymbolAddress((void**)&out_hi,  g_out_hi);  cudaGetSymbolAddress((void**)&out_lo,  g_out_lo);
    cudaGetSymbolAddress((void**)&Wp_h,    g_Wp_h);
    cudaGetSymbolAddress((void**)&oW1_h,   g_oW1_h);
    cudaGetSymbolAddress((void**)&oW2_h,   g_oW2_h);
    cudaGetSymbolAddress((void**)&rW1c_h,  g_rW1c_h);
    cudaGetSymbolAddress((void**)&phW_h,   g_phW_h);

    cudaFuncSetAttribute(gemm2, cudaFuncAttributeMaxDynamicSharedMemorySize,
                         NSTAGE * (int)STAGE_BYTES);
    const int SM = NSTAGE * (int)STAGE_BYTES;

    // (1) all conversions + softmax fused
    prep_kernel<<<PREP_BLOCKS, 256>>>(x, Wp, opW1, opW2, phW, rW1, op_logits);

    // (2) xp = x @ Wp^T + bp          (fp32 + hi/lo out)
    gemm2<<<dim3(H_SZ/GBN, B_SZ/GBM, 1), 256, SM>>>(
        x_hi, x_lo, D_SZ, 0, 0, 1,
        Wp_h, D_SZ, 0,
        bp, 0, nullptr,
        xp, xp_hi, xp_lo, H_SZ, 0, 0, H_SZ, D_SZ, 0);

    // (3) h1[t,k] = relu(xg[t] @ opW1[t,k]^T + opb1)   (A scattered; hi/lo out only)
    gemm2<<<dim3(H_SZ/GBN, G_SZ/GBM, T_SZ*K_SZ), 256, SM>>>(
        xp_hi, xp_lo, H_SZ, 0, T_SZ, K_SZ,
        oW1_h, H_SZ, (long)H_SZ*H_SZ,
        opb1, H_SZ, nullptr,
        nullptr, h1_hi, h1_lo, H_SZ, (long)G_SZ*H_SZ, 0, H_SZ, H_SZ, 1);

    // (4) h2[t,k] = relu(h1[t,k] @ opW2[t,k]^T + opb2)   (fp32 out only)  [profiled]
    gemm2<<<dim3(H_SZ/GBN, G_SZ/GBM, T_SZ*K_SZ), 256, SM>>>(
        h1_hi, h1_lo, H_SZ, (long)G_SZ*H_SZ, 0, 1,
        oW2_h, H_SZ, (long)H_SZ*H_SZ,
        opb2, H_SZ, nullptr,
        h2, nullptr, nullptr, H_SZ, (long)G_SZ*H_SZ, 0, H_SZ, H_SZ, 1);

    // (5) fused weighted mixture + per-row stats
    wsum_stats<<<B_SZ, 128>>>(out_full, noise);

    // (6) signals, decision, routing extra bias
    finalize_kernel<<<T_SZ, 256>>>(id_emb, rW1, gW1, gb1, gW2, gb2, decision);

    // (7) rh = relu(out @ rW1[:, :H]^T + c_extra[t] + rb1)   (A & C rows scattered)
    gemm2<<<dim3(H_SZ/GBN, G_SZ/GBM, T_SZ), 256, SM>>>(
        out_hi, out_lo, H_SZ, 0, T_SZ, 1,
        rW1c_h, H_SZ, 0,
        rb1, 0, extra,
        rh, nullptr, nullptr, H_SZ, 0, T_SZ, H_SZ, H_SZ, 1);

    // (8) logits = rh @ rW2^T + rb2
    logits_kernel<<<B_SZ, (T_SZ + 1) * 32>>>(rW2, rb2, logits);

    // (9) pred = out_full @ phW^T + phb
    gemm2<<<dim3(D_SZ/GBN, B_SZ/GBM, 1), 256, SM>>>(
        out_hi, out_lo, H_SZ, 0, 0, 1,
        phW_h, H_SZ, 0,
        phb, 0, nullptr,
        pred, nullptr, nullptr, D_SZ, 0, 0, D_SZ, H_SZ, 0);
}

// round 16
// speedup vs baseline: 3.7734x; 1.0293x over previous
#include <cuda_runtime.h>
#include <cuda_fp16.h>
#include <stdint.h>
#include <math.h>

typedef __half h16;

#define B_SZ 12288
#define D_SZ 1024
#define H_SZ 512
#define T_SZ 12
#define K_SZ 3
#define G_SZ 1024   // B_SZ / T_SZ

// ---------------- fp32 scratch ----------------
__device__ float g_xp[(size_t)B_SZ * H_SZ];
__device__ float g_h2[(size_t)T_SZ * K_SZ * G_SZ * H_SZ];
__device__ float g_rh[(size_t)B_SZ * H_SZ];
__device__ float g_w[T_SZ * K_SZ];
__device__ float g_conf[T_SZ];
__device__ float g_ent[T_SZ];
__device__ float g_pe[B_SZ];
__device__ float g_nov[B_SZ];
__device__ float g_sp[B_SZ];
__device__ float g_pl[B_SZ];
__device__ float g_extra[T_SZ * H_SZ];

// ---------------- fp16 scratch: A-side hi/lo pairs, B-side single ----------------
__device__ __align__(16) h16 g_x_hi[(size_t)B_SZ * D_SZ];
__device__ __align__(16) h16 g_x_lo[(size_t)B_SZ * D_SZ];
__device__ __align__(16) h16 g_xp_hi[(size_t)B_SZ * H_SZ];
__device__ __align__(16) h16 g_xp_lo[(size_t)B_SZ * H_SZ];
__device__ __align__(16) h16 g_h1_hi[(size_t)T_SZ * K_SZ * G_SZ * H_SZ];
__device__ __align__(16) h16 g_h1_lo[(size_t)T_SZ * K_SZ * G_SZ * H_SZ];
__device__ __align__(16) h16 g_out_hi[(size_t)B_SZ * H_SZ];
__device__ __align__(16) h16 g_out_lo[(size_t)B_SZ * H_SZ];
__device__ __align__(16) h16 g_Wp_h[(size_t)H_SZ * D_SZ];
__device__ __align__(16) h16 g_oW1_h[(size_t)T_SZ * K_SZ * H_SZ * H_SZ];
__device__ __align__(16) h16 g_oW2_h[(size_t)T_SZ * K_SZ * H_SZ * H_SZ];
__device__ __align__(16) h16 g_rW1c_h[(size_t)H_SZ * H_SZ];
__device__ __align__(16) h16 g_phW_h[(size_t)D_SZ * H_SZ];

// ---------------- helpers ----------------
__device__ __forceinline__ void split2h(float v, h16& h, h16& l) {
    h = __float2half_rn(v);
    l = __float2half_rn(v - __half2float(h));
}

__device__ __forceinline__ void mma16816(float* c, const unsigned* a, const unsigned* b) {
    asm volatile(
        "mma.sync.aligned.m16n8k16.row.col.f32.f16.f16.f32 "
        "{%0,%1,%2,%3},{%4,%5,%6,%7},{%8,%9},{%0,%1,%2,%3};"
        : "+f"(c[0]), "+f"(c[1]), "+f"(c[2]), "+f"(c[3])
        : "r"(a[0]), "r"(a[1]), "r"(a[2]), "r"(a[3]), "r"(b[0]), "r"(b[1]));
}

#define LDMX4(R_, ADDR_)                                                      \
    asm volatile("ldmatrix.sync.aligned.m8n8.x4.shared.b16 {%0,%1,%2,%3},[%4];" \
                 : "=r"((R_)[0]), "=r"((R_)[1]), "=r"((R_)[2]), "=r"((R_)[3]) \
                 : "r"(ADDR_))

#define LDMX2(R_, ADDR_)                                                      \
    asm volatile("ldmatrix.sync.aligned.m8n8.x2.shared.b16 {%0,%1},[%2];"     \
                 : "=r"((R_)[0]), "=r"((R_)[1]) : "r"(ADDR_))

#define CPA(DST_, SRC_)                                                       \
    asm volatile("cp.async.cg.shared.global [%0],[%1],16;" :: "r"(DST_), "l"(SRC_))

#define CP_COMMIT asm volatile("cp.async.commit_group;")
#define CP_WAIT1  asm volatile("cp.async.wait_group 1;")
#define CP_WAIT0  asm volatile("cp.async.wait_group 0;")

// ---------------- fp16 2-product tensor-core GEMM: C = A @ B^T (+bias)(+extra)(relu) ----
// A_hi/lo [M, lda] fp16 row-major (k contig) — exact split pair.
// B [N, ldb] single fp16 row-major (k contig).
// a_scatter/c_scatter: logical row r -> global row r*scatter + tcur, tcur = z / t_div.
// BM=BN=128, BK=64 (4 ksteps), 256 threads (8 warps 2x4, warp tile 64x32).
// 2-stage cp.async pipeline; SROW=72 (144B rows: 16B-aligned, ldsm conflict-free:
// 144 mod 128 = 16 -> 8 rows map to 8 distinct 16B slices).
#define GBM 128
#define GBN 128
#define GBK 64
#define SROW 72
#define TILE_BYTES 18432u                 // 128 rows * 72 el * 2 B
#define STAGE_BYTES (3u * TILE_BYTES)     // Ahi, Alo, B = 55296 B
#define NSTAGE 2

// Loader: 12 chunks of 16B per thread (4 per tile). chunk c covers row rBase+32*c,
// byte column cc*16. Source pointers advance linearly: aStep/bStep per c.
#define LOAD_STAGE(S_, KB_) do {                                              \
    uint32_t base_ = smem_u32 + (uint32_t)(S_) * STAGE_BYTES;                 \
    _Pragma("unroll")                                                         \
    for (int c_ = 0; c_ < 4; c_++) {                                          \
        uint32_t so_ = sOffA + (uint32_t)c_ * 4608u;                          \
        CPA(base_ +                 so_, pAh + (KB_) + c_ * aStep);           \
        CPA(base_ + TILE_BYTES    + so_, pAl + (KB_) + c_ * aStep);          \
        CPA(base_ + 2u*TILE_BYTES + so_, pB  + (KB_) + c_ * bStep);          \
    }                                                                         \
} while (0)

__global__ __launch_bounds__(256, 2)
void gemm2(const h16* __restrict__ Ah, const h16* __restrict__ Al,
           int lda, long a_bstride, int a_scatter, int t_div,
           const h16* __restrict__ Bm,
           int ldb, long b_bstride,
           const float* __restrict__ bias, long bias_bstride,
           const float* __restrict__ extra,
           float* __restrict__ C, h16* __restrict__ Chi, h16* __restrict__ Clo,
           int ldc, long c_bstride, int c_scatter,
           int N, int Kdim, int do_relu)
{
    extern __shared__ __align__(16) char smem_raw[];
    uint32_t smem_u32 = (uint32_t)__cvta_generic_to_shared(smem_raw);

    const int tid  = threadIdx.x;
    const int z    = blockIdx.z;
    const int tcur = z / t_div;
    const int brow = blockIdx.y * GBM;
    const int bcol = blockIdx.x * GBN;

    // ---- loader setup ----
    const int rBase = tid >> 3;           // 0..31
    const int cc    = tid & 7;            // 16B chunk within row
    long arow = brow + rBase;
    if (a_scatter) arow = arow * a_scatter + tcur;
    const long aStep = 32L * (a_scatter ? a_scatter : 1) * lda;
    const long bStep = 32L * ldb;
    const h16* pAh = Ah + z * a_bstride + arow * (long)lda + cc * 8;
    const h16* pAl = Al + z * a_bstride + arow * (long)lda + cc * 8;
    const h16* pB  = Bm + z * b_bstride + (long)(bcol + rBase) * ldb + cc * 8;
    const uint32_t sOffA = (uint32_t)(rBase * SROW + cc * 8) * 2u;

    // ---- fragment-load setup ----
    const int lane = tid & 31;
    const int warp = tid >> 5;
    const int wm = (warp & 1) * 64;
    const int wn = (warp >> 1) * 32;
    const int aMat = lane >> 3, aR = lane & 7;
    const uint32_t aOff = (uint32_t)((wm + (aMat & 1) * 8 + aR) * SROW + (aMat >> 1) * 8) * 2u;
    const int bL = lane & 15;
    const uint32_t bOff = (uint32_t)((wn + (bL & 7)) * SROW + ((bL >> 3) & 1) * 8) * 2u;

    float acc[4][4][4];
#pragma unroll
    for (int i = 0; i < 4; i++)
#pragma unroll
        for (int j = 0; j < 4; j++)
#pragma unroll
            for (int q = 0; q < 4; q++) acc[i][j][q] = 0.f;

    const int nIter = Kdim / GBK;        // >= 8 for all shapes
    LOAD_STAGE(0, 0);
    CP_COMMIT;
    LOAD_STAGE(1, GBK);
    CP_COMMIT;

    for (int it = 0; it < nIter; ++it) {
        if (it < nIter - 1) { CP_WAIT1; } else { CP_WAIT0; }
        __syncthreads();

        const uint32_t baseA_hi = smem_u32 + (uint32_t)(it & 1) * STAGE_BYTES;
        const uint32_t baseA_lo = baseA_hi + TILE_BYTES;
        const uint32_t baseB    = baseA_hi + 2u * TILE_BYTES;

#pragma unroll
        for (int kk = 0; kk < 4; kk++) {
            const uint32_t kkb = (uint32_t)kk * 32u;  // 16 cols * 2 B
            unsigned bh[4][2];
#pragma unroll
            for (int j = 0; j < 4; j++)
                LDMX2(bh[j], baseB + bOff + (uint32_t)j * 1152u + kkb);

            unsigned ah[2][4], al[2][4];
            LDMX4(ah[0], baseA_hi + aOff + kkb);
            LDMX4(al[0], baseA_lo + aOff + kkb);
#pragma unroll
            for (int i = 0; i < 4; i++) {
                const int cur = i & 1, nxt = cur ^ 1;
                if (i < 3) {
                    LDMX4(ah[nxt], baseA_hi + aOff + (uint32_t)(i + 1) * 2304u + kkb);
                    LDMX4(al[nxt], baseA_lo + aOff + (uint32_t)(i + 1) * 2304u + kkb);
                }
#pragma unroll
                for (int j = 0; j < 4; j++) {
                    mma16816(acc[i][j], ah[cur], bh[j]);
                    mma16816(acc[i][j], al[cur], bh[j]);
                }
            }
        }

        if (it + 2 < nIter) {
            __syncthreads();   // all warps done reading stage (it&1) before refill
            LOAD_STAGE(it & 1, (long)(it + 2) * GBK);
            CP_COMMIT;
        }
    }

    // ---- epilogue ----
    const float* biasb = bias ? bias + (long)z * bias_bstride : nullptr;
    const int g4 = lane >> 2, t4 = lane & 3;
#pragma unroll
    for (int i = 0; i < 4; i++) {
#pragma unroll
        for (int half_ = 0; half_ < 2; half_++) {
            int m_local = wm + i * 16 + g4 + half_ * 8;
            long crow = brow + m_local;
            if (c_scatter) crow = crow * c_scatter + tcur;
            long rbase = (long)z * c_bstride + crow * (long)ldc;
#pragma unroll
            for (int j = 0; j < 4; j++) {
                int n_local = wn + j * 8 + t4 * 2;
                int n = bcol + n_local;
                float v0 = acc[i][j][half_ * 2 + 0];
                float v1 = acc[i][j][half_ * 2 + 1];
                if (biasb) { v0 += biasb[n]; v1 += biasb[n + 1]; }
                if (extra) { v0 += extra[tcur * N + n]; v1 += extra[tcur * N + n + 1]; }
                if (do_relu) { v0 = fmaxf(v0, 0.f); v1 = fmaxf(v1, 0.f); }
                if (C) {
                    float2 f2; f2.x = v0; f2.y = v1;
                    *(float2*)(C + rbase + n) = f2;
                }
                if (Chi) {
                    h16 h0, l0, h1, l1;
                    split2h(v0, h0, l0); split2h(v1, h1, l1);
                    __half2 ph; ph.x = h0; ph.y = h1;
                    __half2 pl; pl.x = l0; pl.y = l1;
                    *(__half2*)(Chi + rbase + n) = ph;
                    *(__half2*)(Clo + rbase + n) = pl;
                }
            }
        }
    }
}

// ---------------- prep: all conversions + rW1 extract + softmax in ONE kernel ----------
#define SEG_X   6144
#define SEG_WP  (SEG_X + 256)
#define SEG_W1  (SEG_WP + 4608)
#define SEG_W2  (SEG_W1 + 4608)
#define SEG_PH  (SEG_W2 + 256)
#define SEG_RW  (SEG_PH + 128)
#define PREP_BLOCKS (SEG_RW + 1)

__device__ __forceinline__ void conv_split_f4(const float4* in, __half2* hi, __half2* lo, long i) {
    float4 v = in[i];
    h16 h0,h1,h2,h3,l0,l1,l2,l3;
    split2h(v.x,h0,l0); split2h(v.y,h1,l1); split2h(v.z,h2,l2); split2h(v.w,h3,l3);
    __half2 a,b;
    a.x=h0; a.y=h1; b.x=h2; b.y=h3; hi[i*2]=a; hi[i*2+1]=b;
    a.x=l0; a.y=l1; b.x=l2; b.y=l3; lo[i*2]=a; lo[i*2+1]=b;
}
__device__ __forceinline__ void conv_h_f4(const float4* in, __half2* out, long i) {
    float4 v = in[i];
    __half2 a,b;
    a.x=__float2half_rn(v.x); a.y=__float2half_rn(v.y);
    b.x=__float2half_rn(v.z); b.y=__float2half_rn(v.w);
    out[i*2]=a; out[i*2+1]=b;
}

__global__ void prep_kernel(const float* __restrict__ x, const float* __restrict__ Wp,
                            const float* __restrict__ opW1, const float* __restrict__ opW2,
                            const float* __restrict__ phW, const float* __restrict__ rW1,
                            const float* __restrict__ op_logits)
{
    const int b = blockIdx.x, tid = threadIdx.x;
    if (b < SEG_X) {
        long i0 = (long)b * 512 + tid;
        conv_split_f4((const float4*)x, (__half2*)g_x_hi, (__half2*)g_x_lo, i0);
        conv_split_f4((const float4*)x, (__half2*)g_x_hi, (__half2*)g_x_lo, i0 + 256);
    } else if (b < SEG_WP) {
        long i0 = (long)(b - SEG_X) * 512 + tid;
        conv_h_f4((const float4*)Wp, (__half2*)g_Wp_h, i0);
        conv_h_f4((const float4*)Wp, (__half2*)g_Wp_h, i0 + 256);
    } else if (b < SEG_W1) {
        long i0 = (long)(b - SEG_WP) * 512 + tid;
        conv_h_f4((const float4*)opW1, (__half2*)g_oW1_h, i0);
        conv_h_f4((const float4*)opW1, (__half2*)g_oW1_h, i0 + 256);
    } else if (b < SEG_W2) {
        long i0 = (long)(b - SEG_W1) * 512 + tid;
        conv_h_f4((const float4*)opW2, (__half2*)g_oW2_h, i0);
        conv_h_f4((const float4*)opW2, (__half2*)g_oW2_h, i0 + 256);
    } else if (b < SEG_PH) {
        long i0 = (long)(b - SEG_W2) * 512 + tid;
        conv_h_f4((const float4*)phW, (__half2*)g_phW_h, i0);
        conv_h_f4((const float4*)phW, (__half2*)g_phW_h, i0 + 256);
    } else if (b < SEG_RW) {
        int base = (b - SEG_PH) * 2048 + tid * 8;
#pragma unroll
        for (int e = 0; e < 8; e++) {
            int idx = base + e;
            int i = idx >> 9, j = idx & 511;
            g_rW1c_h[idx] = __float2half_rn(rW1[(long)i * (H_SZ + 7) + j]);
        }
    } else {
        int t = tid;
        if (t < T_SZ) {
            float l0 = op_logits[t*K_SZ+0], l1 = op_logits[t*K_SZ+1], l2 = op_logits[t*K_SZ+2];
            float m = fmaxf(l0, fmaxf(l1, l2));
            float e0 = expf(l0 - m), e1 = expf(l1 - m), e2 = expf(l2 - m);
            float s = e0 + e1 + e2;
            float w0 = e0 / s, w1 = e1 / s, w2 = e2 / s;
            g_w[t*K_SZ+0] = w0; g_w[t*K_SZ+1] = w1; g_w[t*K_SZ+2] = w2;
            float mean = (w0 + w1 + w2) * (1.f / 3.f);
            float d0 = w0 - mean, d1 = w1 - mean, d2 = w2 - mean;
            g_conf[t] = sqrtf((d0*d0 + d1*d1 + d2*d2) * 0.5f);
            float sum = w0 + w1 + w2;
            float inv = 1.f / (sum + 1e-6f);
            float u0 = w0*inv, u1 = w1*inv, u2 = w2*inv;
            float ent = -(u0*logf(fmaxf(u0,1e-6f)) + u1*logf(fmaxf(u1,1e-6f)) + u2*logf(fmaxf(u2,1e-6f)));
            g_ent[t] = ent;
        }
    }
}

// ---------------- fused wsum + row stats: one block (128 thr) per row b ----------------
__device__ __forceinline__ float warp_sum(float v) {
#pragma unroll
    for (int o = 16; o > 0; o >>= 1) v += __shfl_down_sync(0xffffffffu, v, o);
    return v;
}

__global__ __launch_bounds__(128)
void wsum_stats(float* __restrict__ out_full, const float* __restrict__ noise)
{
    __shared__ float4 red[4];
    const int b = blockIdx.x;
    const int tid = threadIdx.x;
    const int t = b % T_SZ, g = b / T_SZ;

    float w0 = g_w[t*K_SZ+0], w1 = g_w[t*K_SZ+1], w2 = g_w[t*K_SZ+2];
    const float4* p0 = (const float4*)&g_h2[(((long)(t*K_SZ+0))*G_SZ + g)*H_SZ];
    const float4* p1 = (const float4*)&g_h2[(((long)(t*K_SZ+1))*G_SZ + g)*H_SZ];
    const float4* p2 = (const float4*)&g_h2[(((long)(t*K_SZ+2))*G_SZ + g)*H_SZ];
    float4 v0 = p0[tid], v1 = p1[tid], v2 = p2[tid];
    float4 o;
    o.x = w0*v0.x + w1*v1.x + w2*v2.x;
    o.y = w0*v0.y + w1*v1.y + w2*v2.y;
    o.z = w0*v0.z + w1*v1.z + w2*v2.z;
    o.w = w0*v0.w + w1*v1.w + w2*v2.w;

    const long rowbase = (long)b * H_SZ;
    ((float4*)&out_full[rowbase])[tid] = o;

    h16 h0,h1,h2v,h3,l0,l1,l2v,l3;
    split2h(o.x,h0,l0); split2h(o.y,h1,l1); split2h(o.z,h2v,l2v); split2h(o.w,h3,l3);
    __half2 a2,b2;
    a2.x=h0; a2.y=h1; b2.x=h2v; b2.y=h3;
    ((__half2*)&g_out_hi[rowbase])[tid*2] = a2;
    ((__half2*)&g_out_hi[rowbase])[tid*2+1] = b2;
    a2.x=l0; a2.y=l1; b2.x=l2v; b2.y=l3;
    ((__half2*)&g_out_lo[rowbase])[tid*2] = a2;
    ((__half2*)&g_out_lo[rowbase])[tid*2+1] = b2;

    float4 xv = ((const float4*)&g_xp[rowbase])[tid];
    float4 nv = ((const float4*)&noise[rowbase])[tid];
    float pe, nov, sp, pl, d;
    d = o.x - xv.x; pe  = d*d; nov  = xv.x*xv.x; sp  = fabsf(o.x);
    d = o.y - xv.y; pe += d*d; nov += xv.y*xv.y; sp += fabsf(o.y);
    d = o.z - xv.z; pe += d*d; nov += xv.z*xv.z; sp += fabsf(o.z);
    d = o.w - xv.w; pe += d*d; nov += xv.w*xv.w; sp += fabsf(o.w);
    float nx = nv.x*0.01f, ny = nv.y*0.01f, nz = nv.z*0.01f, nw = nv.w*0.01f;
    pl = nx*nx + ny*ny + nz*nz + nw*nw;

    pe = warp_sum(pe); nov = warp_sum(nov); sp = warp_sum(sp); pl = warp_sum(pl);
    const int lane = tid & 31, warp = tid >> 5;
    if (lane == 0) { float4 f; f.x=pe; f.y=nov; f.z=sp; f.w=pl; red[warp] = f; }
    __syncthreads();
    if (tid == 0) {
        float4 s = red[0];
        s.x += red[1].x + red[2].x + red[3].x;
        s.y += red[1].y + red[2].y + red[3].y;
        s.z += red[1].z + red[2].z + red[3].z;
        s.w += red[1].w + red[2].w + red[3].w;
        const float inv = 1.f / (float)H_SZ;
        g_pe[b]  = s.x * inv;
        g_nov[b] = s.y * inv;
        g_sp[b]  = s.z * inv;
        g_pl[b]  = s.w * inv;
    }
}

// ---------------- finalize (one block per t) ----------------
__device__ __forceinline__ float block_sum(float v, float* red, int tid) {
    red[tid] = v; __syncthreads();
    for (int s = 128; s > 0; s >>= 1) { if (tid < s) red[tid] += red[tid + s]; __syncthreads(); }
    float r = red[0]; __syncthreads();
    return r;
}

__global__ void finalize_kernel(const float* __restrict__ id_emb, const float* __restrict__ rW1,
                                const float* __restrict__ gW1, const float* __restrict__ gb1,
                                const float* __restrict__ gW2, const float* __restrict__ gb2,
                                float* __restrict__ decision)
{
    __shared__ float red[256];
    __shared__ float sig[7];
    __shared__ float gch[H_SZ];
    const int t = blockIdx.x, tid = threadIdx.x;

    float pe = 0.f, pe2 = 0.f, nov = 0.f, sp = 0.f, pl = 0.f;
    for (int g = tid; g < G_SZ; g += 256) {
        int b = g * T_SZ + t;
        float p = g_pe[b];
        pe += p; pe2 += p * p; nov += g_nov[b]; sp += g_sp[b]; pl += g_pl[b];
    }
    float S_pe  = block_sum(pe,  red, tid);
    float S_pe2 = block_sum(pe2, red, tid);
    float S_nov = block_sum(nov, red, tid);
    float S_sp  = block_sum(sp,  red, tid);
    float S_pl  = block_sum(pl,  red, tid);

    if (tid == 0) {
        const float invg = 1.f / (float)G_SZ;
        float pe_m = S_pe * invg, pe2_m = S_pe2 * invg;
        float c = 0.01f * pe_m;
        sig[0] = S_pl * invg;
        sig[1] = S_nov * invg;
        sig[2] = pe_m;
        sig[3] = g_ent[t];
        sig[4] = S_sp * invg;
        sig[5] = -pe_m;
        sig[6] = pe2_m - 2.f * c * pe_m + c * c;
    }
    __syncthreads();

    for (int i = tid; i < H_SZ; i += 256) {
        float a = gb1[t * H_SZ + i];
#pragma unroll
        for (int j = 0; j < 7; j++) a += gW1[((long)(t * H_SZ + i)) * 7 + j] * sig[j];
        gch[i] = fmaxf(a, 0.f);
    }
    __syncthreads();

    for (int o = 0; o < 2; o++) {
        float d = 0.f;
        for (int i = tid; i < H_SZ; i += 256) d += gW2[((long)(t * 2 + o)) * H_SZ + i] * gch[i];
        float S = block_sum(d, red, tid);
        if (tid == 0) decision[t * 2 + o] = S + gb2[t * 2 + o];
    }

    __shared__ float ext[7];
    if (tid == 0) {
        ext[0] = id_emb[t*4+0]; ext[1] = id_emb[t*4+1];
        ext[2] = id_emb[t*4+2]; ext[3] = id_emb[t*4+3];
        ext[4] = sig[1];
        ext[5] = g_conf[t];
        ext[6] = sig[2];
    }
    __syncthreads();
    for (int i = tid; i < H_SZ; i += 256) {
        float a = 0.f;
#pragma unroll
        for (int j = 0; j < 7; j++) a += ext[j] * rW1[(long)i * (H_SZ + 7) + H_SZ + j];
        g_extra[t * H_SZ + i] = a;
    }
}

// ---------------- logits ----------------
__global__ void logits_kernel(const float* __restrict__ rW2, const float* __restrict__ rb2,
                              float* __restrict__ logits)
{
    const int b = blockIdx.x;
    const int o = threadIdx.x >> 5, lane = threadIdx.x & 31;
    const float4* r = (const float4*)(g_rh + (long)b * H_SZ);
    const float4* wrow = (const float4*)(rW2 + (long)o * H_SZ);
    float acc = 0.f;
    for (int i = lane; i < H_SZ/4; i += 32) {
        float4 rv = r[i], wv = wrow[i];
        acc += rv.x*wv.x + rv.y*wv.y + rv.z*wv.z + rv.w*wv.w;
    }
    acc = warp_sum(acc);
    if (lane == 0) logits[(long)b * (T_SZ + 1) + o] = acc + rb2[o];
}

// ---------------- launch ----------------
extern "C" void kernel_launch(void* const* d_in, const int* in_sizes, int n_in,
                              void* d_out, int out_size)
{
    const float* x         = (const float*)d_in[0];
    const float* Wp        = (const float*)d_in[1];
    const float* bp        = (const float*)d_in[2];
    const float* opW1      = (const float*)d_in[3];
    const float* opb1      = (const float*)d_in[4];
    const float* opW2      = (const float*)d_in[5];
    const float* opb2      = (const float*)d_in[6];
    const float* op_logits = (const float*)d_in[7];
    const float* id_emb    = (const float*)d_in[8];
    const float* rW1       = (const float*)d_in[9];
    const float* rb1       = (const float*)d_in[10];
    const float* rW2       = (const float*)d_in[11];
    const float* rb2       = (const float*)d_in[12];
    const float* gW1       = (const float*)d_in[13];
    const float* gb1       = (const float*)d_in[14];
    const float* gW2       = (const float*)d_in[15];
    const float* gb2       = (const float*)d_in[16];
    const float* phW       = (const float*)d_in[17];
    const float* phb       = (const float*)d_in[18];
    const float* noise     = (const float*)d_in[19];

    float* out_full = (float*)d_out;
    float* logits   = out_full + (size_t)B_SZ * H_SZ;
    float* pred     = logits   + (size_t)B_SZ * (T_SZ + 1);
    float* decision = pred     + (size_t)B_SZ * D_SZ;

    float *xp, *h2, *extra, *rh;
    h16 *x_hi, *x_lo, *xp_hi, *xp_lo, *h1_hi, *h1_lo, *out_hi, *out_lo;
    h16 *Wp_h, *oW1_h, *oW2_h, *rW1c_h, *phW_h;
    cudaGetSymbolAddress((void**)&xp,      g_xp);
    cudaGetSymbolAddress((void**)&h2,      g_h2);
    cudaGetSymbolAddress((void**)&extra,   g_extra);
    cudaGetSymbolAddress((void**)&rh,      g_rh);
    cudaGetSymbolAddress((void**)&x_hi,    g_x_hi);    cudaGetSymbolAddress((void**)&x_lo,    g_x_lo);
    cudaGetSymbolAddress((void**)&xp_hi,   g_xp_hi);   cudaGetSymbolAddress((void**)&xp_lo,   g_xp_lo);
    cudaGetSymbolAddress((void**)&h1_hi,   g_h1_hi);   cudaGetSymbolAddress((void**)&h1_lo,   g_h1_lo);
    cudaGetSymbolAddress((void**)&out_hi,  g_out_hi);  cudaGetSymbolAddress((void**)&out_lo,  g_out_lo);
    cudaGetSymbolAddress((void**)&Wp_h,    g_Wp_h);
    cudaGetSymbolAddress((void**)&oW1_h,   g_oW1_h);
    cudaGetSymbolAddress((void**)&oW2_h,   g_oW2_h);
    cudaGetSymbolAddress((void**)&rW1c_h,  g_rW1c_h);
    cudaGetSymbolAddress((void**)&phW_h,   g_phW_h);

    cudaFuncSetAttribute(gemm2, cudaFuncAttributeMaxDynamicSharedMemorySize,
                         NSTAGE * (int)STAGE_BYTES);
    const int SM = NSTAGE * (int)STAGE_BYTES;

    // (1) all conversions + softmax fused
    prep_kernel<<<PREP_BLOCKS, 256>>>(x, Wp, opW1, opW2, phW, rW1, op_logits);

    // (2) xp = x @ Wp^T + bp          (fp32 + hi/lo out)
    gemm2<<<dim3(H_SZ/GBN, B_SZ/GBM, 1), 256, SM>>>(
        x_hi, x_lo, D_SZ, 0, 0, 1,
        Wp_h, D_SZ, 0,
        bp, 0, nullptr,
        xp, xp_hi, xp_lo, H_SZ, 0, 0, H_SZ, D_SZ, 0);

    // (3) h1[t,k] = relu(xg[t] @ opW1[t,k]^T + opb1)   (A scattered; hi/lo out only)
    gemm2<<<dim3(H_SZ/GBN, G_SZ/GBM, T_SZ*K_SZ), 256, SM>>>(
        xp_hi, xp_lo, H_SZ, 0, T_SZ, K_SZ,
        oW1_h, H_SZ, (long)H_SZ*H_SZ,
        opb1, H_SZ, nullptr,
        nullptr, h1_hi, h1_lo, H_SZ, (long)G_SZ*H_SZ, 0, H_SZ, H_SZ, 1);

    // (4) h2[t,k] = relu(h1[t,k] @ opW2[t,k]^T + opb2)   (fp32 out only)  [profiled]
    gemm2<<<dim3(H_SZ/GBN, G_SZ/GBM, T_SZ*K_SZ), 256, SM>>>(
        h1_hi, h1_lo, H_SZ, (long)G_SZ*H_SZ, 0, 1,
        oW2_h, H_SZ, (long)H_SZ*H_SZ,
        opb2, H_SZ, nullptr,
        h2, nullptr, nullptr, H_SZ, (long)G_SZ*H_SZ, 0, H_SZ, H_SZ, 1);

    // (5) fused weighted mixture + per-row stats
    wsum_stats<<<B_SZ, 128>>>(out_full, noise);

    // (6) signals, decision, routing extra bias
    finalize_kernel<<<T_SZ, 256>>>(id_emb, rW1, gW1, gb1, gW2, gb2, decision);

    // (7) rh = relu(out @ rW1[:, :H]^T + c_extra[t] + rb1)   (A & C rows scattered)
    gemm2<<<dim3(H_SZ/GBN, G_SZ/GBM, T_SZ), 256, SM>>>(
        out_hi, out_lo, H_SZ, 0, T_SZ, 1,
        rW1c_h, H_SZ, 0,
        rb1, 0, extra,
        rh, nullptr, nullptr, H_SZ, 0, T_SZ, H_SZ, H_SZ, 1);

    // (8) logits = rh @ rW2^T + rb2
    logits_kernel<<<B_SZ, (T_SZ + 1) * 32>>>(rW2, rb2, logits);

    // (9) pred = out_full @ phW^T + phb
    gemm2<<<dim3(D_SZ/GBN, B_SZ/GBM, 1), 256, SM>>>(
        out_hi, out_lo, H_SZ, 0, 0, 1,
        phW_h, H_SZ, 0,
        phb, 0, nullptr,
        pred, nullptr, nullptr, D_SZ, 0, 0, D_SZ, H_SZ, 0);
}

// round 17
// speedup vs baseline: 3.7916x; 1.0048x over previous
#include <cuda_runtime.h>
#include <cuda_fp16.h>
#include <stdint.h>
#include <math.h>

typedef __half h16;

#define B_SZ 12288
#define D_SZ 1024
#define H_SZ 512
#define T_SZ 12
#define K_SZ 3
#define G_SZ 1024   // B_SZ / T_SZ

// ---------------- fp32 scratch ----------------
__device__ float g_xp[(size_t)B_SZ * H_SZ];
__device__ float g_h2[(size_t)T_SZ * K_SZ * G_SZ * H_SZ];
__device__ float g_rh[(size_t)B_SZ * H_SZ];
__device__ float g_w[T_SZ * K_SZ];
__device__ float g_conf[T_SZ];
__device__ float g_ent[T_SZ];
__device__ float g_pe[B_SZ];
__device__ float g_nov[B_SZ];
__device__ float g_sp[B_SZ];
__device__ float g_pl[B_SZ];
__device__ float g_extra[T_SZ * H_SZ];

// ---------------- fp16 scratch: A-side hi/lo pairs, B-side single ----------------
__device__ __align__(16) h16 g_x_hi[(size_t)B_SZ * D_SZ];
__device__ __align__(16) h16 g_x_lo[(size_t)B_SZ * D_SZ];
__device__ __align__(16) h16 g_xp_hi[(size_t)B_SZ * H_SZ];
__device__ __align__(16) h16 g_xp_lo[(size_t)B_SZ * H_SZ];
__device__ __align__(16) h16 g_h1_hi[(size_t)T_SZ * K_SZ * G_SZ * H_SZ];
__device__ __align__(16) h16 g_h1_lo[(size_t)T_SZ * K_SZ * G_SZ * H_SZ];
__device__ __align__(16) h16 g_out_hi[(size_t)B_SZ * H_SZ];
__device__ __align__(16) h16 g_out_lo[(size_t)B_SZ * H_SZ];
__device__ __align__(16) h16 g_Wp_h[(size_t)H_SZ * D_SZ];
__device__ __align__(16) h16 g_oW1_h[(size_t)T_SZ * K_SZ * H_SZ * H_SZ];
__device__ __align__(16) h16 g_oW2_h[(size_t)T_SZ * K_SZ * H_SZ * H_SZ];
__device__ __align__(16) h16 g_rW1c_h[(size_t)H_SZ * H_SZ];
__device__ __align__(16) h16 g_phW_h[(size_t)D_SZ * H_SZ];

// ---------------- helpers ----------------
__device__ __forceinline__ void split2h(float v, h16& h, h16& l) {
    h = __float2half_rn(v);
    l = __float2half_rn(v - __half2float(h));
}

__device__ __forceinline__ void mma16816(float* c, const unsigned* a, const unsigned* b) {
    asm volatile(
        "mma.sync.aligned.m16n8k16.row.col.f32.f16.f16.f32 "
        "{%0,%1,%2,%3},{%4,%5,%6,%7},{%8,%9},{%0,%1,%2,%3};"
        : "+f"(c[0]), "+f"(c[1]), "+f"(c[2]), "+f"(c[3])
        : "r"(a[0]), "r"(a[1]), "r"(a[2]), "r"(a[3]), "r"(b[0]), "r"(b[1]));
}

#define LDMX4(R_, ADDR_)                                                      \
    asm volatile("ldmatrix.sync.aligned.m8n8.x4.shared.b16 {%0,%1,%2,%3},[%4];" \
                 : "=r"((R_)[0]), "=r"((R_)[1]), "=r"((R_)[2]), "=r"((R_)[3]) \
                 : "r"(ADDR_))

#define LDMX2(R_, ADDR_)                                                      \
    asm volatile("ldmatrix.sync.aligned.m8n8.x2.shared.b16 {%0,%1},[%2];"     \
                 : "=r"((R_)[0]), "=r"((R_)[1]) : "r"(ADDR_))

#define CPA(DST_, SRC_)                                                       \
    asm volatile("cp.async.cg.shared.global [%0],[%1],16;" :: "r"(DST_), "l"(SRC_))

#define CP_COMMIT asm volatile("cp.async.commit_group;")
#define CP_WAIT1  asm volatile("cp.async.wait_group 1;")
#define CP_WAIT0  asm volatile("cp.async.wait_group 0;")

// ---------------- fp16 2-product tensor-core GEMM: C = A @ B^T (+bias)(+extra)(relu) ----
// A_hi/lo [M, lda] fp16 row-major (k contig) — exact split pair.
// B [N, ldb] single fp16 row-major (k contig).
// a_scatter/c_scatter: logical row r -> global row r*scatter + tcur, tcur = z / t_div.
// BM=BN=128, BK=64 (4 ksteps), 256 threads (8 warps 2x4, warp tile 64x32).
// 2-stage cp.async pipeline; SROW=72 (144B rows, ldsm conflict-free).
// MMA schedule: hi-sweep then lo-sweep over j so same-acc MMAs are 4 issues apart
// (hides HMMA completion latency despite asm-volatile program order).
#define GBM 128
#define GBN 128
#define GBK 64
#define SROW 72
#define TILE_BYTES 18432u                 // 128 rows * 72 el * 2 B
#define STAGE_BYTES (3u * TILE_BYTES)     // Ahi, Alo, B = 55296 B
#define NSTAGE 2

#define LOAD_STAGE(S_, KB_) do {                                              \
    uint32_t base_ = smem_u32 + (uint32_t)(S_) * STAGE_BYTES;                 \
    _Pragma("unroll")                                                         \
    for (int c_ = 0; c_ < 4; c_++) {                                          \
        uint32_t so_ = sOffA + (uint32_t)c_ * 4608u;                          \
        CPA(base_ +                 so_, pAh + (KB_) + c_ * aStep);           \
        CPA(base_ + TILE_BYTES    + so_, pAl + (KB_) + c_ * aStep);          \
        CPA(base_ + 2u*TILE_BYTES + so_, pB  + (KB_) + c_ * bStep);          \
    }                                                                         \
} while (0)

__global__ __launch_bounds__(256, 2)
void gemm2(const h16* __restrict__ Ah, const h16* __restrict__ Al,
           int lda, long a_bstride, int a_scatter, int t_div,
           const h16* __restrict__ Bm,
           int ldb, long b_bstride,
           const float* __restrict__ bias, long bias_bstride,
           const float* __restrict__ extra,
           float* __restrict__ C, h16* __restrict__ Chi, h16* __restrict__ Clo,
           int ldc, long c_bstride, int c_scatter,
           int N, int Kdim, int do_relu)
{
    extern __shared__ __align__(16) char smem_raw[];
    uint32_t smem_u32 = (uint32_t)__cvta_generic_to_shared(smem_raw);

    const int tid  = threadIdx.x;
    const int z    = blockIdx.z;
    const int tcur = z / t_div;
    const int brow = blockIdx.y * GBM;
    const int bcol = blockIdx.x * GBN;

    // ---- loader setup ----
    const int rBase = tid >> 3;           // 0..31
    const int cc    = tid & 7;            // 16B chunk within row
    long arow = brow + rBase;
    if (a_scatter) arow = arow * a_scatter + tcur;
    const long aStep = 32L * (a_scatter ? a_scatter : 1) * lda;
    const long bStep = 32L * ldb;
    const h16* pAh = Ah + z * a_bstride + arow * (long)lda + cc * 8;
    const h16* pAl = Al + z * a_bstride + arow * (long)lda + cc * 8;
    const h16* pB  = Bm + z * b_bstride + (long)(bcol + rBase) * ldb + cc * 8;
    const uint32_t sOffA = (uint32_t)(rBase * SROW + cc * 8) * 2u;

    // ---- fragment-load setup ----
    const int lane = tid & 31;
    const int warp = tid >> 5;
    const int wm = (warp & 1) * 64;
    const int wn = (warp >> 1) * 32;
    const int aMat = lane >> 3, aR = lane & 7;
    const uint32_t aOff = (uint32_t)((wm + (aMat & 1) * 8 + aR) * SROW + (aMat >> 1) * 8) * 2u;
    const int bL = lane & 15;
    const uint32_t bOff = (uint32_t)((wn + (bL & 7)) * SROW + ((bL >> 3) & 1) * 8) * 2u;

    float acc[4][4][4];
#pragma unroll
    for (int i = 0; i < 4; i++)
#pragma unroll
        for (int j = 0; j < 4; j++)
#pragma unroll
            for (int q = 0; q < 4; q++) acc[i][j][q] = 0.f;

    const int nIter = Kdim / GBK;        // >= 8 for all shapes
    LOAD_STAGE(0, 0);
    CP_COMMIT;
    LOAD_STAGE(1, GBK);
    CP_COMMIT;

    for (int it = 0; it < nIter; ++it) {
        if (it < nIter - 1) { CP_WAIT1; } else { CP_WAIT0; }
        __syncthreads();

        const uint32_t baseA_hi = smem_u32 + (uint32_t)(it & 1) * STAGE_BYTES;
        const uint32_t baseA_lo = baseA_hi + TILE_BYTES;
        const uint32_t baseB    = baseA_hi + 2u * TILE_BYTES;

#pragma unroll
        for (int kk = 0; kk < 4; kk++) {
            const uint32_t kkb = (uint32_t)kk * 32u;  // 16 cols * 2 B
            unsigned bh[4][2];
#pragma unroll
            for (int j = 0; j < 4; j++)
                LDMX2(bh[j], baseB + bOff + (uint32_t)j * 1152u + kkb);

            unsigned ah[2][4], al[2][4];
            LDMX4(ah[0], baseA_hi + aOff + kkb);
            LDMX4(al[0], baseA_lo + aOff + kkb);
#pragma unroll
            for (int i = 0; i < 4; i++) {
                const int cur = i & 1, nxt = cur ^ 1;
                if (i < 3) {
                    LDMX4(ah[nxt], baseA_hi + aOff + (uint32_t)(i + 1) * 2304u + kkb);
                    LDMX4(al[nxt], baseA_lo + aOff + (uint32_t)(i + 1) * 2304u + kkb);
                }
                // hi sweep: 4 independent accumulators back-to-back
#pragma unroll
                for (int j = 0; j < 4; j++) mma16816(acc[i][j], ah[cur], bh[j]);
                // lo sweep: same accumulators, now 4 issues after their hi MMA
#pragma unroll
                for (int j = 0; j < 4; j++) mma16816(acc[i][j], al[cur], bh[j]);
            }
        }

        if (it + 2 < nIter) {
            __syncthreads();   // all warps done reading stage (it&1) before refill
            LOAD_STAGE(it & 1, (long)(it + 2) * GBK);
            CP_COMMIT;
        }
    }

    // ---- epilogue ----
    const float* biasb = bias ? bias + (long)z * bias_bstride : nullptr;
    const int g4 = lane >> 2, t4 = lane & 3;
#pragma unroll
    for (int i = 0; i < 4; i++) {
#pragma unroll
        for (int half_ = 0; half_ < 2; half_++) {
            int m_local = wm + i * 16 + g4 + half_ * 8;
            long crow = brow + m_local;
            if (c_scatter) crow = crow * c_scatter + tcur;
            long rbase = (long)z * c_bstride + crow * (long)ldc;
#pragma unroll
            for (int j = 0; j < 4; j++) {
                int n_local = wn + j * 8 + t4 * 2;
                int n = bcol + n_local;
                float v0 = acc[i][j][half_ * 2 + 0];
                float v1 = acc[i][j][half_ * 2 + 1];
                if (biasb) { v0 += biasb[n]; v1 += biasb[n + 1]; }
                if (extra) { v0 += extra[tcur * N + n]; v1 += extra[tcur * N + n + 1]; }
                if (do_relu) { v0 = fmaxf(v0, 0.f); v1 = fmaxf(v1, 0.f); }
                if (C) {
                    float2 f2; f2.x = v0; f2.y = v1;
                    *(float2*)(C + rbase + n) = f2;
                }
                if (Chi) {
                    h16 h0, l0, h1, l1;
                    split2h(v0, h0, l0); split2h(v1, h1, l1);
                    __half2 ph; ph.x = h0; ph.y = h1;
                    __half2 pl; pl.x = l0; pl.y = l1;
                    *(__half2*)(Chi + rbase + n) = ph;
                    *(__half2*)(Clo + rbase + n) = pl;
                }
            }
        }
    }
}

// ---------------- prep: all conversions + rW1 extract + softmax in ONE kernel ----------
#define SEG_X   6144
#define SEG_WP  (SEG_X + 256)
#define SEG_W1  (SEG_WP + 4608)
#define SEG_W2  (SEG_W1 + 4608)
#define SEG_PH  (SEG_W2 + 256)
#define SEG_RW  (SEG_PH + 128)
#define PREP_BLOCKS (SEG_RW + 1)

__device__ __forceinline__ void conv_split_f4(const float4* in, __half2* hi, __half2* lo, long i) {
    float4 v = in[i];
    h16 h0,h1,h2,h3,l0,l1,l2,l3;
    split2h(v.x,h0,l0); split2h(v.y,h1,l1); split2h(v.z,h2,l2); split2h(v.w,h3,l3);
    __half2 a,b;
    a.x=h0; a.y=h1; b.x=h2; b.y=h3; hi[i*2]=a; hi[i*2+1]=b;
    a.x=l0; a.y=l1; b.x=l2; b.y=l3; lo[i*2]=a; lo[i*2+1]=b;
}
__device__ __forceinline__ void conv_h_f4(const float4* in, __half2* out, long i) {
    float4 v = in[i];
    __half2 a,b;
    a.x=__float2half_rn(v.x); a.y=__float2half_rn(v.y);
    b.x=__float2half_rn(v.z); b.y=__float2half_rn(v.w);
    out[i*2]=a; out[i*2+1]=b;
}

__global__ void prep_kernel(const float* __restrict__ x, const float* __restrict__ Wp,
                            const float* __restrict__ opW1, const float* __restrict__ opW2,
                            const float* __restrict__ phW, const float* __restrict__ rW1,
                            const float* __restrict__ op_logits)
{
    const int b = blockIdx.x, tid = threadIdx.x;
    if (b < SEG_X) {
        long i0 = (long)b * 512 + tid;
        conv_split_f4((const float4*)x, (__half2*)g_x_hi, (__half2*)g_x_lo, i0);
        conv_split_f4((const float4*)x, (__half2*)g_x_hi, (__half2*)g_x_lo, i0 + 256);
    } else if (b < SEG_WP) {
        long i0 = (long)(b - SEG_X) * 512 + tid;
        conv_h_f4((const float4*)Wp, (__half2*)g_Wp_h, i0);
        conv_h_f4((const float4*)Wp, (__half2*)g_Wp_h, i0 + 256);
    } else if (b < SEG_W1) {
        long i0 = (long)(b - SEG_WP) * 512 + tid;
        conv_h_f4((const float4*)opW1, (__half2*)g_oW1_h, i0);
        conv_h_f4((const float4*)opW1, (__half2*)g_oW1_h, i0 + 256);
    } else if (b < SEG_W2) {
        long i0 = (long)(b - SEG_W1) * 512 + tid;
        conv_h_f4((const float4*)opW2, (__half2*)g_oW2_h, i0);
        conv_h_f4((const float4*)opW2, (__half2*)g_oW2_h, i0 + 256);
    } else if (b < SEG_PH) {
        long i0 = (long)(b - SEG_W2) * 512 + tid;
        conv_h_f4((const float4*)phW, (__half2*)g_phW_h, i0);
        conv_h_f4((const float4*)phW, (__half2*)g_phW_h, i0 + 256);
    } else if (b < SEG_RW) {
        int base = (b - SEG_PH) * 2048 + tid * 8;
#pragma unroll
        for (int e = 0; e < 8; e++) {
            int idx = base + e;
            int i = idx >> 9, j = idx & 511;
            g_rW1c_h[idx] = __float2half_rn(rW1[(long)i * (H_SZ + 7) + j]);
        }
    } else {
        int t = tid;
        if (t < T_SZ) {
            float l0 = op_logits[t*K_SZ+0], l1 = op_logits[t*K_SZ+1], l2 = op_logits[t*K_SZ+2];
            float m = fmaxf(l0, fmaxf(l1, l2));
            float e0 = expf(l0 - m), e1 = expf(l1 - m), e2 = expf(l2 - m);
            float s = e0 + e1 + e2;
            float w0 = e0 / s, w1 = e1 / s, w2 = e2 / s;
            g_w[t*K_SZ+0] = w0; g_w[t*K_SZ+1] = w1; g_w[t*K_SZ+2] = w2;
            float mean = (w0 + w1 + w2) * (1.f / 3.f);
            float d0 = w0 - mean, d1 = w1 - mean, d2 = w2 - mean;
            g_conf[t] = sqrtf((d0*d0 + d1*d1 + d2*d2) * 0.5f);
            float sum = w0 + w1 + w2;
            float inv = 1.f / (sum + 1e-6f);
            float u0 = w0*inv, u1 = w1*inv, u2 = w2*inv;
            float ent = -(u0*logf(fmaxf(u0,1e-6f)) + u1*logf(fmaxf(u1,1e-6f)) + u2*logf(fmaxf(u2,1e-6f)));
            g_ent[t] = ent;
        }
    }
}

// ---------------- fused wsum + row stats: one block (128 thr) per row b ----------------
__device__ __forceinline__ float warp_sum(float v) {
#pragma unroll
    for (int o = 16; o > 0; o >>= 1) v += __shfl_down_sync(0xffffffffu, v, o);
    return v;
}

__global__ __launch_bounds__(128)
void wsum_stats(float* __restrict__ out_full, const float* __restrict__ noise)
{
    __shared__ float4 red[4];
    const int b = blockIdx.x;
    const int tid = threadIdx.x;
    const int t = b % T_SZ, g = b / T_SZ;

    float w0 = g_w[t*K_SZ+0], w1 = g_w[t*K_SZ+1], w2 = g_w[t*K_SZ+2];
    const float4* p0 = (const float4*)&g_h2[(((long)(t*K_SZ+0))*G_SZ + g)*H_SZ];
    const float4* p1 = (const float4*)&g_h2[(((long)(t*K_SZ+1))*G_SZ + g)*H_SZ];
    const float4* p2 = (const float4*)&g_h2[(((long)(t*K_SZ+2))*G_SZ + g)*H_SZ];
    float4 v0 = p0[tid], v1 = p1[tid], v2 = p2[tid];
    float4 o;
    o.x = w0*v0.x + w1*v1.x + w2*v2.x;
    o.y = w0*v0.y + w1*v1.y + w2*v2.y;
    o.z = w0*v0.z + w1*v1.z + w2*v2.z;
    o.w = w0*v0.w + w1*v1.w + w2*v2.w;

    const long rowbase = (long)b * H_SZ;
    ((float4*)&out_full[rowbase])[tid] = o;

    h16 h0,h1,h2v,h3,l0,l1,l2v,l3;
    split2h(o.x,h0,l0); split2h(o.y,h1,l1); split2h(o.z,h2v,l2v); split2h(o.w,h3,l3);
    __half2 a2,b2;
    a2.x=h0; a2.y=h1; b2.x=h2v; b2.y=h3;
    ((__half2*)&g_out_hi[rowbase])[tid*2] = a2;
    ((__half2*)&g_out_hi[rowbase])[tid*2+1] = b2;
    a2.x=l0; a2.y=l1; b2.x=l2v; b2.y=l3;
    ((__half2*)&g_out_lo[rowbase])[tid*2] = a2;
    ((__half2*)&g_out_lo[rowbase])[tid*2+1] = b2;

    float4 xv = ((const float4*)&g_xp[rowbase])[tid];
    float4 nv = ((const float4*)&noise[rowbase])[tid];
    float pe, nov, sp, pl, d;
    d = o.x - xv.x; pe  = d*d; nov  = xv.x*xv.x; sp  = fabsf(o.x);
    d = o.y - xv.y; pe += d*d; nov += xv.y*xv.y; sp += fabsf(o.y);
    d = o.z - xv.z; pe += d*d; nov += xv.z*xv.z; sp += fabsf(o.z);
    d = o.w - xv.w; pe += d*d; nov += xv.w*xv.w; sp += fabsf(o.w);
    float nx = nv.x*0.01f, ny = nv.y*0.01f, nz = nv.z*0.01f, nw = nv.w*0.01f;
    pl = nx*nx + ny*ny + nz*nz + nw*nw;

    pe = warp_sum(pe); nov = warp_sum(nov); sp = warp_sum(sp); pl = warp_sum(pl);
    const int lane = tid & 31, warp = tid >> 5;
    if (lane == 0) { float4 f; f.x=pe; f.y=nov; f.z=sp; f.w=pl; red[warp] = f; }
    __syncthreads();
    if (tid == 0) {
        float4 s = red[0];
        s.x += red[1].x + red[2].x + red[3].x;
        s.y += red[1].y + red[2].y + red[3].y;
        s.z += red[1].z + red[2].z + red[3].z;
        s.w += red[1].w + red[2].w + red[3].w;
        const float inv = 1.f / (float)H_SZ;
        g_pe[b]  = s.x * inv;
        g_nov[b] = s.y * inv;
        g_sp[b]  = s.z * inv;
        g_pl[b]  = s.w * inv;
    }
}

// ---------------- finalize (one block per t) ----------------
__device__ __forceinline__ float block_sum(float v, float* red, int tid) {
    red[tid] = v; __syncthreads();
    for (int s = 128; s > 0; s >>= 1) { if (tid < s) red[tid] += red[tid + s]; __syncthreads(); }
    float r = red[0]; __syncthreads();
    return r;
}

__global__ void finalize_kernel(const float* __restrict__ id_emb, const float* __restrict__ rW1,
                                const float* __restrict__ gW1, const float* __restrict__ gb1,
                                const float* __restrict__ gW2, const float* __restrict__ gb2,
                                float* __restrict__ decision)
{
    __shared__ float red[256];
    __shared__ float sig[7];
    __shared__ float gch[H_SZ];
    const int t = blockIdx.x, tid = threadIdx.x;

    float pe = 0.f, pe2 = 0.f, nov = 0.f, sp = 0.f, pl = 0.f;
    for (int g = tid; g < G_SZ; g += 256) {
        int b = g * T_SZ + t;
        float p = g_pe[b];
        pe += p; pe2 += p * p; nov += g_nov[b]; sp += g_sp[b]; pl += g_pl[b];
    }
    float S_pe  = block_sum(pe,  red, tid);
    float S_pe2 = block_sum(pe2, red, tid);
    float S_nov = block_sum(nov, red, tid);
    float S_sp  = block_sum(sp,  red, tid);
    float S_pl  = block_sum(pl,  red, tid);

    if (tid == 0) {
        const float invg = 1.f / (float)G_SZ;
        float pe_m = S_pe * invg, pe2_m = S_pe2 * invg;
        float c = 0.01f * pe_m;
        sig[0] = S_pl * invg;
        sig[1] = S_nov * invg;
        sig[2] = pe_m;
        sig[3] = g_ent[t];
        sig[4] = S_sp * invg;
        sig[5] = -pe_m;
        sig[6] = pe2_m - 2.f * c * pe_m + c * c;
    }
    __syncthreads();

    for (int i = tid; i < H_SZ; i += 256) {
        float a = gb1[t * H_SZ + i];
#pragma unroll
        for (int j = 0; j < 7; j++) a += gW1[((long)(t * H_SZ + i)) * 7 + j] * sig[j];
        gch[i] = fmaxf(a, 0.f);
    }
    __syncthreads();

    for (int o = 0; o < 2; o++) {
        float d = 0.f;
        for (int i = tid; i < H_SZ; i += 256) d += gW2[((long)(t * 2 + o)) * H_SZ + i] * gch[i];
        float S = block_sum(d, red, tid);
        if (tid == 0) decision[t * 2 + o] = S + gb2[t * 2 + o];
    }

    __shared__ float ext[7];
    if (tid == 0) {
        ext[0] = id_emb[t*4+0]; ext[1] = id_emb[t*4+1];
        ext[2] = id_emb[t*4+2]; ext[3] = id_emb[t*4+3];
        ext[4] = sig[1];
        ext[5] = g_conf[t];
        ext[6] = sig[2];
    }
    __syncthreads();
    for (int i = tid; i < H_SZ; i += 256) {
        float a = 0.f;
#pragma unroll
        for (int j = 0; j < 7; j++) a += ext[j] * rW1[(long)i * (H_SZ + 7) + H_SZ + j];
        g_extra[t * H_SZ + i] = a;
    }
}

// ---------------- logits ----------------
__global__ void logits_kernel(const float* __restrict__ rW2, const float* __restrict__ rb2,
                              float* __restrict__ logits)
{
    const int b = blockIdx.x;
    const int o = threadIdx.x >> 5, lane = threadIdx.x & 31;
    const float4* r = (const float4*)(g_rh + (long)b * H_SZ);
    const float4* wrow = (const float4*)(rW2 + (long)o * H_SZ);
    float acc = 0.f;
    for (int i = lane; i < H_SZ/4; i += 32) {
        float4 rv = r[i], wv = wrow[i];
        acc += rv.x*wv.x + rv.y*wv.y + rv.z*wv.z + rv.w*wv.w;
    }
    acc = warp_sum(acc);
    if (lane == 0) logits[(long)b * (T_SZ + 1) + o] = acc + rb2[o];
}

// ---------------- launch ----------------
extern "C" void kernel_launch(void* const* d_in, const int* in_sizes, int n_in,
                              void* d_out, int out_size)
{
    const float* x         = (const float*)d_in[0];
    const float* Wp        = (const float*)d_in[1];
    const float* bp        = (const float*)d_in[2];
    const float* opW1      = (const float*)d_in[3];
    const float* opb1      = (const float*)d_in[4];
    const float* opW2      = (const float*)d_in[5];
    const float* opb2      = (const float*)d_in[6];
    const float* op_logits = (const float*)d_in[7];
    const float* id_emb    = (const float*)d_in[8];
    const float* rW1       = (const float*)d_in[9];
    const float* rb1       = (const float*)d_in[10];
    const float* rW2       = (const float*)d_in[11];
    const float* rb2       = (const float*)d_in[12];
    const float* gW1       = (const float*)d_in[13];
    const float* gb1       = (const float*)d_in[14];
    const float* gW2       = (const float*)d_in[15];
    const float* gb2       = (const float*)d_in[16];
    const float* phW       = (const float*)d_in[17];
    const float* phb       = (const float*)d_in[18];
    const float* noise     = (const float*)d_in[19];

    float* out_full = (float*)d_out;
    float* logits   = out_full + (size_t)B_SZ * H_SZ;
    float* pred     = logits   + (size_t)B_SZ * (T_SZ + 1);
    float* decision = pred     + (size_t)B_SZ * D_SZ;

    float *xp, *h2, *extra, *rh;
    h16 *x_hi, *x_lo, *xp_hi, *xp_lo, *h1_hi, *h1_lo, *out_hi, *out_lo;
    h16 *Wp_h, *oW1_h, *oW2_h, *rW1c_h, *phW_h;
    cudaGetSymbolAddress((void**)&xp,      g_xp);
    cudaGetSymbolAddress((void**)&h2,      g_h2);
    cudaGetSymbolAddress((void**)&extra,   g_extra);
    cudaGetSymbolAddress((void**)&rh,      g_rh);
    cudaGetSymbolAddress((void**)&x_hi,    g_x_hi);    cudaGetSymbolAddress((void**)&x_lo,    g_x_lo);
    cudaGetSymbolAddress((void**)&xp_hi,   g_xp_hi);   cudaGetSymbolAddress((void**)&xp_lo,   g_xp_lo);
    cudaGetSymbolAddress((void**)&h1_hi,   g_h1_hi);   cudaGetSymbolAddress((void**)&h1_lo,   g_h1_lo);
    cudaGetSymbolAddress((void**)&out_hi,  g_out_hi);  cudaGetSymbolAddress((void**)&out_lo,  g_out_lo);
    cudaGetSymbolAddress((void**)&Wp_h,    g_Wp_h);
    cudaGetSymbolAddress((void**)&oW1_h,   g_oW1_h);
    cudaGetSymbolAddress((void**)&oW2_h,   g_oW2_h);
    cudaGetSymbolAddress((void**)&rW1c_h,  g_rW1c_h);
    cudaGetSymbolAddress((void**)&phW_h,   g_phW_h);

    cudaFuncSetAttribute(gemm2, cudaFuncAttributeMaxDynamicSharedMemorySize,
                         NSTAGE * (int)STAGE_BYTES);
    const int SM = NSTAGE * (int)STAGE_BYTES;

    // (1) all conversions + softmax fused
    prep_kernel<<<PREP_BLOCKS, 256>>>(x, Wp, opW1, opW2, phW, rW1, op_logits);

    // (2) xp = x @ Wp^T + bp          (fp32 + hi/lo out)
    gemm2<<<dim3(H_SZ/GBN, B_SZ/GBM, 1), 256, SM>>>(
        x_hi, x_lo, D_SZ, 0, 0, 1,
        Wp_h, D_SZ, 0,
        bp, 0, nullptr,
        xp, xp_hi, xp_lo, H_SZ, 0, 0, H_SZ, D_SZ, 0);

    // (3) h1[t,k] = relu(xg[t] @ opW1[t,k]^T + opb1)   (A scattered; hi/lo out only)
    gemm2<<<dim3(H_SZ/GBN, G_SZ/GBM, T_SZ*K_SZ), 256, SM>>>(
        xp_hi, xp_lo, H_SZ, 0, T_SZ, K_SZ,
        oW1_h, H_SZ, (long)H_SZ*H_SZ,
        opb1, H_SZ, nullptr,
        nullptr, h1_hi, h1_lo, H_SZ, (long)G_SZ*H_SZ, 0, H_SZ, H_SZ, 1);

    // (4) h2[t,k] = relu(h1[t,k] @ opW2[t,k]^T + opb2)   (fp32 out only)  [profiled]
    gemm2<<<dim3(H_SZ/GBN, G_SZ/GBM, T_SZ*K_SZ), 256, SM>>>(
        h1_hi, h1_lo, H_SZ, (long)G_SZ*H_SZ, 0, 1,
        oW2_h, H_SZ, (long)H_SZ*H_SZ,
        opb2, H_SZ, nullptr,
        h2, nullptr, nullptr, H_SZ, (long)G_SZ*H_SZ, 0, H_SZ, H_SZ, 1);

    // (5) fused weighted mixture + per-row stats
    wsum_stats<<<B_SZ, 128>>>(out_full, noise);

    // (6) signals, decision, routing extra bias
    finalize_kernel<<<T_SZ, 256>>>(id_emb, rW1, gW1, gb1, gW2, gb2, decision);

    // (7) rh = relu(out @ rW1[:, :H]^T + c_extra[t] + rb1)   (A & C rows scattered)
    gemm2<<<dim3(H_SZ/GBN, G_SZ/GBM, T_SZ), 256, SM>>>(
        out_hi, out_lo, H_SZ, 0, T_SZ, 1,
        rW1c_h, H_SZ, 0,
        rb1, 0, extra,
        rh, nullptr, nullptr, H_SZ, 0, T_SZ, H_SZ, H_SZ, 1);

    // (8) logits = rh @ rW2^T + rb2
    logits_kernel<<<B_SZ, (T_SZ + 1) * 32>>>(rW2, rb2, logits);

    // (9) pred = out_full @ phW^T + phb
    gemm2<<<dim3(D_SZ/GBN, B_SZ/GBM, 1), 256, SM>>>(
        out_hi, out_lo, H_SZ, 0, 0, 1,
        phW_h, H_SZ, 0,
        phb, 0, nullptr,
        pred, nullptr, nullptr, D_SZ, 0, 0, D_SZ, H_SZ, 0);
}